// round 1
// baseline (speedup 1.0000x reference)
#include <cuda_runtime.h>
#include <cstdint>

#define NN 100000
#define HH 128
#define EE 1600000
#define LN_EPS 1e-5f

// ---------------- device scratch (static allocation, allowed) ----------------
__device__ float g_x  [NN * HH];
__device__ float g_h  [NN * HH];
__device__ float g_agg[NN * HH];
__device__ float g_P  [NN * HH];
__device__ float g_Q  [NN * HH];
__device__ int   g_deg [NN];
__device__ float g_dinv[NN];

// ---------------- degree / norm ----------------
__global__ void k_deg_zero() {
    int i = blockIdx.x * blockDim.x + threadIdx.x;
    if (i < NN) g_deg[i] = 0;
}

__global__ void k_deg_count(const int* __restrict__ dst) {
    int i = blockIdx.x * blockDim.x + threadIdx.x;
    if (i < EE) atomicAdd(&g_deg[dst[i]], 1);
}

__global__ void k_dinv() {
    int i = blockIdx.x * blockDim.x + threadIdx.x;
    if (i < NN) g_dinv[i] = rsqrtf((float)(g_deg[i] + 1));
}

// ---------------- encoder: Linear(7->128) + LN + ReLU, warp per node ----------------
__global__ void k_encoder(const float* __restrict__ nf,
                          const float* __restrict__ w,  const float* __restrict__ b,
                          const float* __restrict__ lg, const float* __restrict__ lb) {
    int n = blockIdx.x * 8 + (threadIdx.x >> 5);
    if (n >= NN) return;
    int lane = threadIdx.x & 31;

    float f[7];
#pragma unroll
    for (int k = 0; k < 7; k++) f[k] = nf[n * 7 + k];

    float v[4];
#pragma unroll
    for (int j = 0; j < 4; j++) {
        int c = lane + 32 * j;
        float a = b[c];
#pragma unroll
        for (int k = 0; k < 7; k++) a = fmaf(f[k], w[k * HH + c], a);
        v[j] = a;
    }
    float s = 0.f, ss = 0.f;
#pragma unroll
    for (int j = 0; j < 4; j++) { s += v[j]; ss += v[j] * v[j]; }
#pragma unroll
    for (int off = 16; off > 0; off >>= 1) {
        s  += __shfl_xor_sync(0xffffffffu, s,  off);
        ss += __shfl_xor_sync(0xffffffffu, ss, off);
    }
    float mu  = s * (1.f / HH);
    float var = ss * (1.f / HH) - mu * mu;
    float inv = rsqrtf(var + LN_EPS);
#pragma unroll
    for (int j = 0; j < 4; j++) {
        int c = lane + 32 * j;
        float y = (v[j] - mu) * inv * lg[c] + lb[c];
        g_x[n * HH + c] = fmaxf(y, 0.f);
    }
}

// ---------------- GEMM: C[M,128] = A[M,128] @ W[128,128], fp32 ----------------
// 64-row x 128-col tile per block, 256 threads, 8x4 register blocking.
__global__ void __launch_bounds__(256, 4)
k_gemm128(const float* __restrict__ A, const float* __restrict__ W,
          float* __restrict__ C, int M) {
    __shared__ float ws[32][128];   // W chunk  [k][n]
    __shared__ float xs[32][64];    // A chunk transposed [k][m]

    int tid  = threadIdx.x;
    int colg = tid & 31;        // 32 col groups of 4 cols
    int rowg = tid >> 5;        // 8 row groups of 8 rows
    int row0 = blockIdx.x * 64;

    float acc[8][4];
#pragma unroll
    for (int i = 0; i < 8; i++)
#pragma unroll
        for (int j = 0; j < 4; j++) acc[i][j] = 0.f;

    for (int kc = 0; kc < 128; kc += 32) {
        // load W chunk: 32 rows x 128 cols = 1024 float4
#pragma unroll
        for (int idx = tid; idx < 1024; idx += 256) {
            int k = idx >> 5, cv = idx & 31;
            float4 v = *(const float4*)&W[(kc + k) * 128 + cv * 4];
            *(float4*)&ws[k][cv * 4] = v;
        }
        // load A chunk transposed: 64 rows x 32 k = 512 float4 (4 k each)
#pragma unroll
        for (int idx = tid; idx < 512; idx += 256) {
            int r = idx & 63, kv = idx >> 6;
            float4 v = make_float4(0.f, 0.f, 0.f, 0.f);
            if (row0 + r < M) v = *(const float4*)&A[(size_t)(row0 + r) * 128 + kc + kv * 4];
            xs[kv * 4 + 0][r] = v.x;
            xs[kv * 4 + 1][r] = v.y;
            xs[kv * 4 + 2][r] = v.z;
            xs[kv * 4 + 3][r] = v.w;
        }
        __syncthreads();
#pragma unroll
        for (int k = 0; k < 32; k++) {
            float4 w4 = *(float4*)&ws[k][colg * 4];
            float4 xa = *(float4*)&xs[k][rowg * 8];
            float4 xb = *(float4*)&xs[k][rowg * 8 + 4];
            float xr[8] = {xa.x, xa.y, xa.z, xa.w, xb.x, xb.y, xb.z, xb.w};
            float wr[4] = {w4.x, w4.y, w4.z, w4.w};
#pragma unroll
            for (int i = 0; i < 8; i++)
#pragma unroll
                for (int j = 0; j < 4; j++) acc[i][j] = fmaf(xr[i], wr[j], acc[i][j]);
        }
        __syncthreads();
    }
#pragma unroll
    for (int i = 0; i < 8; i++) {
        int r = row0 + rowg * 8 + i;
        if (r < M)
            *(float4*)&C[(size_t)r * 128 + colg * 4] =
                make_float4(acc[i][0], acc[i][1], acc[i][2], acc[i][3]);
    }
}

// ---------------- self-loop init: agg = h * dinv^2 ----------------
__global__ void k_selfinit() {
    int idx = blockIdx.x * blockDim.x + threadIdx.x;   // over NN*32 float4
    if (idx >= NN * 32) return;
    int n = idx >> 5;
    float di = g_dinv[n];
    float sw = di * di;
    float4 h4 = *(const float4*)&g_h[(size_t)idx * 4];
    h4.x *= sw; h4.y *= sw; h4.z *= sw; h4.w *= sw;
    *(float4*)&g_agg[(size_t)idx * 4] = h4;
}

// ---------------- scatter: agg[dst] += h[src] * dinv[src]*dinv[dst], warp/edge ----------------
__global__ void k_scatter(const int* __restrict__ src, const int* __restrict__ dst) {
    int e = blockIdx.x * 8 + (threadIdx.x >> 5);
    if (e >= EE) return;
    int lane = threadIdx.x & 31;
    int s = src[e], d = dst[e];
    float nrm = g_dinv[s] * g_dinv[d];
    float4 v = *(const float4*)&g_h[(size_t)s * 128 + lane * 4];
    v.x *= nrm; v.y *= nrm; v.z *= nrm; v.w *= nrm;
    float* addr = &g_agg[(size_t)d * 128 + lane * 4];
    asm volatile("red.global.add.v4.f32 [%0], {%1, %2, %3, %4};"
                 :: "l"(addr), "f"(v.x), "f"(v.y), "f"(v.z), "f"(v.w)
                 : "memory");
}

// ---------------- layer epilogue: +bias, LN, ReLU, +residual; warp per node ----------------
__global__ void k_epilogue(const float* __restrict__ cb,
                           const float* __restrict__ lg, const float* __restrict__ lb,
                           float* __restrict__ xout /* nullable */) {
    int n = blockIdx.x * 8 + (threadIdx.x >> 5);
    if (n >= NN) return;
    int lane = threadIdx.x & 31;

    float4 a  = *(const float4*)&g_agg[(size_t)n * 128 + lane * 4];
    float4 b4 = *(const float4*)&cb[lane * 4];
    float v[4] = {a.x + b4.x, a.y + b4.y, a.z + b4.z, a.w + b4.w};

    float s = 0.f, ss = 0.f;
#pragma unroll
    for (int j = 0; j < 4; j++) { s += v[j]; ss += v[j] * v[j]; }
#pragma unroll
    for (int off = 16; off > 0; off >>= 1) {
        s  += __shfl_xor_sync(0xffffffffu, s,  off);
        ss += __shfl_xor_sync(0xffffffffu, ss, off);
    }
    float mu  = s * (1.f / HH);
    float var = ss * (1.f / HH) - mu * mu;
    float inv = rsqrtf(var + LN_EPS);

    float4 lg4 = *(const float4*)&lg[lane * 4];
    float4 lb4 = *(const float4*)&lb[lane * 4];
    float4 xo  = *(const float4*)&g_x[(size_t)n * 128 + lane * 4];

    float4 y;
    y.x = fmaxf((v[0] - mu) * inv * lg4.x + lb4.x, 0.f) + xo.x;
    y.y = fmaxf((v[1] - mu) * inv * lg4.y + lb4.y, 0.f) + xo.y;
    y.z = fmaxf((v[2] - mu) * inv * lg4.z + lb4.z, 0.f) + xo.z;
    y.w = fmaxf((v[3] - mu) * inv * lg4.w + lb4.w, 0.f) + xo.w;

    *(float4*)&g_x[(size_t)n * 128 + lane * 4] = y;
    if (xout) *(float4*)&xout[(size_t)n * 128 + lane * 4] = y;
}

// ---------------- edge MLP: logit = relu(P[s]+Q[d]+b1) . w2 + b2, warp/edge ----------------
__global__ void k_edge_mlp(const int* __restrict__ src, const int* __restrict__ dst,
                           const float* __restrict__ b1, const float* __restrict__ w2,
                           const float* __restrict__ b2, float* __restrict__ out) {
    int e = blockIdx.x * 8 + (threadIdx.x >> 5);
    if (e >= EE) return;
    int lane = threadIdx.x & 31;
    int s = src[e], d = dst[e];

    float4 p  = *(const float4*)&g_P[(size_t)s * 128 + lane * 4];
    float4 q  = *(const float4*)&g_Q[(size_t)d * 128 + lane * 4];
    float4 bb = *(const float4*)&b1[lane * 4];
    float4 w  = *(const float4*)&w2[lane * 4];

    float h0 = fmaxf(p.x + q.x + bb.x, 0.f);
    float h1 = fmaxf(p.y + q.y + bb.y, 0.f);
    float h2 = fmaxf(p.z + q.z + bb.z, 0.f);
    float h3 = fmaxf(p.w + q.w + bb.w, 0.f);
    float part = h0 * w.x + h1 * w.y + h2 * w.z + h3 * w.w;
#pragma unroll
    for (int off = 16; off > 0; off >>= 1)
        part += __shfl_xor_sync(0xffffffffu, part, off);
    if (lane == 0) out[e] = part + b2[0];
}

// ---------------- host ----------------
extern "C" void kernel_launch(void* const* d_in, const int* in_sizes, int n_in,
                              void* d_out, int out_size) {
    const float* nf       = (const float*)d_in[0];
    const int*   ei       = (const int*)  d_in[1];
    // d_in[2] = edge_attr (unused by the reference computation)
    const float* enc_w    = (const float*)d_in[3];
    const float* enc_b    = (const float*)d_in[4];
    const float* enc_ln_g = (const float*)d_in[5];
    const float* enc_ln_b = (const float*)d_in[6];
    const float* conv_w   = (const float*)d_in[7];
    const float* conv_b   = (const float*)d_in[8];
    const float* ln_g     = (const float*)d_in[9];
    const float* ln_b     = (const float*)d_in[10];
    const float* mlp_w1   = (const float*)d_in[11];
    const float* mlp_b1   = (const float*)d_in[12];
    const float* mlp_w2   = (const float*)d_in[13];
    const float* mlp_b2   = (const float*)d_in[14];

    const int* src = ei;
    const int* dst = ei + EE;

    float* out        = (float*)d_out;            // x: NN*HH floats
    float* out_logits = out + (size_t)NN * HH;    // logits: EE floats

    float *px, *ph, *pP, *pQ;
    cudaGetSymbolAddress((void**)&px, g_x);
    cudaGetSymbolAddress((void**)&ph, g_h);
    cudaGetSymbolAddress((void**)&pP, g_P);
    cudaGetSymbolAddress((void**)&pQ, g_Q);

    const int GEMM_BLOCKS = (NN + 63) / 64;

    // degree + normalization
    k_deg_zero <<<(NN + 255) / 256, 256>>>();
    k_deg_count<<<(EE + 255) / 256, 256>>>(dst);
    k_dinv     <<<(NN + 255) / 256, 256>>>();

    // encoder
    k_encoder<<<(NN + 7) / 8, 256>>>(nf, enc_w, enc_b, enc_ln_g, enc_ln_b);

    // 3 GCN layers
    for (int l = 0; l < 3; l++) {
        k_gemm128 <<<GEMM_BLOCKS, 256>>>(px, conv_w + (size_t)l * HH * HH, ph, NN);
        k_selfinit<<<(NN * 32 + 255) / 256, 256>>>();
        k_scatter <<<(EE + 7) / 8, 256>>>(src, dst);
        k_epilogue<<<(NN + 7) / 8, 256>>>(conv_b + l * HH, ln_g + l * HH, ln_b + l * HH,
                                          (l == 2) ? out : nullptr);
    }

    // edge scoring: P = x @ W1[:128], Q = x @ W1[128:], then per-edge fuse
    k_gemm128<<<GEMM_BLOCKS, 256>>>(px, mlp_w1, pP, NN);
    k_gemm128<<<GEMM_BLOCKS, 256>>>(px, mlp_w1 + HH * HH, pQ, NN);
    k_edge_mlp<<<(EE + 7) / 8, 256>>>(src, dst, mlp_b1, mlp_w2, mlp_b2, out_logits);
}

// round 2
// speedup vs baseline: 1.4719x; 1.4719x over previous
#include <cuda_runtime.h>
#include <cstdint>

#define NN 100000
#define HH 128
#define EE 1600000
#define LN_EPS 1e-5f
#define NB 391          // (NN+255)/256

// ---------------- device scratch ----------------
__device__ float g_x  [NN * HH];
__device__ float g_h  [NN * HH];     // h_scaled = (x@W) * dinv[row]
__device__ float g_P  [NN * HH];
__device__ float g_Q  [NN * HH];
__device__ int   g_deg   [NN];
__device__ float g_dinv  [NN];
__device__ int   g_rowptr[NN];
__device__ int   g_cursor[NN];
__device__ int   g_csrc  [EE];
__device__ int   g_bsum  [NB];
__device__ int   g_boff  [NB];

// ---------------- degree / norm ----------------
__global__ void k_deg_zero() {
    int i = blockIdx.x * blockDim.x + threadIdx.x;
    if (i < NN) g_deg[i] = 0;
}
__global__ void k_deg_count(const int* __restrict__ dst) {
    int i = blockIdx.x * blockDim.x + threadIdx.x;
    if (i < EE) atomicAdd(&g_deg[dst[i]], 1);
}
__global__ void k_dinv() {
    int i = blockIdx.x * blockDim.x + threadIdx.x;
    if (i < NN) g_dinv[i] = rsqrtf((float)(g_deg[i] + 1));
}

// ---------------- CSR build: 3-kernel exclusive scan + binning fill ----------------
__global__ void k_scanA() {   // per-block sums of deg
    __shared__ int ws[8];
    int i = blockIdx.x * 256 + threadIdx.x;
    int v = (i < NN) ? g_deg[i] : 0;
#pragma unroll
    for (int off = 16; off > 0; off >>= 1) v += __shfl_xor_sync(0xffffffffu, v, off);
    if ((threadIdx.x & 31) == 0) ws[threadIdx.x >> 5] = v;
    __syncthreads();
    if (threadIdx.x == 0) {
        int t = 0;
#pragma unroll
        for (int w = 0; w < 8; w++) t += ws[w];
        g_bsum[blockIdx.x] = t;
    }
}
__global__ void k_scanB() {   // single-block exclusive scan of block sums
    __shared__ int s[512];
    int tid = threadIdx.x;
    int v = (tid < NB) ? g_bsum[tid] : 0;
    s[tid] = v;
    __syncthreads();
    for (int off = 1; off < 512; off <<= 1) {
        int t = (tid >= off) ? s[tid - off] : 0;
        __syncthreads();
        s[tid] += t;
        __syncthreads();
    }
    if (tid < NB) g_boff[tid] = s[tid] - v;
}
__global__ void k_scanC() {   // per-block exclusive scan + block offset -> rowptr, cursor
    __shared__ int s[256];
    int tid = threadIdx.x;
    int i = blockIdx.x * 256 + tid;
    int v = (i < NN) ? g_deg[i] : 0;
    s[tid] = v;
    __syncthreads();
    for (int off = 1; off < 256; off <<= 1) {
        int t = (tid >= off) ? s[tid - off] : 0;
        __syncthreads();
        s[tid] += t;
        __syncthreads();
    }
    if (i < NN) {
        int r = g_boff[blockIdx.x] + s[tid] - v;
        g_rowptr[i] = r;
        g_cursor[i] = r;
    }
}
__global__ void k_fill(const int* __restrict__ src, const int* __restrict__ dst) {
    int e = blockIdx.x * blockDim.x + threadIdx.x;
    if (e >= EE) return;
    int d = dst[e];
    int p = atomicAdd(&g_cursor[d], 1);
    g_csrc[p] = src[e];
}

// ---------------- encoder: Linear(7->128) + LN + ReLU, warp per node ----------------
__global__ void k_encoder(const float* __restrict__ nf,
                          const float* __restrict__ w,  const float* __restrict__ b,
                          const float* __restrict__ lg, const float* __restrict__ lb) {
    int n = blockIdx.x * 8 + (threadIdx.x >> 5);
    if (n >= NN) return;
    int lane = threadIdx.x & 31;

    float f[7];
#pragma unroll
    for (int k = 0; k < 7; k++) f[k] = nf[n * 7 + k];

    float v[4];
#pragma unroll
    for (int j = 0; j < 4; j++) {
        int c = lane + 32 * j;
        float a = b[c];
#pragma unroll
        for (int k = 0; k < 7; k++) a = fmaf(f[k], w[k * HH + c], a);
        v[j] = a;
    }
    float s = 0.f, ss = 0.f;
#pragma unroll
    for (int j = 0; j < 4; j++) { s += v[j]; ss += v[j] * v[j]; }
#pragma unroll
    for (int off = 16; off > 0; off >>= 1) {
        s  += __shfl_xor_sync(0xffffffffu, s,  off);
        ss += __shfl_xor_sync(0xffffffffu, ss, off);
    }
    float mu  = s * (1.f / HH);
    float var = ss * (1.f / HH) - mu * mu;
    float inv = rsqrtf(var + LN_EPS);
#pragma unroll
    for (int j = 0; j < 4; j++) {
        int c = lane + 32 * j;
        float y = (v[j] - mu) * inv * lg[c] + lb[c];
        g_x[n * HH + c] = fmaxf(y, 0.f);
    }
}

// ---------------- GEMM: C[M,128] = A[M,128] @ W[128,128], optional row scaling ----------------
__global__ void __launch_bounds__(256, 4)
k_gemm128(const float* __restrict__ A, const float* __restrict__ W,
          float* __restrict__ C, int M, const float* __restrict__ rowscale) {
    __shared__ float ws[32][128];
    __shared__ float xs[32][64];

    int tid  = threadIdx.x;
    int colg = tid & 31;
    int rowg = tid >> 5;
    int row0 = blockIdx.x * 64;

    float acc[8][4];
#pragma unroll
    for (int i = 0; i < 8; i++)
#pragma unroll
        for (int j = 0; j < 4; j++) acc[i][j] = 0.f;

    for (int kc = 0; kc < 128; kc += 32) {
#pragma unroll
        for (int idx = tid; idx < 1024; idx += 256) {
            int k = idx >> 5, cv = idx & 31;
            *(float4*)&ws[k][cv * 4] = *(const float4*)&W[(kc + k) * 128 + cv * 4];
        }
#pragma unroll
        for (int idx = tid; idx < 512; idx += 256) {
            int r = idx & 63, kv = idx >> 6;
            float4 v = make_float4(0.f, 0.f, 0.f, 0.f);
            if (row0 + r < M) v = *(const float4*)&A[(size_t)(row0 + r) * 128 + kc + kv * 4];
            xs[kv * 4 + 0][r] = v.x;
            xs[kv * 4 + 1][r] = v.y;
            xs[kv * 4 + 2][r] = v.z;
            xs[kv * 4 + 3][r] = v.w;
        }
        __syncthreads();
#pragma unroll
        for (int k = 0; k < 32; k++) {
            float4 w4 = *(float4*)&ws[k][colg * 4];
            float4 xa = *(float4*)&xs[k][rowg * 8];
            float4 xb = *(float4*)&xs[k][rowg * 8 + 4];
            float xr[8] = {xa.x, xa.y, xa.z, xa.w, xb.x, xb.y, xb.z, xb.w};
            float wr[4] = {w4.x, w4.y, w4.z, w4.w};
#pragma unroll
            for (int i = 0; i < 8; i++)
#pragma unroll
                for (int j = 0; j < 4; j++) acc[i][j] = fmaf(xr[i], wr[j], acc[i][j]);
        }
        __syncthreads();
    }
#pragma unroll
    for (int i = 0; i < 8; i++) {
        int r = row0 + rowg * 8 + i;
        if (r < M) {
            float sc = rowscale ? rowscale[r] : 1.f;
            *(float4*)&C[(size_t)r * 128 + colg * 4] =
                make_float4(acc[i][0] * sc, acc[i][1] * sc, acc[i][2] * sc, acc[i][3] * sc);
        }
    }
}

// ---------------- fused layer: gather-agg + bias + LN + ReLU + residual ----------------
// warp per node; agg = dinv[n]*(h_scaled[n] + sum_neighbors h_scaled[s])
__global__ void __launch_bounds__(256, 8)
k_gather_ln(const float* __restrict__ cb,
            const float* __restrict__ lg, const float* __restrict__ lb,
            float* __restrict__ xout /* nullable */) {
    int n = blockIdx.x * 8 + (threadIdx.x >> 5);
    if (n >= NN) return;
    int lane = threadIdx.x & 31;

    int beg = g_rowptr[n];
    int cnt = g_deg[n];

    float4 acc = *(const float4*)&g_h[(size_t)n * 128 + lane * 4];   // self loop (pre-scaled)

    for (int base = 0; base < cnt; base += 32) {
        int k = cnt - base;
        if (k > 32) k = 32;
        int sidx = (lane < k) ? g_csrc[beg + base + lane] : 0;
        int j = 0;
        for (; j + 4 <= k; j += 4) {
            int s0 = __shfl_sync(0xffffffffu, sidx, j + 0);
            int s1 = __shfl_sync(0xffffffffu, sidx, j + 1);
            int s2 = __shfl_sync(0xffffffffu, sidx, j + 2);
            int s3 = __shfl_sync(0xffffffffu, sidx, j + 3);
            float4 v0 = *(const float4*)&g_h[(size_t)s0 * 128 + lane * 4];
            float4 v1 = *(const float4*)&g_h[(size_t)s1 * 128 + lane * 4];
            float4 v2 = *(const float4*)&g_h[(size_t)s2 * 128 + lane * 4];
            float4 v3 = *(const float4*)&g_h[(size_t)s3 * 128 + lane * 4];
            v0.x += v1.x; v0.y += v1.y; v0.z += v1.z; v0.w += v1.w;
            v2.x += v3.x; v2.y += v3.y; v2.z += v3.z; v2.w += v3.w;
            acc.x += v0.x + v2.x;
            acc.y += v0.y + v2.y;
            acc.z += v0.z + v2.z;
            acc.w += v0.w + v2.w;
        }
        for (; j < k; j++) {
            int sj = __shfl_sync(0xffffffffu, sidx, j);
            float4 v = *(const float4*)&g_h[(size_t)sj * 128 + lane * 4];
            acc.x += v.x; acc.y += v.y; acc.z += v.z; acc.w += v.w;
        }
    }

    float di = g_dinv[n];
    float4 b4 = *(const float4*)&cb[lane * 4];
    float v[4] = {acc.x * di + b4.x, acc.y * di + b4.y,
                  acc.z * di + b4.z, acc.w * di + b4.w};

    float s = 0.f, ss = 0.f;
#pragma unroll
    for (int j = 0; j < 4; j++) { s += v[j]; ss += v[j] * v[j]; }
#pragma unroll
    for (int off = 16; off > 0; off >>= 1) {
        s  += __shfl_xor_sync(0xffffffffu, s,  off);
        ss += __shfl_xor_sync(0xffffffffu, ss, off);
    }
    float mu   = s * (1.f / HH);
    float var  = ss * (1.f / HH) - mu * mu;
    float linv = rsqrtf(var + LN_EPS);

    float4 lg4 = *(const float4*)&lg[lane * 4];
    float4 lb4 = *(const float4*)&lb[lane * 4];
    float4 xo  = *(const float4*)&g_x[(size_t)n * 128 + lane * 4];

    float4 y;
    y.x = fmaxf((v[0] - mu) * linv * lg4.x + lb4.x, 0.f) + xo.x;
    y.y = fmaxf((v[1] - mu) * linv * lg4.y + lb4.y, 0.f) + xo.y;
    y.z = fmaxf((v[2] - mu) * linv * lg4.z + lb4.z, 0.f) + xo.z;
    y.w = fmaxf((v[3] - mu) * linv * lg4.w + lb4.w, 0.f) + xo.w;

    *(float4*)&g_x[(size_t)n * 128 + lane * 4] = y;
    if (xout) *(float4*)&xout[(size_t)n * 128 + lane * 4] = y;
}

// ---------------- edge MLP: logit = relu(P[s]+Q[d]+b1) . w2 + b2, warp/edge ----------------
__global__ void k_edge_mlp(const int* __restrict__ src, const int* __restrict__ dst,
                           const float* __restrict__ b1, const float* __restrict__ w2,
                           const float* __restrict__ b2, float* __restrict__ out) {
    int e = blockIdx.x * 8 + (threadIdx.x >> 5);
    if (e >= EE) return;
    int lane = threadIdx.x & 31;
    int s = src[e], d = dst[e];

    float4 p  = *(const float4*)&g_P[(size_t)s * 128 + lane * 4];
    float4 q  = *(const float4*)&g_Q[(size_t)d * 128 + lane * 4];
    float4 bb = *(const float4*)&b1[lane * 4];
    float4 w  = *(const float4*)&w2[lane * 4];

    float h0 = fmaxf(p.x + q.x + bb.x, 0.f);
    float h1 = fmaxf(p.y + q.y + bb.y, 0.f);
    float h2 = fmaxf(p.z + q.z + bb.z, 0.f);
    float h3 = fmaxf(p.w + q.w + bb.w, 0.f);
    float part = h0 * w.x + h1 * w.y + h2 * w.z + h3 * w.w;
#pragma unroll
    for (int off = 16; off > 0; off >>= 1)
        part += __shfl_xor_sync(0xffffffffu, part, off);
    if (lane == 0) out[e] = part + b2[0];
}

// ---------------- host ----------------
extern "C" void kernel_launch(void* const* d_in, const int* in_sizes, int n_in,
                              void* d_out, int out_size) {
    const float* nf       = (const float*)d_in[0];
    const int*   ei       = (const int*)  d_in[1];
    const float* enc_w    = (const float*)d_in[3];
    const float* enc_b    = (const float*)d_in[4];
    const float* enc_ln_g = (const float*)d_in[5];
    const float* enc_ln_b = (const float*)d_in[6];
    const float* conv_w   = (const float*)d_in[7];
    const float* conv_b   = (const float*)d_in[8];
    const float* ln_g     = (const float*)d_in[9];
    const float* ln_b     = (const float*)d_in[10];
    const float* mlp_w1   = (const float*)d_in[11];
    const float* mlp_b1   = (const float*)d_in[12];
    const float* mlp_w2   = (const float*)d_in[13];
    const float* mlp_b2   = (const float*)d_in[14];

    const int* src = ei;
    const int* dst = ei + EE;

    float* out        = (float*)d_out;
    float* out_logits = out + (size_t)NN * HH;

    float *px, *ph, *pP, *pQ, *pdinv;
    cudaGetSymbolAddress((void**)&px, g_x);
    cudaGetSymbolAddress((void**)&ph, g_h);
    cudaGetSymbolAddress((void**)&pP, g_P);
    cudaGetSymbolAddress((void**)&pQ, g_Q);
    cudaGetSymbolAddress((void**)&pdinv, g_dinv);

    const int GEMM_BLOCKS = (NN + 63) / 64;

    // degree + dinv
    k_deg_zero <<<(NN + 255) / 256, 256>>>();
    k_deg_count<<<(EE + 255) / 256, 256>>>(dst);
    k_dinv     <<<(NN + 255) / 256, 256>>>();

    // CSR build
    k_scanA<<<NB, 256>>>();
    k_scanB<<<1, 512>>>();
    k_scanC<<<NB, 256>>>();
    k_fill <<<(EE + 255) / 256, 256>>>(src, dst);

    // encoder
    k_encoder<<<(NN + 7) / 8, 256>>>(nf, enc_w, enc_b, enc_ln_g, enc_ln_b);

    // 3 GCN layers: h_scaled = (x@W)*dinv ; fused gather+LN+residual
    for (int l = 0; l < 3; l++) {
        k_gemm128  <<<GEMM_BLOCKS, 256>>>(px, conv_w + (size_t)l * HH * HH, ph, NN, pdinv);
        k_gather_ln<<<(NN + 7) / 8, 256>>>(conv_b + l * HH, ln_g + l * HH, ln_b + l * HH,
                                           (l == 2) ? out : nullptr);
    }

    // edge scoring
    k_gemm128<<<GEMM_BLOCKS, 256>>>(px, mlp_w1, pP, NN, nullptr);
    k_gemm128<<<GEMM_BLOCKS, 256>>>(px, mlp_w1 + HH * HH, pQ, NN, nullptr);
    k_edge_mlp<<<(EE + 7) / 8, 256>>>(src, dst, mlp_b1, mlp_w2, mlp_b2, out_logits);
}

// round 4
// speedup vs baseline: 1.8920x; 1.2855x over previous
#include <cuda_runtime.h>
#include <cuda_bf16.h>
#include <cstdint>

#define NN 100000
#define HH 128
#define EE 1600000
#define LN_EPS 1e-5f
#define NB 391          // (NN+255)/256
#define GB 782          // (NN+127)/128 gemm tiles

// ---------------- device scratch ----------------
__device__ float g_x  [NN * HH];
__device__ float g_h  [NN * HH];     // h_scaled = (x@W) * dinv[row]
__device__ float g_P  [NN * HH];
__device__ float g_Q  [NN * HH];
__device__ int   g_deg   [NN];
__device__ float g_dinv  [NN];
__device__ int   g_rowptr[NN];
__device__ int   g_cursor[NN];
__device__ int   g_csrc  [EE];
__device__ int   g_bsum  [NB];
__device__ int   g_boff  [NB];
__device__ __nv_bfloat16 g_Whi[5 * 16384];   // B = W^T, [n][k] row-major
__device__ __nv_bfloat16 g_Wlo[5 * 16384];

// ---------------- helpers ----------------
__device__ __forceinline__ uint32_t smem_u32(const void* p) {
    uint32_t a;
    asm("{ .reg .u64 t; cvta.to.shared.u64 t, %1; cvt.u32.u64 %0, t; }" : "=r"(a) : "l"(p));
    return a;
}
__device__ __forceinline__ void ldm4(uint32_t* r, uint32_t addr) {
    asm volatile("ldmatrix.sync.aligned.m8n8.x4.shared.b16 {%0,%1,%2,%3}, [%4];"
                 : "=r"(r[0]), "=r"(r[1]), "=r"(r[2]), "=r"(r[3]) : "r"(addr));
}
__device__ __forceinline__ void mma_bf16(float* d, const uint32_t* a, const uint32_t* b) {
    asm volatile("mma.sync.aligned.m16n8k16.row.col.f32.bf16.bf16.f32 "
                 "{%0,%1,%2,%3}, {%4,%5,%6,%7}, {%8,%9}, {%0,%1,%2,%3};"
                 : "+f"(d[0]), "+f"(d[1]), "+f"(d[2]), "+f"(d[3])
                 : "r"(a[0]), "r"(a[1]), "r"(a[2]), "r"(a[3]), "r"(b[0]), "r"(b[1]));
}

// ---------------- degree / norm ----------------
__global__ void k_deg_zero() {
    int i = blockIdx.x * blockDim.x + threadIdx.x;
    if (i < NN) g_deg[i] = 0;
}
__global__ void k_deg_count(const int* __restrict__ dst) {
    int i = blockIdx.x * blockDim.x + threadIdx.x;
    if (i < EE) atomicAdd(&g_deg[dst[i]], 1);
}
__global__ void k_dinv() {
    int i = blockIdx.x * blockDim.x + threadIdx.x;
    if (i < NN) g_dinv[i] = rsqrtf((float)(g_deg[i] + 1));
}

// ---------------- CSR build ----------------
__global__ void k_scanA() {
    __shared__ int ws[8];
    int i = blockIdx.x * 256 + threadIdx.x;
    int v = (i < NN) ? g_deg[i] : 0;
#pragma unroll
    for (int off = 16; off > 0; off >>= 1) v += __shfl_xor_sync(0xffffffffu, v, off);
    if ((threadIdx.x & 31) == 0) ws[threadIdx.x >> 5] = v;
    __syncthreads();
    if (threadIdx.x == 0) {
        int t = 0;
#pragma unroll
        for (int w = 0; w < 8; w++) t += ws[w];
        g_bsum[blockIdx.x] = t;
    }
}
__global__ void k_scanB() {
    __shared__ int s[512];
    int tid = threadIdx.x;
    int v = (tid < NB) ? g_bsum[tid] : 0;
    s[tid] = v;
    __syncthreads();
    for (int off = 1; off < 512; off <<= 1) {
        int t = (tid >= off) ? s[tid - off] : 0;
        __syncthreads();
        s[tid] += t;
        __syncthreads();
    }
    if (tid < NB) g_boff[tid] = s[tid] - v;
}
__global__ void k_scanC() {
    __shared__ int s[256];
    int tid = threadIdx.x;
    int i = blockIdx.x * 256 + tid;
    int v = (i < NN) ? g_deg[i] : 0;
    s[tid] = v;
    __syncthreads();
    for (int off = 1; off < 256; off <<= 1) {
        int t = (tid >= off) ? s[tid - off] : 0;
        __syncthreads();
        s[tid] += t;
        __syncthreads();
    }
    if (i < NN) {
        int r = g_boff[blockIdx.x] + s[tid] - v;
        g_rowptr[i] = r;
        g_cursor[i] = r;
    }
}
__global__ void k_fill(const int* __restrict__ src, const int* __restrict__ dst) {
    int e = blockIdx.x * blockDim.x + threadIdx.x;
    if (e >= EE) return;
    int d = dst[e];
    int p = atomicAdd(&g_cursor[d], 1);
    g_csrc[p] = src[e];
}

// ---------------- weight prep: transpose + hi/lo split, [n][k] layout ----------------
__global__ void k_prep_w(const float* __restrict__ conv_w, const float* __restrict__ mlp_w1) {
    int mat = blockIdx.x;   // 0..2 conv, 3..4 mlp halves
    const float* W = (mat < 3) ? conv_w + mat * 16384 : mlp_w1 + (mat - 3) * 16384;
    for (int idx = threadIdx.x; idx < 16384; idx += blockDim.x) {
        int n = idx >> 7, k = idx & 127;
        float w = W[k * 128 + n];                   // B[n][k] = W[k][n]
        __nv_bfloat16 hi = __float2bfloat16(w);
        __nv_bfloat16 lo = __float2bfloat16(w - __bfloat162float(hi));
        g_Whi[mat * 16384 + idx] = hi;
        g_Wlo[mat * 16384 + idx] = lo;
    }
}

// ---------------- mma.sync GEMM: C[M,128] = A[M,128] @ W, split-bf16, fp32 acc ----------------
// 128x128 tile/CTA, 8 warps, warp = 32 rows x 64 cols. smem rows padded to 272B.
#define RS 272
#define SM_AHI 0
#define SM_ALO (128 * RS)
#define SM_BHI (2 * 128 * RS)
#define SM_BLO (3 * 128 * RS)
#define SMEM_SZ (4 * 128 * RS)

__global__ void __launch_bounds__(256, 1)
k_gemm_mma(const float* __restrict__ A, int mat, float* __restrict__ C, int M,
           const float* __restrict__ rowscale) {
    extern __shared__ char smem[];
    uint32_t sb = smem_u32(smem);
    int tid = threadIdx.x, wid = tid >> 5, lane = tid & 31;
    int row0 = blockIdx.x * 128;

    // ---- fill B hi/lo (copy [n][k] 256B rows into 272B-strided rows) ----
    {
        const float4* bh = (const float4*)(g_Whi + mat * 16384);
        const float4* bl = (const float4*)(g_Wlo + mat * 16384);
#pragma unroll
        for (int i = tid; i < 2048; i += 256) {
            int n = i >> 4, seg = i & 15;
            *(float4*)(smem + SM_BHI + n * RS + seg * 16) = bh[i];
            *(float4*)(smem + SM_BLO + n * RS + seg * 16) = bl[i];
        }
    }
    // ---- fill A hi/lo: load fp32, split ----
#pragma unroll
    for (int it = 0; it < 16; it++) {
        int r = it * 8 + wid;
        int kc = lane * 4;
        int grow = row0 + r;
        float4 v = make_float4(0.f, 0.f, 0.f, 0.f);
        if (grow < M) v = *(const float4*)&A[(size_t)grow * 128 + kc];
        __nv_bfloat16 h0 = __float2bfloat16(v.x), h1 = __float2bfloat16(v.y);
        __nv_bfloat16 h2 = __float2bfloat16(v.z), h3 = __float2bfloat16(v.w);
        __nv_bfloat16 l0 = __float2bfloat16(v.x - __bfloat162float(h0));
        __nv_bfloat16 l1 = __float2bfloat16(v.y - __bfloat162float(h1));
        __nv_bfloat16 l2 = __float2bfloat16(v.z - __bfloat162float(h2));
        __nv_bfloat16 l3 = __float2bfloat16(v.w - __bfloat162float(h3));
        __nv_bfloat162 hA = {h0, h1}, hB = {h2, h3}, lA = {l0, l1}, lB = {l2, l3};
        uint2 hp = {*(uint32_t*)&hA, *(uint32_t*)&hB};
        uint2 lp = {*(uint32_t*)&lA, *(uint32_t*)&lB};
        *(uint2*)(smem + SM_AHI + r * RS + lane * 8) = hp;
        *(uint2*)(smem + SM_ALO + r * RS + lane * 8) = lp;
    }
    __syncthreads();

    // ---- per-thread ldmatrix base addresses (k-step 0) ----
    // A x4: t0-7 rows0-7@k0 | t8-15 rows8-15@k0 | t16-23 rows0-7@k8 | t24-31 rows8-15@k8
    int arow = (wid >> 1) * 32 + (lane & 7) + ((lane >> 3) & 1) * 8;
    uint32_t akb = ((lane >> 4) & 1) * 16;
    uint32_t aA0 = sb + SM_AHI + arow * RS + akb;           // m-tile 0 (hi)
    uint32_t aA1 = aA0 + 16 * RS;                           // m-tile 1 (hi)
    // B x4: m0 = n0-7@k0 (b0,t0), m1 = n0-7@k8 (b1,t0), m2 = n8-15@k0, m3 = n8-15@k8
    int brow = (lane & 7) + ((lane >> 4) & 1) * 8;
    uint32_t bkb = ((lane >> 3) & 1) * 16;
    uint32_t bB0 = sb + SM_BHI + ((wid & 1) * 64 + brow) * RS + bkb;   // g=0 (hi)

    float acc[2][8][4];
#pragma unroll
    for (int m = 0; m < 2; m++)
#pragma unroll
        for (int n = 0; n < 8; n++)
#pragma unroll
            for (int j = 0; j < 4; j++) acc[m][n][j] = 0.f;

#pragma unroll
    for (int ks = 0; ks < 8; ks++) {
        uint32_t ko = ks * 32;
        uint32_t ahi[2][4], alo[2][4];
        ldm4(ahi[0], aA0 + ko);
        ldm4(ahi[1], aA1 + ko);
        ldm4(alo[0], aA0 + (SM_ALO - SM_AHI) + ko);
        ldm4(alo[1], aA1 + (SM_ALO - SM_AHI) + ko);
#pragma unroll
        for (int g = 0; g < 4; g++) {
            uint32_t bhi[4], blo[4];
            ldm4(bhi, bB0 + g * 16 * RS + ko);
            ldm4(blo, bB0 + g * 16 * RS + (SM_BLO - SM_BHI) + ko);
#pragma unroll
            for (int h = 0; h < 2; h++) {
                int n = g * 2 + h;
#pragma unroll
                for (int m = 0; m < 2; m++) {
                    mma_bf16(acc[m][n], ahi[m], &bhi[h * 2]);   // hi*hi
                    mma_bf16(acc[m][n], ahi[m], &blo[h * 2]);   // hi*lo
                    mma_bf16(acc[m][n], alo[m], &bhi[h * 2]);   // lo*hi
                }
            }
        }
    }

    // ---- epilogue: c0,c1 -> (row, col..col+1); c2,c3 -> (row+8, ...) ----
    int rbase = row0 + (wid >> 1) * 32;
    int cbase = (wid & 1) * 64;
#pragma unroll
    for (int m = 0; m < 2; m++) {
        int r0r = rbase + m * 16 + (lane >> 2);
        int r1r = r0r + 8;
        float s0 = 1.f, s1 = 1.f;
        if (rowscale) {
            if (r0r < M) s0 = rowscale[r0r];
            if (r1r < M) s1 = rowscale[r1r];
        }
#pragma unroll
        for (int n = 0; n < 8; n++) {
            int col = cbase + n * 8 + (lane & 3) * 2;
            if (r0r < M) {
                float2 o = {acc[m][n][0] * s0, acc[m][n][1] * s0};
                *(float2*)&C[(size_t)r0r * 128 + col] = o;
            }
            if (r1r < M) {
                float2 o = {acc[m][n][2] * s1, acc[m][n][3] * s1};
                *(float2*)&C[(size_t)r1r * 128 + col] = o;
            }
        }
    }
}

// ---------------- encoder: Linear(7->128) + LN + ReLU, warp per node ----------------
__global__ void k_encoder(const float* __restrict__ nf,
                          const float* __restrict__ w,  const float* __restrict__ b,
                          const float* __restrict__ lg, const float* __restrict__ lb) {
    int n = blockIdx.x * 8 + (threadIdx.x >> 5);
    if (n >= NN) return;
    int lane = threadIdx.x & 31;

    float f[7];
#pragma unroll
    for (int k = 0; k < 7; k++) f[k] = nf[n * 7 + k];

    float v[4];
#pragma unroll
    for (int j = 0; j < 4; j++) {
        int c = lane + 32 * j;
        float a = b[c];
#pragma unroll
        for (int k = 0; k < 7; k++) a = fmaf(f[k], w[k * HH + c], a);
        v[j] = a;
    }
    float s = 0.f, ss = 0.f;
#pragma unroll
    for (int j = 0; j < 4; j++) { s += v[j]; ss += v[j] * v[j]; }
#pragma unroll
    for (int off = 16; off > 0; off >>= 1) {
        s  += __shfl_xor_sync(0xffffffffu, s,  off);
        ss += __shfl_xor_sync(0xffffffffu, ss, off);
    }
    float mu  = s * (1.f / HH);
    float var = ss * (1.f / HH) - mu * mu;
    float inv = rsqrtf(var + LN_EPS);
#pragma unroll
    for (int j = 0; j < 4; j++) {
        int c = lane + 32 * j;
        float y = (v[j] - mu) * inv * lg[c] + lb[c];
        g_x[n * HH + c] = fmaxf(y, 0.f);
    }
}

// ---------------- fused layer: gather-agg + bias + LN + ReLU + residual ----------------
__global__ void __launch_bounds__(256, 8)
k_gather_ln(const float* __restrict__ cb,
            const float* __restrict__ lg, const float* __restrict__ lb,
            float* __restrict__ xout) {
    int n = blockIdx.x * 8 + (threadIdx.x >> 5);
    if (n >= NN) return;
    int lane = threadIdx.x & 31;

    int beg = g_rowptr[n];
    int cnt = g_deg[n];

    float4 acc = *(const float4*)&g_h[(size_t)n * 128 + lane * 4];

    for (int base = 0; base < cnt; base += 32) {
        int k = cnt - base;
        if (k > 32) k = 32;
        int sidx = (lane < k) ? g_csrc[beg + base + lane] : 0;
        int j = 0;
        for (; j + 4 <= k; j += 4) {
            int s0 = __shfl_sync(0xffffffffu, sidx, j + 0);
            int s1 = __shfl_sync(0xffffffffu, sidx, j + 1);
            int s2 = __shfl_sync(0xffffffffu, sidx, j + 2);
            int s3 = __shfl_sync(0xffffffffu, sidx, j + 3);
            float4 v0 = *(const float4*)&g_h[(size_t)s0 * 128 + lane * 4];
            float4 v1 = *(const float4*)&g_h[(size_t)s1 * 128 + lane * 4];
            float4 v2 = *(const float4*)&g_h[(size_t)s2 * 128 + lane * 4];
            float4 v3 = *(const float4*)&g_h[(size_t)s3 * 128 + lane * 4];
            v0.x += v1.x; v0.y += v1.y; v0.z += v1.z; v0.w += v1.w;
            v2.x += v3.x; v2.y += v3.y; v2.z += v3.z; v2.w += v3.w;
            acc.x += v0.x + v2.x;
            acc.y += v0.y + v2.y;
            acc.z += v0.z + v2.z;
            acc.w += v0.w + v2.w;
        }
        for (; j < k; j++) {
            int sj = __shfl_sync(0xffffffffu, sidx, j);
            float4 v = *(const float4*)&g_h[(size_t)sj * 128 + lane * 4];
            acc.x += v.x; acc.y += v.y; acc.z += v.z; acc.w += v.w;
        }
    }

    float di = g_dinv[n];
    float4 b4 = *(const float4*)&cb[lane * 4];
    float v[4] = {acc.x * di + b4.x, acc.y * di + b4.y,
                  acc.z * di + b4.z, acc.w * di + b4.w};

    float s = 0.f, ss = 0.f;
#pragma unroll
    for (int j = 0; j < 4; j++) { s += v[j]; ss += v[j] * v[j]; }
#pragma unroll
    for (int off = 16; off > 0; off >>= 1) {
        s  += __shfl_xor_sync(0xffffffffu, s,  off);
        ss += __shfl_xor_sync(0xffffffffu, ss, off);
    }
    float mu   = s * (1.f / HH);
    float var  = ss * (1.f / HH) - mu * mu;
    float linv = rsqrtf(var + LN_EPS);

    float4 lg4 = *(const float4*)&lg[lane * 4];
    float4 lb4 = *(const float4*)&lb[lane * 4];
    float4 xo  = *(const float4*)&g_x[(size_t)n * 128 + lane * 4];

    float4 y;
    y.x = fmaxf((v[0] - mu) * linv * lg4.x + lb4.x, 0.f) + xo.x;
    y.y = fmaxf((v[1] - mu) * linv * lg4.y + lb4.y, 0.f) + xo.y;
    y.z = fmaxf((v[2] - mu) * linv * lg4.z + lb4.z, 0.f) + xo.z;
    y.w = fmaxf((v[3] - mu) * linv * lg4.w + lb4.w, 0.f) + xo.w;

    *(float4*)&g_x[(size_t)n * 128 + lane * 4] = y;
    if (xout) *(float4*)&xout[(size_t)n * 128 + lane * 4] = y;
}

// ---------------- edge MLP ----------------
__global__ void k_edge_mlp(const int* __restrict__ src, const int* __restrict__ dst,
                           const float* __restrict__ b1, const float* __restrict__ w2,
                           const float* __restrict__ b2, float* __restrict__ out) {
    int e = blockIdx.x * 8 + (threadIdx.x >> 5);
    if (e >= EE) return;
    int lane = threadIdx.x & 31;
    int s = src[e], d = dst[e];

    float4 p  = *(const float4*)&g_P[(size_t)s * 128 + lane * 4];
    float4 q  = *(const float4*)&g_Q[(size_t)d * 128 + lane * 4];
    float4 bb = *(const float4*)&b1[lane * 4];
    float4 w  = *(const float4*)&w2[lane * 4];

    float h0 = fmaxf(p.x + q.x + bb.x, 0.f);
    float h1 = fmaxf(p.y + q.y + bb.y, 0.f);
    float h2 = fmaxf(p.z + q.z + bb.z, 0.f);
    float h3 = fmaxf(p.w + q.w + bb.w, 0.f);
    float part = h0 * w.x + h1 * w.y + h2 * w.z + h3 * w.w;
#pragma unroll
    for (int off = 16; off > 0; off >>= 1)
        part += __shfl_xor_sync(0xffffffffu, part, off);
    if (lane == 0) out[e] = part + b2[0];
}

// ---------------- host ----------------
extern "C" void kernel_launch(void* const* d_in, const int* in_sizes, int n_in,
                              void* d_out, int out_size) {
    const float* nf       = (const float*)d_in[0];
    const int*   ei       = (const int*)  d_in[1];
    const float* enc_w    = (const float*)d_in[3];
    const float* enc_b    = (const float*)d_in[4];
    const float* enc_ln_g = (const float*)d_in[5];
    const float* enc_ln_b = (const float*)d_in[6];
    const float* conv_w   = (const float*)d_in[7];
    const float* conv_b   = (const float*)d_in[8];
    const float* ln_g     = (const float*)d_in[9];
    const float* ln_b     = (const float*)d_in[10];
    const float* mlp_w1   = (const float*)d_in[11];
    const float* mlp_b1   = (const float*)d_in[12];
    const float* mlp_w2   = (const float*)d_in[13];
    const float* mlp_b2   = (const float*)d_in[14];

    const int* src = ei;
    const int* dst = ei + EE;

    float* out        = (float*)d_out;
    float* out_logits = out + (size_t)NN * HH;

    float *px, *ph, *pP, *pQ, *pdinv;
    cudaGetSymbolAddress((void**)&px, g_x);
    cudaGetSymbolAddress((void**)&ph, g_h);
    cudaGetSymbolAddress((void**)&pP, g_P);
    cudaGetSymbolAddress((void**)&pQ, g_Q);
    cudaGetSymbolAddress((void**)&pdinv, g_dinv);

    cudaFuncSetAttribute(k_gemm_mma, cudaFuncAttributeMaxDynamicSharedMemorySize, SMEM_SZ);

    // degree + dinv
    k_deg_zero <<<(NN + 255) / 256, 256>>>();
    k_deg_count<<<(EE + 255) / 256, 256>>>(dst);
    k_dinv     <<<(NN + 255) / 256, 256>>>();

    // CSR build + weight prep (independent of x)
    k_scanA<<<NB, 256>>>();
    k_scanB<<<1, 512>>>();
    k_scanC<<<NB, 256>>>();
    k_fill <<<(EE + 255) / 256, 256>>>(src, dst);
    k_prep_w<<<5, 256>>>(conv_w, mlp_w1);

    // encoder
    k_encoder<<<(NN + 7) / 8, 256>>>(nf, enc_w, enc_b, enc_ln_g, enc_ln_b);

    // 3 GCN layers
    for (int l = 0; l < 3; l++) {
        k_gemm_mma <<<GB, 256, SMEM_SZ>>>(px, l, ph, NN, pdinv);
        k_gather_ln<<<(NN + 7) / 8, 256>>>(conv_b + l * HH, ln_g + l * HH, ln_b + l * HH,
                                           (l == 2) ? out : nullptr);
    }

    // edge scoring
    k_gemm_mma<<<GB, 256, SMEM_SZ>>>(px, 3, pP, NN, nullptr);
    k_gemm_mma<<<GB, 256, SMEM_SZ>>>(px, 4, pQ, NN, nullptr);
    k_edge_mlp<<<(EE + 7) / 8, 256>>>(src, dst, mlp_b1, mlp_w2, mlp_b2, out_logits);
}

// round 5
// speedup vs baseline: 2.3110x; 1.2214x over previous
#include <cuda_runtime.h>
#include <cuda_bf16.h>
#include <cstdint>

#define NN 100000
#define HH 128
#define EE 1600000
#define LN_EPS 1e-5f
#define NB 391          // (NN+255)/256
#define GB 782          // (NN+127)/128 gemm tiles

// ---------------- device scratch ----------------
__device__ float g_x  [NN * HH];
__device__ float g_h  [NN * HH];     // h_scaled = (x@W) * dinv[row]
__device__ float g_P  [NN * HH];
__device__ float g_Q  [NN * HH];
__device__ int   g_deg   [NN];
__device__ float g_dinv  [NN];
__device__ int   g_rowptr[NN];
__device__ int   g_cursor[NN];
__device__ int   g_csrc  [EE];
__device__ int   g_eid   [EE];
__device__ int   g_bsum  [NB];
__device__ int   g_boff  [NB];
__device__ __nv_bfloat16 g_Whi[5 * 16384];   // B = W^T, [n][k] row-major
__device__ __nv_bfloat16 g_Wlo[5 * 16384];

// ---------------- helpers ----------------
__device__ __forceinline__ uint32_t smem_u32(const void* p) {
    uint32_t a;
    asm("{ .reg .u64 t; cvta.to.shared.u64 t, %1; cvt.u32.u64 %0, t; }" : "=r"(a) : "l"(p));
    return a;
}
__device__ __forceinline__ void ldm4(uint32_t* r, uint32_t addr) {
    asm volatile("ldmatrix.sync.aligned.m8n8.x4.shared.b16 {%0,%1,%2,%3}, [%4];"
                 : "=r"(r[0]), "=r"(r[1]), "=r"(r[2]), "=r"(r[3]) : "r"(addr));
}
__device__ __forceinline__ void mma_bf16(float* d, const uint32_t* a, const uint32_t* b) {
    asm volatile("mma.sync.aligned.m16n8k16.row.col.f32.bf16.bf16.f32 "
                 "{%0,%1,%2,%3}, {%4,%5,%6,%7}, {%8,%9}, {%0,%1,%2,%3};"
                 : "+f"(d[0]), "+f"(d[1]), "+f"(d[2]), "+f"(d[3])
                 : "r"(a[0]), "r"(a[1]), "r"(a[2]), "r"(a[3]), "r"(b[0]), "r"(b[1]));
}

// ---------------- degree ----------------
__global__ void k_deg_zero() {
    int i = blockIdx.x * blockDim.x + threadIdx.x;
    if (i < NN) g_deg[i] = 0;
}
__global__ void k_deg_count(const int* __restrict__ dst) {
    int i = blockIdx.x * blockDim.x + threadIdx.x;
    if (i < EE) atomicAdd(&g_deg[dst[i]], 1);
}

// ---------------- CSR build ----------------
__global__ void k_scanA() {
    __shared__ int ws[8];
    int i = blockIdx.x * 256 + threadIdx.x;
    int v = (i < NN) ? g_deg[i] : 0;
#pragma unroll
    for (int off = 16; off > 0; off >>= 1) v += __shfl_xor_sync(0xffffffffu, v, off);
    if ((threadIdx.x & 31) == 0) ws[threadIdx.x >> 5] = v;
    __syncthreads();
    if (threadIdx.x == 0) {
        int t = 0;
#pragma unroll
        for (int w = 0; w < 8; w++) t += ws[w];
        g_bsum[blockIdx.x] = t;
    }
}
__global__ void k_scanB() {
    __shared__ int s[512];
    int tid = threadIdx.x;
    int v = (tid < NB) ? g_bsum[tid] : 0;
    s[tid] = v;
    __syncthreads();
    for (int off = 1; off < 512; off <<= 1) {
        int t = (tid >= off) ? s[tid - off] : 0;
        __syncthreads();
        s[tid] += t;
        __syncthreads();
    }
    if (tid < NB) g_boff[tid] = s[tid] - v;
}
__global__ void k_scanC() {   // also computes dinv (deg already loaded)
    __shared__ int s[256];
    int tid = threadIdx.x;
    int i = blockIdx.x * 256 + tid;
    int v = (i < NN) ? g_deg[i] : 0;
    s[tid] = v;
    __syncthreads();
    for (int off = 1; off < 256; off <<= 1) {
        int t = (tid >= off) ? s[tid - off] : 0;
        __syncthreads();
        s[tid] += t;
        __syncthreads();
    }
    if (i < NN) {
        int r = g_boff[blockIdx.x] + s[tid] - v;
        g_rowptr[i] = r;
        g_cursor[i] = r;
        g_dinv[i] = rsqrtf((float)(v + 1));
    }
}
__global__ void k_fill(const int* __restrict__ src, const int* __restrict__ dst) {
    int e = blockIdx.x * blockDim.x + threadIdx.x;
    if (e >= EE) return;
    int d = dst[e];
    int p = atomicAdd(&g_cursor[d], 1);
    g_csrc[p] = src[e];
    g_eid[p] = e;
}

// ---------------- weight prep: transpose + hi/lo split, [n][k] layout ----------------
__global__ void k_prep_w(const float* __restrict__ conv_w, const float* __restrict__ mlp_w1) {
    int mat = blockIdx.x;   // 0..2 conv, 3..4 mlp halves
    const float* W = (mat < 3) ? conv_w + mat * 16384 : mlp_w1 + (mat - 3) * 16384;
    for (int idx = threadIdx.x; idx < 16384; idx += blockDim.x) {
        int n = idx >> 7, k = idx & 127;
        float w = W[k * 128 + n];                   // B[n][k] = W[k][n]
        __nv_bfloat16 hi = __float2bfloat16(w);
        __nv_bfloat16 lo = __float2bfloat16(w - __bfloat162float(hi));
        g_Whi[mat * 16384 + idx] = hi;
        g_Wlo[mat * 16384 + idx] = lo;
    }
}

// ---------------- mma.sync GEMM: C[M,128] = A[M,128] @ W, split-bf16, fp32 acc ----------------
#define RS 272
#define SM_AHI 0
#define SM_ALO (128 * RS)
#define SM_BHI (2 * 128 * RS)
#define SM_BLO (3 * 128 * RS)
#define SMEM_SZ (4 * 128 * RS)

__device__ __forceinline__ void gemm_fill_A(char* smem, const float* __restrict__ A,
                                            int row0, int M, int wid, int lane) {
#pragma unroll
    for (int it = 0; it < 16; it++) {
        int r = it * 8 + wid;
        int kc = lane * 4;
        int grow = row0 + r;
        float4 v = make_float4(0.f, 0.f, 0.f, 0.f);
        if (grow < M) v = *(const float4*)&A[(size_t)grow * 128 + kc];
        __nv_bfloat16 h0 = __float2bfloat16(v.x), h1 = __float2bfloat16(v.y);
        __nv_bfloat16 h2 = __float2bfloat16(v.z), h3 = __float2bfloat16(v.w);
        __nv_bfloat16 l0 = __float2bfloat16(v.x - __bfloat162float(h0));
        __nv_bfloat16 l1 = __float2bfloat16(v.y - __bfloat162float(h1));
        __nv_bfloat16 l2 = __float2bfloat16(v.z - __bfloat162float(h2));
        __nv_bfloat16 l3 = __float2bfloat16(v.w - __bfloat162float(h3));
        __nv_bfloat162 hA = {h0, h1}, hB = {h2, h3}, lA = {l0, l1}, lB = {l2, l3};
        uint2 hp = {*(uint32_t*)&hA, *(uint32_t*)&hB};
        uint2 lp = {*(uint32_t*)&lA, *(uint32_t*)&lB};
        *(uint2*)(smem + SM_AHI + r * RS + lane * 8) = hp;
        *(uint2*)(smem + SM_ALO + r * RS + lane * 8) = lp;
    }
}

__device__ __forceinline__ void gemm_fill_B(char* smem, int mat, int tid) {
    const float4* bh = (const float4*)(g_Whi + mat * 16384);
    const float4* bl = (const float4*)(g_Wlo + mat * 16384);
#pragma unroll
    for (int i = tid; i < 2048; i += 256) {
        int n = i >> 4, seg = i & 15;
        *(float4*)(smem + SM_BHI + n * RS + seg * 16) = bh[i];
        *(float4*)(smem + SM_BLO + n * RS + seg * 16) = bl[i];
    }
}

__device__ __forceinline__ void gemm_core_epi(char* smem, uint32_t sb,
                                              float* __restrict__ C, int M,
                                              const float* __restrict__ rowscale,
                                              int row0, int wid, int lane) {
    int arow = (wid >> 1) * 32 + (lane & 7) + ((lane >> 3) & 1) * 8;
    uint32_t akb = ((lane >> 4) & 1) * 16;
    uint32_t aA0 = sb + SM_AHI + arow * RS + akb;
    uint32_t aA1 = aA0 + 16 * RS;
    int brow = (lane & 7) + ((lane >> 4) & 1) * 8;
    uint32_t bkb = ((lane >> 3) & 1) * 16;
    uint32_t bB0 = sb + SM_BHI + ((wid & 1) * 64 + brow) * RS + bkb;

    float acc[2][8][4];
#pragma unroll
    for (int m = 0; m < 2; m++)
#pragma unroll
        for (int n = 0; n < 8; n++)
#pragma unroll
            for (int j = 0; j < 4; j++) acc[m][n][j] = 0.f;

#pragma unroll
    for (int ks = 0; ks < 8; ks++) {
        uint32_t ko = ks * 32;
        uint32_t ahi[2][4], alo[2][4];
        ldm4(ahi[0], aA0 + ko);
        ldm4(ahi[1], aA1 + ko);
        ldm4(alo[0], aA0 + (SM_ALO - SM_AHI) + ko);
        ldm4(alo[1], aA1 + (SM_ALO - SM_AHI) + ko);
#pragma unroll
        for (int g = 0; g < 4; g++) {
            uint32_t bhi[4], blo[4];
            ldm4(bhi, bB0 + g * 16 * RS + ko);
            ldm4(blo, bB0 + g * 16 * RS + (SM_BLO - SM_BHI) + ko);
#pragma unroll
            for (int h = 0; h < 2; h++) {
                int n = g * 2 + h;
#pragma unroll
                for (int m = 0; m < 2; m++) {
                    mma_bf16(acc[m][n], ahi[m], &bhi[h * 2]);
                    mma_bf16(acc[m][n], ahi[m], &blo[h * 2]);
                    mma_bf16(acc[m][n], alo[m], &bhi[h * 2]);
                }
            }
        }
    }

    int rbase = row0 + (wid >> 1) * 32;
    int cbase = (wid & 1) * 64;
#pragma unroll
    for (int m = 0; m < 2; m++) {
        int r0r = rbase + m * 16 + (lane >> 2);
        int r1r = r0r + 8;
        float s0 = 1.f, s1 = 1.f;
        if (rowscale) {
            if (r0r < M) s0 = rowscale[r0r];
            if (r1r < M) s1 = rowscale[r1r];
        }
#pragma unroll
        for (int n = 0; n < 8; n++) {
            int col = cbase + n * 8 + (lane & 3) * 2;
            if (r0r < M) {
                float2 o = {acc[m][n][0] * s0, acc[m][n][1] * s0};
                *(float2*)&C[(size_t)r0r * 128 + col] = o;
            }
            if (r1r < M) {
                float2 o = {acc[m][n][2] * s1, acc[m][n][3] * s1};
                *(float2*)&C[(size_t)r1r * 128 + col] = o;
            }
        }
    }
}

__global__ void __launch_bounds__(256, 1)
k_gemm_mma(const float* __restrict__ A, int mat, float* __restrict__ C, int M,
           const float* __restrict__ rowscale) {
    extern __shared__ char smem[];
    uint32_t sb = smem_u32(smem);
    int tid = threadIdx.x, wid = tid >> 5, lane = tid & 31;
    int row0 = blockIdx.x * 128;
    gemm_fill_B(smem, mat, tid);
    gemm_fill_A(smem, A, row0, M, wid, lane);
    __syncthreads();
    gemm_core_epi(smem, sb, C, M, rowscale, row0, wid, lane);
}

// P and Q in one pass: A loaded once, B swapped between the two mats
__global__ void __launch_bounds__(256, 1)
k_gemm_pq(const float* __restrict__ A, float* __restrict__ P, float* __restrict__ Q, int M) {
    extern __shared__ char smem[];
    uint32_t sb = smem_u32(smem);
    int tid = threadIdx.x, wid = tid >> 5, lane = tid & 31;
    int row0 = blockIdx.x * 128;
    gemm_fill_A(smem, A, row0, M, wid, lane);
    gemm_fill_B(smem, 3, tid);
    __syncthreads();
    gemm_core_epi(smem, sb, P, M, nullptr, row0, wid, lane);
    __syncthreads();
    gemm_fill_B(smem, 4, tid);
    __syncthreads();
    gemm_core_epi(smem, sb, Q, M, nullptr, row0, wid, lane);
}

// ---------------- encoder: Linear(7->128) + LN + ReLU, warp loops over nodes ----------------
__global__ void k_encoder(const float* __restrict__ nf,
                          const float* __restrict__ w,  const float* __restrict__ b,
                          const float* __restrict__ lg, const float* __restrict__ lb) {
    int gw = blockIdx.x * 8 + (threadIdx.x >> 5);
    int nw = gridDim.x * 8;
    int lane = threadIdx.x & 31;

    // hoist per-lane column params into registers (invariant across nodes)
    float wr[7][4], br[4], lgr[4], lbr[4];
#pragma unroll
    for (int j = 0; j < 4; j++) {
        int c = lane + 32 * j;
        br[j] = b[c]; lgr[j] = lg[c]; lbr[j] = lb[c];
#pragma unroll
        for (int k = 0; k < 7; k++) wr[k][j] = w[k * HH + c];
    }

    for (int n = gw; n < NN; n += nw) {
        float f[7];
#pragma unroll
        for (int k = 0; k < 7; k++) f[k] = nf[n * 7 + k];

        float v[4];
#pragma unroll
        for (int j = 0; j < 4; j++) {
            float a = br[j];
#pragma unroll
            for (int k = 0; k < 7; k++) a = fmaf(f[k], wr[k][j], a);
            v[j] = a;
        }
        float s = 0.f, ss = 0.f;
#pragma unroll
        for (int j = 0; j < 4; j++) { s += v[j]; ss += v[j] * v[j]; }
#pragma unroll
        for (int off = 16; off > 0; off >>= 1) {
            s  += __shfl_xor_sync(0xffffffffu, s,  off);
            ss += __shfl_xor_sync(0xffffffffu, ss, off);
        }
        float mu  = s * (1.f / HH);
        float var = ss * (1.f / HH) - mu * mu;
        float inv = rsqrtf(var + LN_EPS);
#pragma unroll
        for (int j = 0; j < 4; j++) {
            int c = lane + 32 * j;
            float y = (v[j] - mu) * inv * lgr[j] + lbr[j];
            g_x[(size_t)n * HH + c] = fmaxf(y, 0.f);
        }
    }
}

// ---------------- fused layer: gather-agg + bias + LN + ReLU + residual ----------------
__global__ void __launch_bounds__(256, 8)
k_gather_ln(const float* __restrict__ cb,
            const float* __restrict__ lg, const float* __restrict__ lb,
            float* __restrict__ xout) {
    int n = blockIdx.x * 8 + (threadIdx.x >> 5);
    if (n >= NN) return;
    int lane = threadIdx.x & 31;

    int beg = g_rowptr[n];
    int cnt = g_deg[n];

    float4 acc = *(const float4*)&g_h[(size_t)n * 128 + lane * 4];

    for (int base = 0; base < cnt; base += 32) {
        int k = cnt - base;
        if (k > 32) k = 32;
        int sidx = (lane < k) ? g_csrc[beg + base + lane] : 0;
        int j = 0;
        for (; j + 4 <= k; j += 4) {
            int s0 = __shfl_sync(0xffffffffu, sidx, j + 0);
            int s1 = __shfl_sync(0xffffffffu, sidx, j + 1);
            int s2 = __shfl_sync(0xffffffffu, sidx, j + 2);
            int s3 = __shfl_sync(0xffffffffu, sidx, j + 3);
            float4 v0 = *(const float4*)&g_h[(size_t)s0 * 128 + lane * 4];
            float4 v1 = *(const float4*)&g_h[(size_t)s1 * 128 + lane * 4];
            float4 v2 = *(const float4*)&g_h[(size_t)s2 * 128 + lane * 4];
            float4 v3 = *(const float4*)&g_h[(size_t)s3 * 128 + lane * 4];
            v0.x += v1.x; v0.y += v1.y; v0.z += v1.z; v0.w += v1.w;
            v2.x += v3.x; v2.y += v3.y; v2.z += v3.z; v2.w += v3.w;
            acc.x += v0.x + v2.x;
            acc.y += v0.y + v2.y;
            acc.z += v0.z + v2.z;
            acc.w += v0.w + v2.w;
        }
        for (; j < k; j++) {
            int sj = __shfl_sync(0xffffffffu, sidx, j);
            float4 v = *(const float4*)&g_h[(size_t)sj * 128 + lane * 4];
            acc.x += v.x; acc.y += v.y; acc.z += v.z; acc.w += v.w;
        }
    }

    float di = g_dinv[n];
    float4 b4 = *(const float4*)&cb[lane * 4];
    float v[4] = {acc.x * di + b4.x, acc.y * di + b4.y,
                  acc.z * di + b4.z, acc.w * di + b4.w};

    float s = 0.f, ss = 0.f;
#pragma unroll
    for (int j = 0; j < 4; j++) { s += v[j]; ss += v[j] * v[j]; }
#pragma unroll
    for (int off = 16; off > 0; off >>= 1) {
        s  += __shfl_xor_sync(0xffffffffu, s,  off);
        ss += __shfl_xor_sync(0xffffffffu, ss, off);
    }
    float mu   = s * (1.f / HH);
    float var  = ss * (1.f / HH) - mu * mu;
    float linv = rsqrtf(var + LN_EPS);

    float4 lg4 = *(const float4*)&lg[lane * 4];
    float4 lb4 = *(const float4*)&lb[lane * 4];
    float4 xo  = *(const float4*)&g_x[(size_t)n * 128 + lane * 4];

    float4 y;
    y.x = fmaxf((v[0] - mu) * linv * lg4.x + lb4.x, 0.f) + xo.x;
    y.y = fmaxf((v[1] - mu) * linv * lg4.y + lb4.y, 0.f) + xo.y;
    y.z = fmaxf((v[2] - mu) * linv * lg4.z + lb4.z, 0.f) + xo.z;
    y.w = fmaxf((v[3] - mu) * linv * lg4.w + lb4.w, 0.f) + xo.w;

    *(float4*)&g_x[(size_t)n * 128 + lane * 4] = y;
    if (xout) *(float4*)&xout[(size_t)n * 128 + lane * 4] = y;
}

// ---------------- edge MLP, CSR-grouped by dst: Q row loaded once per node ----------------
__global__ void __launch_bounds__(256, 8)
k_edge_mlp_csr(const float* __restrict__ b1, const float* __restrict__ w2,
               const float* __restrict__ b2, float* __restrict__ out) {
    int n = blockIdx.x * 8 + (threadIdx.x >> 5);
    if (n >= NN) return;
    int lane = threadIdx.x & 31;

    int beg = g_rowptr[n];
    int cnt = g_deg[n];
    if (cnt == 0) return;

    float4 qb = *(const float4*)&g_Q[(size_t)n * 128 + lane * 4];
    float4 bb = *(const float4*)&b1[lane * 4];
    qb.x += bb.x; qb.y += bb.y; qb.z += bb.z; qb.w += bb.w;
    float4 w = *(const float4*)&w2[lane * 4];
    float bias2 = b2[0];

    for (int base = 0; base < cnt; base += 32) {
        int k = cnt - base;
        if (k > 32) k = 32;
        int sidx = 0, eidx = 0;
        if (lane < k) {
            sidx = g_csrc[beg + base + lane];
            eidx = g_eid [beg + base + lane];
        }
        float myval = 0.f;
        for (int j = 0; j < k; j++) {
            int sj = __shfl_sync(0xffffffffu, sidx, j);
            float4 p = *(const float4*)&g_P[(size_t)sj * 128 + lane * 4];
            float h0 = fmaxf(p.x + qb.x, 0.f);
            float h1 = fmaxf(p.y + qb.y, 0.f);
            float h2 = fmaxf(p.z + qb.z, 0.f);
            float h3 = fmaxf(p.w + qb.w, 0.f);
            float part = fmaf(h0, w.x, fmaf(h1, w.y, fmaf(h2, w.z, h3 * w.w)));
#pragma unroll
            for (int off = 16; off > 0; off >>= 1)
                part += __shfl_xor_sync(0xffffffffu, part, off);
            if (lane == j) myval = part;
        }
        if (lane < k) out[eidx] = myval + bias2;
    }
}

// ---------------- host ----------------
extern "C" void kernel_launch(void* const* d_in, const int* in_sizes, int n_in,
                              void* d_out, int out_size) {
    const float* nf       = (const float*)d_in[0];
    const int*   ei       = (const int*)  d_in[1];
    const float* enc_w    = (const float*)d_in[3];
    const float* enc_b    = (const float*)d_in[4];
    const float* enc_ln_g = (const float*)d_in[5];
    const float* enc_ln_b = (const float*)d_in[6];
    const float* conv_w   = (const float*)d_in[7];
    const float* conv_b   = (const float*)d_in[8];
    const float* ln_g     = (const float*)d_in[9];
    const float* ln_b     = (const float*)d_in[10];
    const float* mlp_w1   = (const float*)d_in[11];
    const float* mlp_b1   = (const float*)d_in[12];
    const float* mlp_w2   = (const float*)d_in[13];
    const float* mlp_b2   = (const float*)d_in[14];

    const int* src = ei;
    const int* dst = ei + EE;

    float* out        = (float*)d_out;
    float* out_logits = out + (size_t)NN * HH;

    float *px, *ph, *pP, *pQ, *pdinv;
    cudaGetSymbolAddress((void**)&px, g_x);
    cudaGetSymbolAddress((void**)&ph, g_h);
    cudaGetSymbolAddress((void**)&pP, g_P);
    cudaGetSymbolAddress((void**)&pQ, g_Q);
    cudaGetSymbolAddress((void**)&pdinv, g_dinv);

    cudaFuncSetAttribute(k_gemm_mma, cudaFuncAttributeMaxDynamicSharedMemorySize, SMEM_SZ);
    cudaFuncSetAttribute(k_gemm_pq,  cudaFuncAttributeMaxDynamicSharedMemorySize, SMEM_SZ);

    // degree
    k_deg_zero <<<(NN + 255) / 256, 256>>>();
    k_deg_count<<<(EE + 255) / 256, 256>>>(dst);

    // CSR build (scanC also computes dinv) + weight prep
    k_scanA<<<NB, 256>>>();
    k_scanB<<<1, 512>>>();
    k_scanC<<<NB, 256>>>();
    k_fill <<<(EE + 255) / 256, 256>>>(src, dst);
    k_prep_w<<<5, 256>>>(conv_w, mlp_w1);

    // encoder
    k_encoder<<<1184, 256>>>(nf, enc_w, enc_b, enc_ln_g, enc_ln_b);

    // 3 GCN layers
    for (int l = 0; l < 3; l++) {
        k_gemm_mma <<<GB, 256, SMEM_SZ>>>(px, l, ph, NN, pdinv);
        k_gather_ln<<<(NN + 7) / 8, 256>>>(conv_b + l * HH, ln_g + l * HH, ln_b + l * HH,
                                           (l == 2) ? out : nullptr);
    }

    // edge scoring: P/Q in one pass, then CSR-grouped edge MLP
    k_gemm_pq<<<GB, 256, SMEM_SZ>>>(px, pP, pQ, NN);
    k_edge_mlp_csr<<<(NN + 7) / 8, 256>>>(mlp_b1, mlp_w2, mlp_b2, out_logits);
}

// round 6
// speedup vs baseline: 2.3855x; 1.0323x over previous
#include <cuda_runtime.h>
#include <cuda_bf16.h>
#include <cstdint>

#define NN 100000
#define HH 128
#define EE 1600000
#define LN_EPS 1e-5f
#define NB 391          // (NN+255)/256
#define GB 782          // (NN+127)/128 gemm tiles

// ---------------- device scratch ----------------
__device__ float g_x  [NN * HH];
__device__ float g_h  [NN * HH];     // h_scaled = (x@W) * dinv[row]
__device__ float g_P  [NN * HH];
__device__ float g_Q  [NN * HH];
__device__ int   g_deg   [NN];
__device__ float g_dinv  [NN];
__device__ int   g_rowptr[NN];
__device__ int   g_cursor[NN];
__device__ int   g_csrc  [EE];
__device__ int   g_eid   [EE];
__device__ int   g_bsum  [NB];
__device__ int   g_boff  [NB];
__device__ __nv_bfloat16 g_Whi[5 * 16384];   // B = W^T, [n][k] row-major
__device__ __nv_bfloat16 g_Wlo[5 * 16384];

// ---------------- helpers ----------------
__device__ __forceinline__ uint32_t smem_u32(const void* p) {
    uint32_t a;
    asm("{ .reg .u64 t; cvta.to.shared.u64 t, %1; cvt.u32.u64 %0, t; }" : "=r"(a) : "l"(p));
    return a;
}
__device__ __forceinline__ void ldm4(uint32_t* r, uint32_t addr) {
    asm volatile("ldmatrix.sync.aligned.m8n8.x4.shared.b16 {%0,%1,%2,%3}, [%4];"
                 : "=r"(r[0]), "=r"(r[1]), "=r"(r[2]), "=r"(r[3]) : "r"(addr));
}
__device__ __forceinline__ void mma_bf16(float* d, const uint32_t* a, const uint32_t* b) {
    asm volatile("mma.sync.aligned.m16n8k16.row.col.f32.bf16.bf16.f32 "
                 "{%0,%1,%2,%3}, {%4,%5,%6,%7}, {%8,%9}, {%0,%1,%2,%3};"
                 : "+f"(d[0]), "+f"(d[1]), "+f"(d[2]), "+f"(d[3])
                 : "r"(a[0]), "r"(a[1]), "r"(a[2]), "r"(a[3]), "r"(b[0]), "r"(b[1]));
}

// ---------------- degree ----------------
__global__ void k_deg_zero() {
    int i = blockIdx.x * blockDim.x + threadIdx.x;
    if (i < NN) g_deg[i] = 0;
}
__global__ void k_deg_count(const int* __restrict__ dst) {
    int i = blockIdx.x * blockDim.x + threadIdx.x;
    if (i < EE) atomicAdd(&g_deg[dst[i]], 1);
}

// ---------------- CSR build ----------------
__global__ void k_scanA() {
    __shared__ int ws[8];
    int i = blockIdx.x * 256 + threadIdx.x;
    int v = (i < NN) ? g_deg[i] : 0;
#pragma unroll
    for (int off = 16; off > 0; off >>= 1) v += __shfl_xor_sync(0xffffffffu, v, off);
    if ((threadIdx.x & 31) == 0) ws[threadIdx.x >> 5] = v;
    __syncthreads();
    if (threadIdx.x == 0) {
        int t = 0;
#pragma unroll
        for (int w = 0; w < 8; w++) t += ws[w];
        g_bsum[blockIdx.x] = t;
    }
}
__global__ void k_scanB() {
    __shared__ int s[512];
    int tid = threadIdx.x;
    int v = (tid < NB) ? g_bsum[tid] : 0;
    s[tid] = v;
    __syncthreads();
    for (int off = 1; off < 512; off <<= 1) {
        int t = (tid >= off) ? s[tid - off] : 0;
        __syncthreads();
        s[tid] += t;
        __syncthreads();
    }
    if (tid < NB) g_boff[tid] = s[tid] - v;
}
__global__ void k_scanC() {   // also computes dinv
    __shared__ int s[256];
    int tid = threadIdx.x;
    int i = blockIdx.x * 256 + tid;
    int v = (i < NN) ? g_deg[i] : 0;
    s[tid] = v;
    __syncthreads();
    for (int off = 1; off < 256; off <<= 1) {
        int t = (tid >= off) ? s[tid - off] : 0;
        __syncthreads();
        s[tid] += t;
        __syncthreads();
    }
    if (i < NN) {
        int r = g_boff[blockIdx.x] + s[tid] - v;
        g_rowptr[i] = r;
        g_cursor[i] = r;
        g_dinv[i] = rsqrtf((float)(v + 1));
    }
}
__global__ void k_fill(const int* __restrict__ src, const int* __restrict__ dst) {
    int e = blockIdx.x * blockDim.x + threadIdx.x;
    if (e >= EE) return;
    int d = dst[e];
    int p = atomicAdd(&g_cursor[d], 1);
    g_csrc[p] = src[e];
    g_eid[p] = e;
}

// ---------------- weight prep: transpose + hi/lo split, [n][k] layout ----------------
__global__ void k_prep_w(const float* __restrict__ conv_w, const float* __restrict__ mlp_w1) {
    int mat = blockIdx.x;   // 0..2 conv, 3..4 mlp halves
    const float* W = (mat < 3) ? conv_w + mat * 16384 : mlp_w1 + (mat - 3) * 16384;
    for (int idx = threadIdx.x; idx < 16384; idx += blockDim.x) {
        int n = idx >> 7, k = idx & 127;
        float w = W[k * 128 + n];                   // B[n][k] = W[k][n]
        __nv_bfloat16 hi = __float2bfloat16(w);
        __nv_bfloat16 lo = __float2bfloat16(w - __bfloat162float(hi));
        g_Whi[mat * 16384 + idx] = hi;
        g_Wlo[mat * 16384 + idx] = lo;
    }
}

// ---------------- mma.sync GEMM: C[M,128] = A[M,128] @ W, split-bf16, fp32 acc ----------------
#define RS 272
#define SM_AHI 0
#define SM_ALO (128 * RS)
#define SM_BHI (2 * 128 * RS)
#define SM_BLO (3 * 128 * RS)
#define SMEM_SZ (4 * 128 * RS)

__device__ __forceinline__ void gemm_fill_A(char* smem, const float* __restrict__ A,
                                            int row0, int M, int wid, int lane) {
#pragma unroll
    for (int it = 0; it < 16; it++) {
        int r = it * 8 + wid;
        int kc = lane * 4;
        int grow = row0 + r;
        float4 v = make_float4(0.f, 0.f, 0.f, 0.f);
        if (grow < M) v = *(const float4*)&A[(size_t)grow * 128 + kc];
        __nv_bfloat16 h0 = __float2bfloat16(v.x), h1 = __float2bfloat16(v.y);
        __nv_bfloat16 h2 = __float2bfloat16(v.z), h3 = __float2bfloat16(v.w);
        __nv_bfloat16 l0 = __float2bfloat16(v.x - __bfloat162float(h0));
        __nv_bfloat16 l1 = __float2bfloat16(v.y - __bfloat162float(h1));
        __nv_bfloat16 l2 = __float2bfloat16(v.z - __bfloat162float(h2));
        __nv_bfloat16 l3 = __float2bfloat16(v.w - __bfloat162float(h3));
        __nv_bfloat162 hA = {h0, h1}, hB = {h2, h3}, lA = {l0, l1}, lB = {l2, l3};
        uint2 hp = {*(uint32_t*)&hA, *(uint32_t*)&hB};
        uint2 lp = {*(uint32_t*)&lA, *(uint32_t*)&lB};
        *(uint2*)(smem + SM_AHI + r * RS + lane * 8) = hp;
        *(uint2*)(smem + SM_ALO + r * RS + lane * 8) = lp;
    }
}

__device__ __forceinline__ void gemm_fill_B(char* smem, int mat, int tid) {
    const float4* bh = (const float4*)(g_Whi + mat * 16384);
    const float4* bl = (const float4*)(g_Wlo + mat * 16384);
#pragma unroll
    for (int i = tid; i < 2048; i += 256) {
        int n = i >> 4, seg = i & 15;
        *(float4*)(smem + SM_BHI + n * RS + seg * 16) = bh[i];
        *(float4*)(smem + SM_BLO + n * RS + seg * 16) = bl[i];
    }
}

__device__ __forceinline__ void gemm_core_epi(char* smem, uint32_t sb,
                                              float* __restrict__ C, int M,
                                              const float* __restrict__ rowscale,
                                              int row0, int wid, int lane) {
    int arow = (wid >> 1) * 32 + (lane & 7) + ((lane >> 3) & 1) * 8;
    uint32_t akb = ((lane >> 4) & 1) * 16;
    uint32_t aA0 = sb + SM_AHI + arow * RS + akb;
    uint32_t aA1 = aA0 + 16 * RS;
    int brow = (lane & 7) + ((lane >> 4) & 1) * 8;
    uint32_t bkb = ((lane >> 3) & 1) * 16;
    uint32_t bB0 = sb + SM_BHI + ((wid & 1) * 64 + brow) * RS + bkb;

    float acc[2][8][4];
#pragma unroll
    for (int m = 0; m < 2; m++)
#pragma unroll
        for (int n = 0; n < 8; n++)
#pragma unroll
            for (int j = 0; j < 4; j++) acc[m][n][j] = 0.f;

#pragma unroll
    for (int ks = 0; ks < 8; ks++) {
        uint32_t ko = ks * 32;
        uint32_t ahi[2][4], alo[2][4];
        ldm4(ahi[0], aA0 + ko);
        ldm4(ahi[1], aA1 + ko);
        ldm4(alo[0], aA0 + (SM_ALO - SM_AHI) + ko);
        ldm4(alo[1], aA1 + (SM_ALO - SM_AHI) + ko);
#pragma unroll
        for (int g = 0; g < 4; g++) {
            uint32_t bhi[4], blo[4];
            ldm4(bhi, bB0 + g * 16 * RS + ko);
            ldm4(blo, bB0 + g * 16 * RS + (SM_BLO - SM_BHI) + ko);
#pragma unroll
            for (int h = 0; h < 2; h++) {
                int n = g * 2 + h;
#pragma unroll
                for (int m = 0; m < 2; m++) {
                    mma_bf16(acc[m][n], ahi[m], &bhi[h * 2]);
                    mma_bf16(acc[m][n], ahi[m], &blo[h * 2]);
                    mma_bf16(acc[m][n], alo[m], &bhi[h * 2]);
                }
            }
        }
    }

    int rbase = row0 + (wid >> 1) * 32;
    int cbase = (wid & 1) * 64;
#pragma unroll
    for (int m = 0; m < 2; m++) {
        int r0r = rbase + m * 16 + (lane >> 2);
        int r1r = r0r + 8;
        float s0 = 1.f, s1 = 1.f;
        if (rowscale) {
            if (r0r < M) s0 = rowscale[r0r];
            if (r1r < M) s1 = rowscale[r1r];
        }
#pragma unroll
        for (int n = 0; n < 8; n++) {
            int col = cbase + n * 8 + (lane & 3) * 2;
            if (r0r < M) {
                float2 o = {acc[m][n][0] * s0, acc[m][n][1] * s0};
                *(float2*)&C[(size_t)r0r * 128 + col] = o;
            }
            if (r1r < M) {
                float2 o = {acc[m][n][2] * s1, acc[m][n][3] * s1};
                *(float2*)&C[(size_t)r1r * 128 + col] = o;
            }
        }
    }
}

__global__ void __launch_bounds__(256, 1)
k_gemm_mma(const float* __restrict__ A, int mat, float* __restrict__ C, int M,
           const float* __restrict__ rowscale) {
    extern __shared__ char smem[];
    uint32_t sb = smem_u32(smem);
    int tid = threadIdx.x, wid = tid >> 5, lane = tid & 31;
    int row0 = blockIdx.x * 128;
    gemm_fill_B(smem, mat, tid);
    gemm_fill_A(smem, A, row0, M, wid, lane);
    __syncthreads();
    gemm_core_epi(smem, sb, C, M, rowscale, row0, wid, lane);
}

// P and Q in one pass: A loaded once, B swapped between the two mats
__global__ void __launch_bounds__(256, 1)
k_gemm_pq(const float* __restrict__ A, float* __restrict__ P, float* __restrict__ Q, int M) {
    extern __shared__ char smem[];
    uint32_t sb = smem_u32(smem);
    int tid = threadIdx.x, wid = tid >> 5, lane = tid & 31;
    int row0 = blockIdx.x * 128;
    gemm_fill_A(smem, A, row0, M, wid, lane);
    gemm_fill_B(smem, 3, tid);
    __syncthreads();
    gemm_core_epi(smem, sb, P, M, nullptr, row0, wid, lane);
    __syncthreads();
    gemm_fill_B(smem, 4, tid);
    __syncthreads();
    gemm_core_epi(smem, sb, Q, M, nullptr, row0, wid, lane);
}

// ---------------- encoder: Linear(7->128) + LN + ReLU, warp loops over nodes ----------------
__global__ void k_encoder(const float* __restrict__ nf,
                          const float* __restrict__ w,  const float* __restrict__ b,
                          const float* __restrict__ lg, const float* __restrict__ lb) {
    int gw = blockIdx.x * 8 + (threadIdx.x >> 5);
    int nw = gridDim.x * 8;
    int lane = threadIdx.x & 31;

    float wr[7][4], br[4], lgr[4], lbr[4];
#pragma unroll
    for (int j = 0; j < 4; j++) {
        int c = lane + 32 * j;
        br[j] = b[c]; lgr[j] = lg[c]; lbr[j] = lb[c];
#pragma unroll
        for (int k = 0; k < 7; k++) wr[k][j] = w[k * HH + c];
    }

    for (int n = gw; n < NN; n += nw) {
        float f[7];
#pragma unroll
        for (int k = 0; k < 7; k++) f[k] = nf[n * 7 + k];

        float v[4];
#pragma unroll
        for (int j = 0; j < 4; j++) {
            float a = br[j];
#pragma unroll
            for (int k = 0; k < 7; k++) a = fmaf(f[k], wr[k][j], a);
            v[j] = a;
        }
        float s = 0.f, ss = 0.f;
#pragma unroll
        for (int j = 0; j < 4; j++) { s += v[j]; ss += v[j] * v[j]; }
#pragma unroll
        for (int off = 16; off > 0; off >>= 1) {
            s  += __shfl_xor_sync(0xffffffffu, s,  off);
            ss += __shfl_xor_sync(0xffffffffu, ss, off);
        }
        float mu  = s * (1.f / HH);
        float var = ss * (1.f / HH) - mu * mu;
        float inv = rsqrtf(var + LN_EPS);
#pragma unroll
        for (int j = 0; j < 4; j++) {
            int c = lane + 32 * j;
            float y = (v[j] - mu) * inv * lgr[j] + lbr[j];
            g_x[(size_t)n * HH + c] = fmaxf(y, 0.f);
        }
    }
}

// ---------------- fused layer: gather-agg + bias + LN + ReLU + residual ----------------
__global__ void __launch_bounds__(256, 8)
k_gather_ln(const float* __restrict__ cb,
            const float* __restrict__ lg, const float* __restrict__ lb,
            float* __restrict__ xout) {
    int n = blockIdx.x * 8 + (threadIdx.x >> 5);
    if (n >= NN) return;
    int lane = threadIdx.x & 31;

    int beg = g_rowptr[n];
    int cnt = g_deg[n];

    float4 acc = *(const float4*)&g_h[(size_t)n * 128 + lane * 4];

    for (int base = 0; base < cnt; base += 32) {
        int k = cnt - base;
        if (k > 32) k = 32;
        int sidx = (lane < k) ? g_csrc[beg + base + lane] : 0;
        int j = 0;
        for (; j + 4 <= k; j += 4) {
            int s0 = __shfl_sync(0xffffffffu, sidx, j + 0);
            int s1 = __shfl_sync(0xffffffffu, sidx, j + 1);
            int s2 = __shfl_sync(0xffffffffu, sidx, j + 2);
            int s3 = __shfl_sync(0xffffffffu, sidx, j + 3);
            float4 v0 = *(const float4*)&g_h[(size_t)s0 * 128 + lane * 4];
            float4 v1 = *(const float4*)&g_h[(size_t)s1 * 128 + lane * 4];
            float4 v2 = *(const float4*)&g_h[(size_t)s2 * 128 + lane * 4];
            float4 v3 = *(const float4*)&g_h[(size_t)s3 * 128 + lane * 4];
            v0.x += v1.x; v0.y += v1.y; v0.z += v1.z; v0.w += v1.w;
            v2.x += v3.x; v2.y += v3.y; v2.z += v3.z; v2.w += v3.w;
            acc.x += v0.x + v2.x;
            acc.y += v0.y + v2.y;
            acc.z += v0.z + v2.z;
            acc.w += v0.w + v2.w;
        }
        for (; j < k; j++) {
            int sj = __shfl_sync(0xffffffffu, sidx, j);
            float4 v = *(const float4*)&g_h[(size_t)sj * 128 + lane * 4];
            acc.x += v.x; acc.y += v.y; acc.z += v.z; acc.w += v.w;
        }
    }

    float di = g_dinv[n];
    float4 b4 = *(const float4*)&cb[lane * 4];
    float v[4] = {acc.x * di + b4.x, acc.y * di + b4.y,
                  acc.z * di + b4.z, acc.w * di + b4.w};

    float s = 0.f, ss = 0.f;
#pragma unroll
    for (int j = 0; j < 4; j++) { s += v[j]; ss += v[j] * v[j]; }
#pragma unroll
    for (int off = 16; off > 0; off >>= 1) {
        s  += __shfl_xor_sync(0xffffffffu, s,  off);
        ss += __shfl_xor_sync(0xffffffffu, ss, off);
    }
    float mu   = s * (1.f / HH);
    float var  = ss * (1.f / HH) - mu * mu;
    float linv = rsqrtf(var + LN_EPS);

    float4 lg4 = *(const float4*)&lg[lane * 4];
    float4 lb4 = *(const float4*)&lb[lane * 4];
    float4 xo  = *(const float4*)&g_x[(size_t)n * 128 + lane * 4];

    float4 y;
    y.x = fmaxf((v[0] - mu) * linv * lg4.x + lb4.x, 0.f) + xo.x;
    y.y = fmaxf((v[1] - mu) * linv * lg4.y + lb4.y, 0.f) + xo.y;
    y.z = fmaxf((v[2] - mu) * linv * lg4.z + lb4.z, 0.f) + xo.z;
    y.w = fmaxf((v[3] - mu) * linv * lg4.w + lb4.w, 0.f) + xo.w;

    *(float4*)&g_x[(size_t)n * 128 + lane * 4] = y;
    if (xout) *(float4*)&xout[(size_t)n * 128 + lane * 4] = y;
}

// ---------------- edge MLP, CSR-grouped by dst ----------------
__global__ void __launch_bounds__(256, 8)
k_edge_mlp_csr(const float* __restrict__ b1, const float* __restrict__ w2,
               const float* __restrict__ b2, float* __restrict__ out) {
    int n = blockIdx.x * 8 + (threadIdx.x >> 5);
    if (n >= NN) return;
    int lane = threadIdx.x & 31;

    int beg = g_rowptr[n];
    int cnt = g_deg[n];
    if (cnt == 0) return;

    float4 qb = *(const float4*)&g_Q[(size_t)n * 128 + lane * 4];
    float4 bb = *(const float4*)&b1[lane * 4];
    qb.x += bb.x; qb.y += bb.y; qb.z += bb.z; qb.w += bb.w;
    float4 w = *(const float4*)&w2[lane * 4];
    float bias2 = b2[0];

    for (int base = 0; base < cnt; base += 32) {
        int k = cnt - base;
        if (k > 32) k = 32;
        int sidx = 0, eidx = 0;
        if (lane < k) {
            sidx = g_csrc[beg + base + lane];
            eidx = g_eid [beg + base + lane];
        }
        float myval = 0.f;
        for (int j = 0; j < k; j++) {
            int sj = __shfl_sync(0xffffffffu, sidx, j);
            float4 p = *(const float4*)&g_P[(size_t)sj * 128 + lane * 4];
            float h0 = fmaxf(p.x + qb.x, 0.f);
            float h1 = fmaxf(p.y + qb.y, 0.f);
            float h2 = fmaxf(p.z + qb.z, 0.f);
            float h3 = fmaxf(p.w + qb.w, 0.f);
            float part = fmaf(h0, w.x, fmaf(h1, w.y, fmaf(h2, w.z, h3 * w.w)));
#pragma unroll
            for (int off = 16; off > 0; off >>= 1)
                part += __shfl_xor_sync(0xffffffffu, part, off);
            if (lane == j) myval = part;
        }
        if (lane < k) out[eidx] = myval + bias2;
    }
}

// ---------------- host ----------------
extern "C" void kernel_launch(void* const* d_in, const int* in_sizes, int n_in,
                              void* d_out, int out_size) {
    const float* nf       = (const float*)d_in[0];
    const int*   ei       = (const int*)  d_in[1];
    const float* enc_w    = (const float*)d_in[3];
    const float* enc_b    = (const float*)d_in[4];
    const float* enc_ln_g = (const float*)d_in[5];
    const float* enc_ln_b = (const float*)d_in[6];
    const float* conv_w   = (const float*)d_in[7];
    const float* conv_b   = (const float*)d_in[8];
    const float* ln_g     = (const float*)d_in[9];
    const float* ln_b     = (const float*)d_in[10];
    const float* mlp_w1   = (const float*)d_in[11];
    const float* mlp_b1   = (const float*)d_in[12];
    const float* mlp_w2   = (const float*)d_in[13];
    const float* mlp_b2   = (const float*)d_in[14];

    const int* src = ei;
    const int* dst = ei + EE;

    float* out        = (float*)d_out;
    float* out_logits = out + (size_t)NN * HH;

    float *px, *ph, *pP, *pQ, *pdinv;
    cudaGetSymbolAddress((void**)&px, g_x);
    cudaGetSymbolAddress((void**)&ph, g_h);
    cudaGetSymbolAddress((void**)&pP, g_P);
    cudaGetSymbolAddress((void**)&pQ, g_Q);
    cudaGetSymbolAddress((void**)&pdinv, g_dinv);

    cudaFuncSetAttribute(k_gemm_mma, cudaFuncAttributeMaxDynamicSharedMemorySize, SMEM_SZ);
    cudaFuncSetAttribute(k_gemm_pq,  cudaFuncAttributeMaxDynamicSharedMemorySize, SMEM_SZ);

    // side stream + events (created once; host-side only, no device allocation)
    static cudaStream_t s1 = nullptr;
    static cudaEvent_t ev_fork0 = nullptr, ev_enc = nullptr, ev_fork1 = nullptr, ev_fill = nullptr;
    if (!s1) {
        cudaStreamCreateWithFlags(&s1, cudaStreamNonBlocking);
        cudaEventCreateWithFlags(&ev_fork0, cudaEventDisableTiming);
        cudaEventCreateWithFlags(&ev_enc,   cudaEventDisableTiming);
        cudaEventCreateWithFlags(&ev_fork1, cudaEventDisableTiming);
        cudaEventCreateWithFlags(&ev_fill,  cudaEventDisableTiming);
    }

    // ---- fork: encoder + weight prep on s1 (depend only on inputs) ----
    cudaEventRecord(ev_fork0, 0);
    cudaStreamWaitEvent(s1, ev_fork0, 0);
    k_encoder<<<1184, 256, 0, s1>>>(nf, enc_w, enc_b, enc_ln_g, enc_ln_b);
    k_prep_w <<<5, 256, 0, s1>>>(conv_w, mlp_w1);
    cudaEventRecord(ev_enc, s1);

    // ---- main: degree + scan chain (produces rowptr/cursor/dinv) ----
    k_deg_zero <<<(NN + 255) / 256, 256>>>();
    k_deg_count<<<(EE + 255) / 256, 256>>>(dst);
    k_scanA<<<NB, 256>>>();
    k_scanB<<<1, 512>>>();
    k_scanC<<<NB, 256>>>();

    // ---- fork: fill (needs scanC only) runs under gemm l0 ----
    cudaEventRecord(ev_fork1, 0);
    cudaStreamWaitEvent(s1, ev_fork1, 0);
    k_fill<<<(EE + 255) / 256, 256, 0, s1>>>(src, dst);
    cudaEventRecord(ev_fill, s1);

    // ---- main: wait for encoder/prep, then layer pipeline ----
    cudaStreamWaitEvent(0, ev_enc, 0);
    for (int l = 0; l < 3; l++) {
        k_gemm_mma<<<GB, 256, SMEM_SZ>>>(px, l, ph, NN, pdinv);
        if (l == 0) cudaStreamWaitEvent(0, ev_fill, 0);   // CSR ready before first gather
        k_gather_ln<<<(NN + 7) / 8, 256>>>(conv_b + l * HH, ln_g + l * HH, ln_b + l * HH,
                                           (l == 2) ? out : nullptr);
    }

    // edge scoring: P/Q in one pass, then CSR-grouped edge MLP
    k_gemm_pq<<<GB, 256, SMEM_SZ>>>(px, pP, pQ, NN);
    k_edge_mlp_csr<<<(NN + 7) / 8, 256>>>(mlp_b1, mlp_w2, mlp_b2, out_logits);
}

// round 7
// speedup vs baseline: 2.3934x; 1.0033x over previous
#include <cuda_runtime.h>
#include <cuda_bf16.h>
#include <cstdint>

#define NN 100000
#define HH 128
#define EE 1600000
#define LN_EPS 1e-5f
#define NB 391           // (NN+255)/256
#define GB64 1563        // (NN+63)/64 gemm tiles

// ---------------- device scratch ----------------
__device__ float g_x  [NN * HH];
__device__ float g_h  [NN * HH];     // h_scaled = (x@W) * dinv[row]
__device__ float g_P  [NN * HH];
__device__ float g_Q  [NN * HH];
__device__ int   g_deg   [NN];
__device__ float g_dinv  [NN];
__device__ int   g_rowptr[NN];
__device__ int   g_cursor[NN];
__device__ int   g_csrc  [EE];
__device__ int   g_eid   [EE];
__device__ int   g_bsum  [NB];
__device__ int   g_boff  [NB];
__device__ __nv_bfloat16 g_Whi[5 * 16384];   // B = W^T, [n][k] row-major
__device__ __nv_bfloat16 g_Wlo[5 * 16384];

// ---------------- helpers ----------------
__device__ __forceinline__ uint32_t smem_u32(const void* p) {
    uint32_t a;
    asm("{ .reg .u64 t; cvta.to.shared.u64 t, %1; cvt.u32.u64 %0, t; }" : "=r"(a) : "l"(p));
    return a;
}
__device__ __forceinline__ void ldm4(uint32_t* r, uint32_t addr) {
    asm volatile("ldmatrix.sync.aligned.m8n8.x4.shared.b16 {%0,%1,%2,%3}, [%4];"
                 : "=r"(r[0]), "=r"(r[1]), "=r"(r[2]), "=r"(r[3]) : "r"(addr));
}
__device__ __forceinline__ void mma_bf16(float* d, const uint32_t* a, const uint32_t* b) {
    asm volatile("mma.sync.aligned.m16n8k16.row.col.f32.bf16.bf16.f32 "
                 "{%0,%1,%2,%3}, {%4,%5,%6,%7}, {%8,%9}, {%0,%1,%2,%3};"
                 : "+f"(d[0]), "+f"(d[1]), "+f"(d[2]), "+f"(d[3])
                 : "r"(a[0]), "r"(a[1]), "r"(a[2]), "r"(a[3]), "r"(b[0]), "r"(b[1]));
}

// ---------------- degree ----------------
__global__ void k_deg_zero() {
    int i = blockIdx.x * blockDim.x + threadIdx.x;
    if (i < NN) g_deg[i] = 0;
}
__global__ void k_deg_count(const int* __restrict__ dst) {
    int i = blockIdx.x * blockDim.x + threadIdx.x;
    if (i < EE) atomicAdd(&g_deg[dst[i]], 1);
}

// ---------------- CSR build ----------------
__global__ void k_scanA() {
    __shared__ int ws[8];
    int i = blockIdx.x * 256 + threadIdx.x;
    int v = (i < NN) ? g_deg[i] : 0;
#pragma unroll
    for (int off = 16; off > 0; off >>= 1) v += __shfl_xor_sync(0xffffffffu, v, off);
    if ((threadIdx.x & 31) == 0) ws[threadIdx.x >> 5] = v;
    __syncthreads();
    if (threadIdx.x == 0) {
        int t = 0;
#pragma unroll
        for (int w = 0; w < 8; w++) t += ws[w];
        g_bsum[blockIdx.x] = t;
    }
}
__global__ void k_scanB() {
    __shared__ int s[512];
    int tid = threadIdx.x;
    int v = (tid < NB) ? g_bsum[tid] : 0;
    s[tid] = v;
    __syncthreads();
    for (int off = 1; off < 512; off <<= 1) {
        int t = (tid >= off) ? s[tid - off] : 0;
        __syncthreads();
        s[tid] += t;
        __syncthreads();
    }
    if (tid < NB) g_boff[tid] = s[tid] - v;
}
__global__ void k_scanC() {   // also computes dinv
    __shared__ int s[256];
    int tid = threadIdx.x;
    int i = blockIdx.x * 256 + tid;
    int v = (i < NN) ? g_deg[i] : 0;
    s[tid] = v;
    __syncthreads();
    for (int off = 1; off < 256; off <<= 1) {
        int t = (tid >= off) ? s[tid - off] : 0;
        __syncthreads();
        s[tid] += t;
        __syncthreads();
    }
    if (i < NN) {
        int r = g_boff[blockIdx.x] + s[tid] - v;
        g_rowptr[i] = r;
        g_cursor[i] = r;
        g_dinv[i] = rsqrtf((float)(v + 1));
    }
}
__global__ void k_fill(const int* __restrict__ src, const int* __restrict__ dst) {
    int e = blockIdx.x * blockDim.x + threadIdx.x;
    if (e >= EE) return;
    int d = dst[e];
    int p = atomicAdd(&g_cursor[d], 1);
    g_csrc[p] = src[e];
    g_eid[p] = e;
}

// ---------------- weight prep: transpose + hi/lo split, [n][k] layout ----------------
__global__ void k_prep_w(const float* __restrict__ conv_w, const float* __restrict__ mlp_w1) {
    int mat = blockIdx.x;   // 0..2 conv, 3..4 mlp halves
    const float* W = (mat < 3) ? conv_w + mat * 16384 : mlp_w1 + (mat - 3) * 16384;
    for (int idx = threadIdx.x; idx < 16384; idx += blockDim.x) {
        int n = idx >> 7, k = idx & 127;
        float w = W[k * 128 + n];                   // B[n][k] = W[k][n]
        __nv_bfloat16 hi = __float2bfloat16(w);
        __nv_bfloat16 lo = __float2bfloat16(w - __bfloat162float(hi));
        g_Whi[mat * 16384 + idx] = hi;
        g_Wlo[mat * 16384 + idx] = lo;
    }
}

// ---------------- mma.sync GEMM: 64-row tiles, 2 CTA/SM ----------------
#define RS 272
#define SM_AHI 0
#define SM_ALO (64 * RS)
#define SM_BHI (2 * 64 * RS)
#define SM_BLO (2 * 64 * RS + 128 * RS)
#define SMEM_SZ (2 * 64 * RS + 2 * 128 * RS)   // 104448 B

__device__ __forceinline__ void gemm_fill_A(char* smem, const float* __restrict__ A,
                                            int row0, int M, int wid, int lane) {
#pragma unroll
    for (int it = 0; it < 8; it++) {
        int r = it * 8 + wid;
        int kc = lane * 4;
        int grow = row0 + r;
        float4 v = make_float4(0.f, 0.f, 0.f, 0.f);
        if (grow < M) v = *(const float4*)&A[(size_t)grow * 128 + kc];
        __nv_bfloat16 h0 = __float2bfloat16(v.x), h1 = __float2bfloat16(v.y);
        __nv_bfloat16 h2 = __float2bfloat16(v.z), h3 = __float2bfloat16(v.w);
        __nv_bfloat16 l0 = __float2bfloat16(v.x - __bfloat162float(h0));
        __nv_bfloat16 l1 = __float2bfloat16(v.y - __bfloat162float(h1));
        __nv_bfloat16 l2 = __float2bfloat16(v.z - __bfloat162float(h2));
        __nv_bfloat16 l3 = __float2bfloat16(v.w - __bfloat162float(h3));
        __nv_bfloat162 hA = {h0, h1}, hB = {h2, h3}, lA = {l0, l1}, lB = {l2, l3};
        uint2 hp = {*(uint32_t*)&hA, *(uint32_t*)&hB};
        uint2 lp = {*(uint32_t*)&lA, *(uint32_t*)&lB};
        *(uint2*)(smem + SM_AHI + r * RS + lane * 8) = hp;
        *(uint2*)(smem + SM_ALO + r * RS + lane * 8) = lp;
    }
}

__device__ __forceinline__ void gemm_fill_B(char* smem, int mat, int tid) {
    const float4* bh = (const float4*)(g_Whi + mat * 16384);
    const float4* bl = (const float4*)(g_Wlo + mat * 16384);
#pragma unroll
    for (int i = tid; i < 2048; i += 256) {
        int n = i >> 4, seg = i & 15;
        *(float4*)(smem + SM_BHI + n * RS + seg * 16) = bh[i];
        *(float4*)(smem + SM_BLO + n * RS + seg * 16) = bl[i];
    }
}

__device__ __forceinline__ void gemm_core_epi(char* smem, uint32_t sb,
                                              float* __restrict__ C, int M,
                                              const float* __restrict__ rowscale,
                                              int row0, int wid, int lane) {
    // warp = 16 rows x 64 cols
    int arow = (wid >> 1) * 16 + (lane & 7) + ((lane >> 3) & 1) * 8;
    uint32_t akb = ((lane >> 4) & 1) * 16;
    uint32_t aA0 = sb + SM_AHI + arow * RS + akb;
    int brow = (lane & 7) + ((lane >> 4) & 1) * 8;
    uint32_t bkb = ((lane >> 3) & 1) * 16;
    uint32_t bB0 = sb + SM_BHI + ((wid & 1) * 64 + brow) * RS + bkb;

    float acc[8][4];
#pragma unroll
    for (int n = 0; n < 8; n++)
#pragma unroll
        for (int j = 0; j < 4; j++) acc[n][j] = 0.f;

#pragma unroll
    for (int ks = 0; ks < 8; ks++) {
        uint32_t ko = ks * 32;
        uint32_t ahi[4], alo[4];
        ldm4(ahi, aA0 + ko);
        ldm4(alo, aA0 + (SM_ALO - SM_AHI) + ko);
#pragma unroll
        for (int g = 0; g < 4; g++) {
            uint32_t bhi[4], blo[4];
            ldm4(bhi, bB0 + g * 16 * RS + ko);
            ldm4(blo, bB0 + g * 16 * RS + (SM_BLO - SM_BHI) + ko);
#pragma unroll
            for (int h = 0; h < 2; h++) {
                int n = g * 2 + h;
                mma_bf16(acc[n], ahi, &bhi[h * 2]);
                mma_bf16(acc[n], ahi, &blo[h * 2]);
                mma_bf16(acc[n], alo, &bhi[h * 2]);
            }
        }
    }

    int r0r = row0 + (wid >> 1) * 16 + (lane >> 2);
    int r1r = r0r + 8;
    int cbase = (wid & 1) * 64;
    float s0 = 1.f, s1 = 1.f;
    if (rowscale) {
        if (r0r < M) s0 = rowscale[r0r];
        if (r1r < M) s1 = rowscale[r1r];
    }
#pragma unroll
    for (int n = 0; n < 8; n++) {
        int col = cbase + n * 8 + (lane & 3) * 2;
        if (r0r < M) {
            float2 o = {acc[n][0] * s0, acc[n][1] * s0};
            *(float2*)&C[(size_t)r0r * 128 + col] = o;
        }
        if (r1r < M) {
            float2 o = {acc[n][2] * s1, acc[n][3] * s1};
            *(float2*)&C[(size_t)r1r * 128 + col] = o;
        }
    }
}

__global__ void __launch_bounds__(256, 2)
k_gemm_mma(const float* __restrict__ A, int mat, float* __restrict__ C, int M,
           const float* __restrict__ rowscale) {
    extern __shared__ char smem[];
    uint32_t sb = smem_u32(smem);
    int tid = threadIdx.x, wid = tid >> 5, lane = tid & 31;
    int row0 = blockIdx.x * 64;
    gemm_fill_B(smem, mat, tid);
    gemm_fill_A(smem, A, row0, M, wid, lane);
    __syncthreads();
    gemm_core_epi(smem, sb, C, M, rowscale, row0, wid, lane);
}

// P and Q in one pass: A loaded once, B swapped between the two mats
__global__ void __launch_bounds__(256, 2)
k_gemm_pq(const float* __restrict__ A, float* __restrict__ P, float* __restrict__ Q, int M) {
    extern __shared__ char smem[];
    uint32_t sb = smem_u32(smem);
    int tid = threadIdx.x, wid = tid >> 5, lane = tid & 31;
    int row0 = blockIdx.x * 64;
    gemm_fill_A(smem, A, row0, M, wid, lane);
    gemm_fill_B(smem, 3, tid);
    __syncthreads();
    gemm_core_epi(smem, sb, P, M, nullptr, row0, wid, lane);
    __syncthreads();
    gemm_fill_B(smem, 4, tid);
    __syncthreads();
    gemm_core_epi(smem, sb, Q, M, nullptr, row0, wid, lane);
}

// ---------------- encoder: Linear(7->128) + LN + ReLU, warp loops over nodes ----------------
__global__ void k_encoder(const float* __restrict__ nf,
                          const float* __restrict__ w,  const float* __restrict__ b,
                          const float* __restrict__ lg, const float* __restrict__ lb) {
    int gw = blockIdx.x * 8 + (threadIdx.x >> 5);
    int nw = gridDim.x * 8;
    int lane = threadIdx.x & 31;

    float wr[7][4], br[4], lgr[4], lbr[4];
#pragma unroll
    for (int j = 0; j < 4; j++) {
        int c = lane + 32 * j;
        br[j] = b[c]; lgr[j] = lg[c]; lbr[j] = lb[c];
#pragma unroll
        for (int k = 0; k < 7; k++) wr[k][j] = w[k * HH + c];
    }

    for (int n = gw; n < NN; n += nw) {
        float f[7];
#pragma unroll
        for (int k = 0; k < 7; k++) f[k] = nf[n * 7 + k];

        float v[4];
#pragma unroll
        for (int j = 0; j < 4; j++) {
            float a = br[j];
#pragma unroll
            for (int k = 0; k < 7; k++) a = fmaf(f[k], wr[k][j], a);
            v[j] = a;
        }
        float s = 0.f, ss = 0.f;
#pragma unroll
        for (int j = 0; j < 4; j++) { s += v[j]; ss += v[j] * v[j]; }
#pragma unroll
        for (int off = 16; off > 0; off >>= 1) {
            s  += __shfl_xor_sync(0xffffffffu, s,  off);
            ss += __shfl_xor_sync(0xffffffffu, ss, off);
        }
        float mu  = s * (1.f / HH);
        float var = ss * (1.f / HH) - mu * mu;
        float inv = rsqrtf(var + LN_EPS);
#pragma unroll
        for (int j = 0; j < 4; j++) {
            int c = lane + 32 * j;
            float y = (v[j] - mu) * inv * lgr[j] + lbr[j];
            g_x[(size_t)n * HH + c] = fmaxf(y, 0.f);
        }
    }
}

// ---------------- fused layer: gather-agg + bias + LN + ReLU + residual ----------------
__global__ void __launch_bounds__(256, 8)
k_gather_ln(const float* __restrict__ cb,
            const float* __restrict__ lg, const float* __restrict__ lb,
            float* __restrict__ xout) {
    int n = blockIdx.x * 8 + (threadIdx.x >> 5);
    if (n >= NN) return;
    int lane = threadIdx.x & 31;

    int beg = g_rowptr[n];
    int cnt = g_deg[n];

    float4 acc = *(const float4*)&g_h[(size_t)n * 128 + lane * 4];

    for (int base = 0; base < cnt; base += 32) {
        int k = cnt - base;
        if (k > 32) k = 32;
        int sidx = (lane < k) ? g_csrc[beg + base + lane] : 0;
        int j = 0;
        for (; j + 4 <= k; j += 4) {
            int s0 = __shfl_sync(0xffffffffu, sidx, j + 0);
            int s1 = __shfl_sync(0xffffffffu, sidx, j + 1);
            int s2 = __shfl_sync(0xffffffffu, sidx, j + 2);
            int s3 = __shfl_sync(0xffffffffu, sidx, j + 3);
            float4 v0 = *(const float4*)&g_h[(size_t)s0 * 128 + lane * 4];
            float4 v1 = *(const float4*)&g_h[(size_t)s1 * 128 + lane * 4];
            float4 v2 = *(const float4*)&g_h[(size_t)s2 * 128 + lane * 4];
            float4 v3 = *(const float4*)&g_h[(size_t)s3 * 128 + lane * 4];
            v0.x += v1.x; v0.y += v1.y; v0.z += v1.z; v0.w += v1.w;
            v2.x += v3.x; v2.y += v3.y; v2.z += v3.z; v2.w += v3.w;
            acc.x += v0.x + v2.x;
            acc.y += v0.y + v2.y;
            acc.z += v0.z + v2.z;
            acc.w += v0.w + v2.w;
        }
        for (; j < k; j++) {
            int sj = __shfl_sync(0xffffffffu, sidx, j);
            float4 v = *(const float4*)&g_h[(size_t)sj * 128 + lane * 4];
            acc.x += v.x; acc.y += v.y; acc.z += v.z; acc.w += v.w;
        }
    }

    float di = g_dinv[n];
    float4 b4 = *(const float4*)&cb[lane * 4];
    float v[4] = {acc.x * di + b4.x, acc.y * di + b4.y,
                  acc.z * di + b4.z, acc.w * di + b4.w};

    float s = 0.f, ss = 0.f;
#pragma unroll
    for (int j = 0; j < 4; j++) { s += v[j]; ss += v[j] * v[j]; }
#pragma unroll
    for (int off = 16; off > 0; off >>= 1) {
        s  += __shfl_xor_sync(0xffffffffu, s,  off);
        ss += __shfl_xor_sync(0xffffffffu, ss, off);
    }
    float mu   = s * (1.f / HH);
    float var  = ss * (1.f / HH) - mu * mu;
    float linv = rsqrtf(var + LN_EPS);

    float4 lg4 = *(const float4*)&lg[lane * 4];
    float4 lb4 = *(const float4*)&lb[lane * 4];
    float4 xo  = *(const float4*)&g_x[(size_t)n * 128 + lane * 4];

    float4 y;
    y.x = fmaxf((v[0] - mu) * linv * lg4.x + lb4.x, 0.f) + xo.x;
    y.y = fmaxf((v[1] - mu) * linv * lg4.y + lb4.y, 0.f) + xo.y;
    y.z = fmaxf((v[2] - mu) * linv * lg4.z + lb4.z, 0.f) + xo.z;
    y.w = fmaxf((v[3] - mu) * linv * lg4.w + lb4.w, 0.f) + xo.w;

    *(float4*)&g_x[(size_t)n * 128 + lane * 4] = y;
    if (xout) *(float4*)&xout[(size_t)n * 128 + lane * 4] = y;
}

// ---------------- edge MLP, CSR-grouped by dst ----------------
__global__ void __launch_bounds__(256, 8)
k_edge_mlp_csr(const float* __restrict__ b1, const float* __restrict__ w2,
               const float* __restrict__ b2, float* __restrict__ out) {
    int n = blockIdx.x * 8 + (threadIdx.x >> 5);
    if (n >= NN) return;
    int lane = threadIdx.x & 31;

    int beg = g_rowptr[n];
    int cnt = g_deg[n];
    if (cnt == 0) return;

    float4 qb = *(const float4*)&g_Q[(size_t)n * 128 + lane * 4];
    float4 bb = *(const float4*)&b1[lane * 4];
    qb.x += bb.x; qb.y += bb.y; qb.z += bb.z; qb.w += bb.w;
    float4 w = *(const float4*)&w2[lane * 4];
    float bias2 = b2[0];

    for (int base = 0; base < cnt; base += 32) {
        int k = cnt - base;
        if (k > 32) k = 32;
        int sidx = 0, eidx = 0;
        if (lane < k) {
            sidx = g_csrc[beg + base + lane];
            eidx = g_eid [beg + base + lane];
        }
        float myval = 0.f;
        for (int j = 0; j < k; j++) {
            int sj = __shfl_sync(0xffffffffu, sidx, j);
            float4 p = *(const float4*)&g_P[(size_t)sj * 128 + lane * 4];
            float h0 = fmaxf(p.x + qb.x, 0.f);
            float h1 = fmaxf(p.y + qb.y, 0.f);
            float h2 = fmaxf(p.z + qb.z, 0.f);
            float h3 = fmaxf(p.w + qb.w, 0.f);
            float part = fmaf(h0, w.x, fmaf(h1, w.y, fmaf(h2, w.z, h3 * w.w)));
#pragma unroll
            for (int off = 16; off > 0; off >>= 1)
                part += __shfl_xor_sync(0xffffffffu, part, off);
            if (lane == j) myval = part;
        }
        if (lane < k) out[eidx] = myval + bias2;
    }
}

// ---------------- host ----------------
extern "C" void kernel_launch(void* const* d_in, const int* in_sizes, int n_in,
                              void* d_out, int out_size) {
    const float* nf       = (const float*)d_in[0];
    const int*   ei       = (const int*)  d_in[1];
    const float* enc_w    = (const float*)d_in[3];
    const float* enc_b    = (const float*)d_in[4];
    const float* enc_ln_g = (const float*)d_in[5];
    const float* enc_ln_b = (const float*)d_in[6];
    const float* conv_w   = (const float*)d_in[7];
    const float* conv_b   = (const float*)d_in[8];
    const float* ln_g     = (const float*)d_in[9];
    const float* ln_b     = (const float*)d_in[10];
    const float* mlp_w1   = (const float*)d_in[11];
    const float* mlp_b1   = (const float*)d_in[12];
    const float* mlp_w2   = (const float*)d_in[13];
    const float* mlp_b2   = (const float*)d_in[14];

    const int* src = ei;
    const int* dst = ei + EE;

    float* out        = (float*)d_out;
    float* out_logits = out + (size_t)NN * HH;

    float *px, *ph, *pP, *pQ, *pdinv;
    cudaGetSymbolAddress((void**)&px, g_x);
    cudaGetSymbolAddress((void**)&ph, g_h);
    cudaGetSymbolAddress((void**)&pP, g_P);
    cudaGetSymbolAddress((void**)&pQ, g_Q);
    cudaGetSymbolAddress((void**)&pdinv, g_dinv);

    cudaFuncSetAttribute(k_gemm_mma, cudaFuncAttributeMaxDynamicSharedMemorySize, SMEM_SZ);
    cudaFuncSetAttribute(k_gemm_pq,  cudaFuncAttributeMaxDynamicSharedMemorySize, SMEM_SZ);

    // side stream + events (created once; host-side only)
    static cudaStream_t s1 = nullptr;
    static cudaEvent_t ev_fork0 = nullptr, ev_enc = nullptr, ev_fork1 = nullptr, ev_fill = nullptr;
    if (!s1) {
        cudaStreamCreateWithFlags(&s1, cudaStreamNonBlocking);
        cudaEventCreateWithFlags(&ev_fork0, cudaEventDisableTiming);
        cudaEventCreateWithFlags(&ev_enc,   cudaEventDisableTiming);
        cudaEventCreateWithFlags(&ev_fork1, cudaEventDisableTiming);
        cudaEventCreateWithFlags(&ev_fill,  cudaEventDisableTiming);
    }

    // ---- fork: encoder + weight prep on s1 ----
    cudaEventRecord(ev_fork0, 0);
    cudaStreamWaitEvent(s1, ev_fork0, 0);
    k_encoder<<<1184, 256, 0, s1>>>(nf, enc_w, enc_b, enc_ln_g, enc_ln_b);
    k_prep_w <<<5, 256, 0, s1>>>(conv_w, mlp_w1);
    cudaEventRecord(ev_enc, s1);

    // ---- main: degree + scan chain ----
    k_deg_zero <<<(NN + 255) / 256, 256>>>();
    k_deg_count<<<(EE + 255) / 256, 256>>>(dst);
    k_scanA<<<NB, 256>>>();
    k_scanB<<<1, 512>>>();
    k_scanC<<<NB, 256>>>();

    // ---- fork: fill runs under gemm l0 ----
    cudaEventRecord(ev_fork1, 0);
    cudaStreamWaitEvent(s1, ev_fork1, 0);
    k_fill<<<(EE + 255) / 256, 256, 0, s1>>>(src, dst);
    cudaEventRecord(ev_fill, s1);

    // ---- main: layer pipeline ----
    cudaStreamWaitEvent(0, ev_enc, 0);
    for (int l = 0; l < 3; l++) {
        k_gemm_mma<<<GB64, 256, SMEM_SZ>>>(px, l, ph, NN, pdinv);
        if (l == 0) cudaStreamWaitEvent(0, ev_fill, 0);
        k_gather_ln<<<(NN + 7) / 8, 256>>>(conv_b + l * HH, ln_g + l * HH, ln_b + l * HH,
                                           (l == 2) ? out : nullptr);
    }

    // edge scoring
    k_gemm_pq<<<GB64, 256, SMEM_SZ>>>(px, pP, pQ, NN);
    k_edge_mlp_csr<<<(NN + 7) / 8, 256>>>(mlp_b1, mlp_w2, mlp_b2, out_logits);
}

// round 8
// speedup vs baseline: 2.5432x; 1.0626x over previous
#include <cuda_runtime.h>
#include <cuda_bf16.h>
#include <cuda_fp16.h>
#include <cstdint>

#define NN 100000
#define HH 128
#define EE 1600000
#define LN_EPS 1e-5f
#define NB 391           // (NN+255)/256
#define GB64 1563        // (NN+63)/64 gemm tiles

// ---------------- device scratch ----------------
__device__ float  g_x  [NN * HH];
__device__ __half g_h16[NN * HH];    // h_scaled = (x@W)*dinv, fp16 storage
__device__ __half g_P16[NN * HH];    // P = x@W1[:128], fp16 storage
__device__ float  g_Q  [NN * HH];    // Q = x@W1[128:], fp32 (read once per node)
__device__ int   g_deg   [NN];
__device__ float g_dinv  [NN];
__device__ int   g_rowptr[NN];
__device__ int   g_cursor[NN];
__device__ int   g_csrc  [EE];
__device__ int   g_eid   [EE];
__device__ int   g_bsum  [NB];
__device__ int   g_boff  [NB];
__device__ __nv_bfloat16 g_Whi[5 * 16384];   // B = W^T, [n][k] row-major
__device__ __nv_bfloat16 g_Wlo[5 * 16384];

// ---------------- helpers ----------------
__device__ __forceinline__ uint32_t smem_u32(const void* p) {
    uint32_t a;
    asm("{ .reg .u64 t; cvta.to.shared.u64 t, %1; cvt.u32.u64 %0, t; }" : "=r"(a) : "l"(p));
    return a;
}
__device__ __forceinline__ void ldm4(uint32_t* r, uint32_t addr) {
    asm volatile("ldmatrix.sync.aligned.m8n8.x4.shared.b16 {%0,%1,%2,%3}, [%4];"
                 : "=r"(r[0]), "=r"(r[1]), "=r"(r[2]), "=r"(r[3]) : "r"(addr));
}
__device__ __forceinline__ void mma_bf16(float* d, const uint32_t* a, const uint32_t* b) {
    asm volatile("mma.sync.aligned.m16n8k16.row.col.f32.bf16.bf16.f32 "
                 "{%0,%1,%2,%3}, {%4,%5,%6,%7}, {%8,%9}, {%0,%1,%2,%3};"
                 : "+f"(d[0]), "+f"(d[1]), "+f"(d[2]), "+f"(d[3])
                 : "r"(a[0]), "r"(a[1]), "r"(a[2]), "r"(a[3]), "r"(b[0]), "r"(b[1]));
}

// ---------------- degree ----------------
__global__ void k_deg_zero() {
    int i = blockIdx.x * blockDim.x + threadIdx.x;
    if (i < NN) g_deg[i] = 0;
}
__global__ void k_deg_count(const int* __restrict__ dst) {
    int i = blockIdx.x * blockDim.x + threadIdx.x;
    if (i < EE) atomicAdd(&g_deg[dst[i]], 1);
}

// ---------------- CSR build ----------------
__global__ void k_scanA() {
    __shared__ int ws[8];
    int i = blockIdx.x * 256 + threadIdx.x;
    int v = (i < NN) ? g_deg[i] : 0;
#pragma unroll
    for (int off = 16; off > 0; off >>= 1) v += __shfl_xor_sync(0xffffffffu, v, off);
    if ((threadIdx.x & 31) == 0) ws[threadIdx.x >> 5] = v;
    __syncthreads();
    if (threadIdx.x == 0) {
        int t = 0;
#pragma unroll
        for (int w = 0; w < 8; w++) t += ws[w];
        g_bsum[blockIdx.x] = t;
    }
}
__global__ void k_scanB() {
    __shared__ int s[512];
    int tid = threadIdx.x;
    int v = (tid < NB) ? g_bsum[tid] : 0;
    s[tid] = v;
    __syncthreads();
    for (int off = 1; off < 512; off <<= 1) {
        int t = (tid >= off) ? s[tid - off] : 0;
        __syncthreads();
        s[tid] += t;
        __syncthreads();
    }
    if (tid < NB) g_boff[tid] = s[tid] - v;
}
__global__ void k_scanC() {   // also computes dinv
    __shared__ int s[256];
    int tid = threadIdx.x;
    int i = blockIdx.x * 256 + tid;
    int v = (i < NN) ? g_deg[i] : 0;
    s[tid] = v;
    __syncthreads();
    for (int off = 1; off < 256; off <<= 1) {
        int t = (tid >= off) ? s[tid - off] : 0;
        __syncthreads();
        s[tid] += t;
        __syncthreads();
    }
    if (i < NN) {
        int r = g_boff[blockIdx.x] + s[tid] - v;
        g_rowptr[i] = r;
        g_cursor[i] = r;
        g_dinv[i] = rsqrtf((float)(v + 1));
    }
}
__global__ void k_fill(const int* __restrict__ src, const int* __restrict__ dst) {
    int e = blockIdx.x * blockDim.x + threadIdx.x;
    if (e >= EE) return;
    int d = dst[e];
    int p = atomicAdd(&g_cursor[d], 1);
    g_csrc[p] = src[e];
    g_eid[p] = e;
}

// ---------------- weight prep: transpose + hi/lo split, [n][k] layout ----------------
__global__ void k_prep_w(const float* __restrict__ conv_w, const float* __restrict__ mlp_w1) {
    int mat = blockIdx.x;   // 0..2 conv, 3..4 mlp halves
    const float* W = (mat < 3) ? conv_w + mat * 16384 : mlp_w1 + (mat - 3) * 16384;
    for (int idx = threadIdx.x; idx < 16384; idx += blockDim.x) {
        int n = idx >> 7, k = idx & 127;
        float w = W[k * 128 + n];                   // B[n][k] = W[k][n]
        __nv_bfloat16 hi = __float2bfloat16(w);
        __nv_bfloat16 lo = __float2bfloat16(w - __bfloat162float(hi));
        g_Whi[mat * 16384 + idx] = hi;
        g_Wlo[mat * 16384 + idx] = lo;
    }
}

// ---------------- mma.sync GEMM: 64-row tiles, 2 CTA/SM, templated output dtype ----------------
#define RS 272
#define SM_AHI 0
#define SM_ALO (64 * RS)
#define SM_BHI (2 * 64 * RS)
#define SM_BLO (2 * 64 * RS + 128 * RS)
#define SMEM_SZ (2 * 64 * RS + 2 * 128 * RS)   // 104448 B

__device__ __forceinline__ void gemm_fill_A(char* smem, const float* __restrict__ A,
                                            int row0, int M, int wid, int lane) {
#pragma unroll
    for (int it = 0; it < 8; it++) {
        int r = it * 8 + wid;
        int kc = lane * 4;
        int grow = row0 + r;
        float4 v = make_float4(0.f, 0.f, 0.f, 0.f);
        if (grow < M) v = *(const float4*)&A[(size_t)grow * 128 + kc];
        __nv_bfloat16 h0 = __float2bfloat16(v.x), h1 = __float2bfloat16(v.y);
        __nv_bfloat16 h2 = __float2bfloat16(v.z), h3 = __float2bfloat16(v.w);
        __nv_bfloat16 l0 = __float2bfloat16(v.x - __bfloat162float(h0));
        __nv_bfloat16 l1 = __float2bfloat16(v.y - __bfloat162float(h1));
        __nv_bfloat16 l2 = __float2bfloat16(v.z - __bfloat162float(h2));
        __nv_bfloat16 l3 = __float2bfloat16(v.w - __bfloat162float(h3));
        __nv_bfloat162 hA = {h0, h1}, hB = {h2, h3}, lA = {l0, l1}, lB = {l2, l3};
        uint2 hp = {*(uint32_t*)&hA, *(uint32_t*)&hB};
        uint2 lp = {*(uint32_t*)&lA, *(uint32_t*)&lB};
        *(uint2*)(smem + SM_AHI + r * RS + lane * 8) = hp;
        *(uint2*)(smem + SM_ALO + r * RS + lane * 8) = lp;
    }
}

__device__ __forceinline__ void gemm_fill_B(char* smem, int mat, int tid) {
    const float4* bh = (const float4*)(g_Whi + mat * 16384);
    const float4* bl = (const float4*)(g_Wlo + mat * 16384);
#pragma unroll
    for (int i = tid; i < 2048; i += 256) {
        int n = i >> 4, seg = i & 15;
        *(float4*)(smem + SM_BHI + n * RS + seg * 16) = bh[i];
        *(float4*)(smem + SM_BLO + n * RS + seg * 16) = bl[i];
    }
}

template <bool H16>
__device__ __forceinline__ void gemm_core_epi(char* smem, uint32_t sb,
                                              void* __restrict__ Cp, int M,
                                              const float* __restrict__ rowscale,
                                              int row0, int wid, int lane) {
    int arow = (wid >> 1) * 16 + (lane & 7) + ((lane >> 3) & 1) * 8;
    uint32_t akb = ((lane >> 4) & 1) * 16;
    uint32_t aA0 = sb + SM_AHI + arow * RS + akb;
    int brow = (lane & 7) + ((lane >> 4) & 1) * 8;
    uint32_t bkb = ((lane >> 3) & 1) * 16;
    uint32_t bB0 = sb + SM_BHI + ((wid & 1) * 64 + brow) * RS + bkb;

    float acc[8][4];
#pragma unroll
    for (int n = 0; n < 8; n++)
#pragma unroll
        for (int j = 0; j < 4; j++) acc[n][j] = 0.f;

#pragma unroll
    for (int ks = 0; ks < 8; ks++) {
        uint32_t ko = ks * 32;
        uint32_t ahi[4], alo[4];
        ldm4(ahi, aA0 + ko);
        ldm4(alo, aA0 + (SM_ALO - SM_AHI) + ko);
#pragma unroll
        for (int g = 0; g < 4; g++) {
            uint32_t bhi[4], blo[4];
            ldm4(bhi, bB0 + g * 16 * RS + ko);
            ldm4(blo, bB0 + g * 16 * RS + (SM_BLO - SM_BHI) + ko);
#pragma unroll
            for (int h = 0; h < 2; h++) {
                int n = g * 2 + h;
                mma_bf16(acc[n], ahi, &bhi[h * 2]);
                mma_bf16(acc[n], ahi, &blo[h * 2]);
                mma_bf16(acc[n], alo, &bhi[h * 2]);
            }
        }
    }

    int r0r = row0 + (wid >> 1) * 16 + (lane >> 2);
    int r1r = r0r + 8;
    int cbase = (wid & 1) * 64;
    float s0 = 1.f, s1 = 1.f;
    if (rowscale) {
        if (r0r < M) s0 = rowscale[r0r];
        if (r1r < M) s1 = rowscale[r1r];
    }
#pragma unroll
    for (int n = 0; n < 8; n++) {
        int col = cbase + n * 8 + (lane & 3) * 2;
        if (H16) {
            __half2* C2 = (__half2*)Cp;
            if (r0r < M)
                C2[(size_t)r0r * 64 + (col >> 1)] = __floats2half2_rn(acc[n][0] * s0, acc[n][1] * s0);
            if (r1r < M)
                C2[(size_t)r1r * 64 + (col >> 1)] = __floats2half2_rn(acc[n][2] * s1, acc[n][3] * s1);
        } else {
            float* C = (float*)Cp;
            if (r0r < M) {
                float2 o = {acc[n][0] * s0, acc[n][1] * s0};
                *(float2*)&C[(size_t)r0r * 128 + col] = o;
            }
            if (r1r < M) {
                float2 o = {acc[n][2] * s1, acc[n][3] * s1};
                *(float2*)&C[(size_t)r1r * 128 + col] = o;
            }
        }
    }
}

// conv-layer GEMM: writes fp16 h_scaled
__global__ void __launch_bounds__(256, 2)
k_gemm_h16(const float* __restrict__ A, int mat, __half* __restrict__ C, int M,
           const float* __restrict__ rowscale) {
    extern __shared__ char smem[];
    uint32_t sb = smem_u32(smem);
    int tid = threadIdx.x, wid = tid >> 5, lane = tid & 31;
    int row0 = blockIdx.x * 64;
    gemm_fill_B(smem, mat, tid);
    gemm_fill_A(smem, A, row0, M, wid, lane);
    __syncthreads();
    gemm_core_epi<true>(smem, sb, C, M, rowscale, row0, wid, lane);
}

// P (fp16) and Q (fp32) in one pass
__global__ void __launch_bounds__(256, 2)
k_gemm_pq(const float* __restrict__ A, __half* __restrict__ P, float* __restrict__ Q, int M) {
    extern __shared__ char smem[];
    uint32_t sb = smem_u32(smem);
    int tid = threadIdx.x, wid = tid >> 5, lane = tid & 31;
    int row0 = blockIdx.x * 64;
    gemm_fill_A(smem, A, row0, M, wid, lane);
    gemm_fill_B(smem, 3, tid);
    __syncthreads();
    gemm_core_epi<true>(smem, sb, P, M, nullptr, row0, wid, lane);
    __syncthreads();
    gemm_fill_B(smem, 4, tid);
    __syncthreads();
    gemm_core_epi<false>(smem, sb, Q, M, nullptr, row0, wid, lane);
}

// ---------------- encoder ----------------
__global__ void k_encoder(const float* __restrict__ nf,
                          const float* __restrict__ w,  const float* __restrict__ b,
                          const float* __restrict__ lg, const float* __restrict__ lb) {
    int gw = blockIdx.x * 8 + (threadIdx.x >> 5);
    int nw = gridDim.x * 8;
    int lane = threadIdx.x & 31;

    float wr[7][4], br[4], lgr[4], lbr[4];
#pragma unroll
    for (int j = 0; j < 4; j++) {
        int c = lane + 32 * j;
        br[j] = b[c]; lgr[j] = lg[c]; lbr[j] = lb[c];
#pragma unroll
        for (int k = 0; k < 7; k++) wr[k][j] = w[k * HH + c];
    }

    for (int n = gw; n < NN; n += nw) {
        float f[7];
#pragma unroll
        for (int k = 0; k < 7; k++) f[k] = nf[n * 7 + k];

        float v[4];
#pragma unroll
        for (int j = 0; j < 4; j++) {
            float a = br[j];
#pragma unroll
            for (int k = 0; k < 7; k++) a = fmaf(f[k], wr[k][j], a);
            v[j] = a;
        }
        float s = 0.f, ss = 0.f;
#pragma unroll
        for (int j = 0; j < 4; j++) { s += v[j]; ss += v[j] * v[j]; }
#pragma unroll
        for (int off = 16; off > 0; off >>= 1) {
            s  += __shfl_xor_sync(0xffffffffu, s,  off);
            ss += __shfl_xor_sync(0xffffffffu, ss, off);
        }
        float mu  = s * (1.f / HH);
        float var = ss * (1.f / HH) - mu * mu;
        float inv = rsqrtf(var + LN_EPS);
#pragma unroll
        for (int j = 0; j < 4; j++) {
            int c = lane + 32 * j;
            float y = (v[j] - mu) * inv * lgr[j] + lbr[j];
            g_x[(size_t)n * HH + c] = fmaxf(y, 0.f);
        }
    }
}

// ---------------- fused layer: fp16 gather + bias + LN + ReLU + residual ----------------
__device__ __forceinline__ void acc_h16(float* a, int row, int lane) {
    uint2 hv = *(const uint2*)&g_h16[(size_t)row * 128 + lane * 4];
    float2 fa = __half22float2(*(__half2*)&hv.x);
    float2 fb = __half22float2(*(__half2*)&hv.y);
    a[0] += fa.x; a[1] += fa.y; a[2] += fb.x; a[3] += fb.y;
}

__global__ void __launch_bounds__(256, 8)
k_gather_ln(const float* __restrict__ cb,
            const float* __restrict__ lg, const float* __restrict__ lb,
            float* __restrict__ xout) {
    int n = blockIdx.x * 8 + (threadIdx.x >> 5);
    if (n >= NN) return;
    int lane = threadIdx.x & 31;

    int beg = g_rowptr[n];
    int cnt = g_deg[n];

    float acc[4] = {0.f, 0.f, 0.f, 0.f};
    acc_h16(acc, n, lane);                         // self loop (pre-scaled)

    for (int base = 0; base < cnt; base += 32) {
        int k = cnt - base;
        if (k > 32) k = 32;
        int sidx = (lane < k) ? g_csrc[beg + base + lane] : 0;
        int j = 0;
        for (; j + 4 <= k; j += 4) {
            int s0 = __shfl_sync(0xffffffffu, sidx, j + 0);
            int s1 = __shfl_sync(0xffffffffu, sidx, j + 1);
            int s2 = __shfl_sync(0xffffffffu, sidx, j + 2);
            int s3 = __shfl_sync(0xffffffffu, sidx, j + 3);
            acc_h16(acc, s0, lane);
            acc_h16(acc, s1, lane);
            acc_h16(acc, s2, lane);
            acc_h16(acc, s3, lane);
        }
        for (; j < k; j++) {
            int sj = __shfl_sync(0xffffffffu, sidx, j);
            acc_h16(acc, sj, lane);
        }
    }

    float di = g_dinv[n];
    float4 b4 = *(const float4*)&cb[lane * 4];
    float v[4] = {acc[0] * di + b4.x, acc[1] * di + b4.y,
                  acc[2] * di + b4.z, acc[3] * di + b4.w};

    float s = 0.f, ss = 0.f;
#pragma unroll
    for (int j = 0; j < 4; j++) { s += v[j]; ss += v[j] * v[j]; }
#pragma unroll
    for (int off = 16; off > 0; off >>= 1) {
        s  += __shfl_xor_sync(0xffffffffu, s,  off);
        ss += __shfl_xor_sync(0xffffffffu, ss, off);
    }
    float mu   = s * (1.f / HH);
    float var  = ss * (1.f / HH) - mu * mu;
    float linv = rsqrtf(var + LN_EPS);

    float4 lg4 = *(const float4*)&lg[lane * 4];
    float4 lb4 = *(const float4*)&lb[lane * 4];
    float4 xo  = *(const float4*)&g_x[(size_t)n * 128 + lane * 4];

    float4 y;
    y.x = fmaxf((v[0] - mu) * linv * lg4.x + lb4.x, 0.f) + xo.x;
    y.y = fmaxf((v[1] - mu) * linv * lg4.y + lb4.y, 0.f) + xo.y;
    y.z = fmaxf((v[2] - mu) * linv * lg4.z + lb4.z, 0.f) + xo.z;
    y.w = fmaxf((v[3] - mu) * linv * lg4.w + lb4.w, 0.f) + xo.w;

    *(float4*)&g_x[(size_t)n * 128 + lane * 4] = y;
    if (xout) *(float4*)&xout[(size_t)n * 128 + lane * 4] = y;
}

// ---------------- edge MLP, CSR-grouped by dst, fp16 P ----------------
__global__ void __launch_bounds__(256, 8)
k_edge_mlp_csr(const float* __restrict__ b1, const float* __restrict__ w2,
               const float* __restrict__ b2, float* __restrict__ out) {
    int n = blockIdx.x * 8 + (threadIdx.x >> 5);
    if (n >= NN) return;
    int lane = threadIdx.x & 31;

    int beg = g_rowptr[n];
    int cnt = g_deg[n];
    if (cnt == 0) return;

    float4 qb = *(const float4*)&g_Q[(size_t)n * 128 + lane * 4];
    float4 bb = *(const float4*)&b1[lane * 4];
    qb.x += bb.x; qb.y += bb.y; qb.z += bb.z; qb.w += bb.w;
    float4 w = *(const float4*)&w2[lane * 4];
    float bias2 = b2[0];

    for (int base = 0; base < cnt; base += 32) {
        int k = cnt - base;
        if (k > 32) k = 32;
        int sidx = 0, eidx = 0;
        if (lane < k) {
            sidx = g_csrc[beg + base + lane];
            eidx = g_eid [beg + base + lane];
        }
        float myval = 0.f;
        for (int j = 0; j < k; j++) {
            int sj = __shfl_sync(0xffffffffu, sidx, j);
            uint2 pv = *(const uint2*)&g_P16[(size_t)sj * 128 + lane * 4];
            float2 pa = __half22float2(*(__half2*)&pv.x);
            float2 pb = __half22float2(*(__half2*)&pv.y);
            float h0 = fmaxf(pa.x + qb.x, 0.f);
            float h1 = fmaxf(pa.y + qb.y, 0.f);
            float h2 = fmaxf(pb.x + qb.z, 0.f);
            float h3 = fmaxf(pb.y + qb.w, 0.f);
            float part = fmaf(h0, w.x, fmaf(h1, w.y, fmaf(h2, w.z, h3 * w.w)));
#pragma unroll
            for (int off = 16; off > 0; off >>= 1)
                part += __shfl_xor_sync(0xffffffffu, part, off);
            if (lane == j) myval = part;
        }
        if (lane < k) out[eidx] = myval + bias2;
    }
}

// ---------------- host ----------------
extern "C" void kernel_launch(void* const* d_in, const int* in_sizes, int n_in,
                              void* d_out, int out_size) {
    const float* nf       = (const float*)d_in[0];
    const int*   ei       = (const int*)  d_in[1];
    const float* enc_w    = (const float*)d_in[3];
    const float* enc_b    = (const float*)d_in[4];
    const float* enc_ln_g = (const float*)d_in[5];
    const float* enc_ln_b = (const float*)d_in[6];
    const float* conv_w   = (const float*)d_in[7];
    const float* conv_b   = (const float*)d_in[8];
    const float* ln_g     = (const float*)d_in[9];
    const float* ln_b     = (const float*)d_in[10];
    const float* mlp_w1   = (const float*)d_in[11];
    const float* mlp_b1   = (const float*)d_in[12];
    const float* mlp_w2   = (const float*)d_in[13];
    const float* mlp_b2   = (const float*)d_in[14];

    const int* src = ei;
    const int* dst = ei + EE;

    float* out        = (float*)d_out;
    float* out_logits = out + (size_t)NN * HH;

    float *px, *pQ, *pdinv;
    __half *ph16, *pP16;
    cudaGetSymbolAddress((void**)&px,   g_x);
    cudaGetSymbolAddress((void**)&ph16, g_h16);
    cudaGetSymbolAddress((void**)&pP16, g_P16);
    cudaGetSymbolAddress((void**)&pQ,   g_Q);
    cudaGetSymbolAddress((void**)&pdinv, g_dinv);

    cudaFuncSetAttribute(k_gemm_h16, cudaFuncAttributeMaxDynamicSharedMemorySize, SMEM_SZ);
    cudaFuncSetAttribute(k_gemm_pq,  cudaFuncAttributeMaxDynamicSharedMemorySize, SMEM_SZ);

    // side stream + events (created once; host-side only)
    static cudaStream_t s1 = nullptr;
    static cudaEvent_t ev_fork0 = nullptr, ev_enc = nullptr, ev_fork1 = nullptr, ev_fill = nullptr;
    if (!s1) {
        cudaStreamCreateWithFlags(&s1, cudaStreamNonBlocking);
        cudaEventCreateWithFlags(&ev_fork0, cudaEventDisableTiming);
        cudaEventCreateWithFlags(&ev_enc,   cudaEventDisableTiming);
        cudaEventCreateWithFlags(&ev_fork1, cudaEventDisableTiming);
        cudaEventCreateWithFlags(&ev_fill,  cudaEventDisableTiming);
    }

    // ---- fork: encoder + weight prep on s1 ----
    cudaEventRecord(ev_fork0, 0);
    cudaStreamWaitEvent(s1, ev_fork0, 0);
    k_encoder<<<1184, 256, 0, s1>>>(nf, enc_w, enc_b, enc_ln_g, enc_ln_b);
    k_prep_w <<<5, 256, 0, s1>>>(conv_w, mlp_w1);
    cudaEventRecord(ev_enc, s1);

    // ---- main: degree + scan chain ----
    k_deg_zero <<<(NN + 255) / 256, 256>>>();
    k_deg_count<<<(EE + 255) / 256, 256>>>(dst);
    k_scanA<<<NB, 256>>>();
    k_scanB<<<1, 512>>>();
    k_scanC<<<NB, 256>>>();

    // ---- fork: fill runs under gemm l0 ----
    cudaEventRecord(ev_fork1, 0);
    cudaStreamWaitEvent(s1, ev_fork1, 0);
    k_fill<<<(EE + 255) / 256, 256, 0, s1>>>(src, dst);
    cudaEventRecord(ev_fill, s1);

    // ---- main: layer pipeline ----
    cudaStreamWaitEvent(0, ev_enc, 0);
    for (int l = 0; l < 3; l++) {
        k_gemm_h16<<<GB64, 256, SMEM_SZ>>>(px, l, ph16, NN, pdinv);
        if (l == 0) cudaStreamWaitEvent(0, ev_fill, 0);
        k_gather_ln<<<(NN + 7) / 8, 256>>>(conv_b + l * HH, ln_g + l * HH, ln_b + l * HH,
                                           (l == 2) ? out : nullptr);
    }

    // edge scoring
    k_gemm_pq<<<GB64, 256, SMEM_SZ>>>(px, pP16, pQ, NN);
    k_edge_mlp_csr<<<(NN + 7) / 8, 256>>>(mlp_b1, mlp_w2, mlp_b2, out_logits);
}

// round 10
// speedup vs baseline: 2.5577x; 1.0057x over previous
#include <cuda_runtime.h>
#include <cuda_bf16.h>
#include <cuda_fp16.h>
#include <cstdint>

#define NN 100000
#define HH 128
#define EE 1600000
#define LN_EPS 1e-5f
#define NB 391           // (NN+255)/256
#define GB64 1563        // (NN+63)/64 gemm tiles

// ---------------- device scratch ----------------
__device__ float  g_x  [NN * HH];
__device__ __half g_h16[NN * HH];    // h_scaled = (x@W)*dinv, fp16 storage
__device__ __half g_P16[NN * HH];    // P = x@W1[:128], fp16 storage
__device__ float  g_Q  [NN * HH];    // Q = x@W1[128:], fp32 (read once per node)
__device__ int   g_deg   [NN];
__device__ float g_dinv  [NN];
__device__ int   g_rowptr[NN];
__device__ int   g_cursor[NN];
__device__ int   g_csrc  [EE];
__device__ int   g_eid   [EE];
__device__ int   g_bsum  [NB];
__device__ int   g_boff  [NB];
__device__ __nv_bfloat16 g_Whi[5 * 16384];   // B = W^T, [n][k] row-major
__device__ __nv_bfloat16 g_Wlo[5 * 16384];

// ---------------- helpers ----------------
__device__ __forceinline__ uint32_t smem_u32(const void* p) {
    uint32_t a;
    asm("{ .reg .u64 t; cvta.to.shared.u64 t, %1; cvt.u32.u64 %0, t; }" : "=r"(a) : "l"(p));
    return a;
}
__device__ __forceinline__ void ldm4(uint32_t* r, uint32_t addr) {
    asm volatile("ldmatrix.sync.aligned.m8n8.x4.shared.b16 {%0,%1,%2,%3}, [%4];"
                 : "=r"(r[0]), "=r"(r[1]), "=r"(r[2]), "=r"(r[3]) : "r"(addr));
}
__device__ __forceinline__ void mma_bf16(float* d, const uint32_t* a, const uint32_t* b) {
    asm volatile("mma.sync.aligned.m16n8k16.row.col.f32.bf16.bf16.f32 "
                 "{%0,%1,%2,%3}, {%4,%5,%6,%7}, {%8,%9}, {%0,%1,%2,%3};"
                 : "+f"(d[0]), "+f"(d[1]), "+f"(d[2]), "+f"(d[3])
                 : "r"(a[0]), "r"(a[1]), "r"(a[2]), "r"(a[3]), "r"(b[0]), "r"(b[1]));
}

// ---------------- degree ----------------
__global__ void k_deg_zero() {
    int i = blockIdx.x * blockDim.x + threadIdx.x;
    if (i < NN) g_deg[i] = 0;
}
__global__ void k_deg_count(const int* __restrict__ dst) {
    int i = blockIdx.x * blockDim.x + threadIdx.x;
    if (i < EE) atomicAdd(&g_deg[dst[i]], 1);
}

// ---------------- CSR build ----------------
__global__ void k_scanA() {
    __shared__ int ws[8];
    int i = blockIdx.x * 256 + threadIdx.x;
    int v = (i < NN) ? g_deg[i] : 0;
#pragma unroll
    for (int off = 16; off > 0; off >>= 1) v += __shfl_xor_sync(0xffffffffu, v, off);
    if ((threadIdx.x & 31) == 0) ws[threadIdx.x >> 5] = v;
    __syncthreads();
    if (threadIdx.x == 0) {
        int t = 0;
#pragma unroll
        for (int w = 0; w < 8; w++) t += ws[w];
        g_bsum[blockIdx.x] = t;
    }
}
__global__ void k_scanB() {
    __shared__ int s[512];
    int tid = threadIdx.x;
    int v = (tid < NB) ? g_bsum[tid] : 0;
    s[tid] = v;
    __syncthreads();
    for (int off = 1; off < 512; off <<= 1) {
        int t = (tid >= off) ? s[tid - off] : 0;
        __syncthreads();
        s[tid] += t;
        __syncthreads();
    }
    if (tid < NB) g_boff[tid] = s[tid] - v;
}
__global__ void k_scanC() {   // also computes dinv
    __shared__ int s[256];
    int tid = threadIdx.x;
    int i = blockIdx.x * 256 + tid;
    int v = (i < NN) ? g_deg[i] : 0;
    s[tid] = v;
    __syncthreads();
    for (int off = 1; off < 256; off <<= 1) {
        int t = (tid >= off) ? s[tid - off] : 0;
        __syncthreads();
        s[tid] += t;
        __syncthreads();
    }
    if (i < NN) {
        int r = g_boff[blockIdx.x] + s[tid] - v;
        g_rowptr[i] = r;
        g_cursor[i] = r;
        g_dinv[i] = rsqrtf((float)(v + 1));
    }
}
__global__ void k_fill(const int* __restrict__ src, const int* __restrict__ dst) {
    int e = blockIdx.x * blockDim.x + threadIdx.x;
    if (e >= EE) return;
    int d = dst[e];
    int p = atomicAdd(&g_cursor[d], 1);
    g_csrc[p] = src[e];
    g_eid[p] = e;
}

// ---------------- weight prep: transpose + hi/lo split, [n][k] layout ----------------
__global__ void k_prep_w(const float* __restrict__ conv_w, const float* __restrict__ mlp_w1) {
    int mat = blockIdx.x;   // 0..2 conv, 3..4 mlp halves
    const float* W = (mat < 3) ? conv_w + mat * 16384 : mlp_w1 + (mat - 3) * 16384;
    for (int idx = threadIdx.x; idx < 16384; idx += blockDim.x) {
        int n = idx >> 7, k = idx & 127;
        float w = W[k * 128 + n];                   // B[n][k] = W[k][n]
        __nv_bfloat16 hi = __float2bfloat16(w);
        __nv_bfloat16 lo = __float2bfloat16(w - __bfloat162float(hi));
        g_Whi[mat * 16384 + idx] = hi;
        g_Wlo[mat * 16384 + idx] = lo;
    }
}

// ---------------- mma.sync GEMM: 64-row tiles, 2 CTA/SM, templated output dtype ----------------
#define RS 272
#define SM_AHI 0
#define SM_ALO (64 * RS)
#define SM_BHI (2 * 64 * RS)
#define SM_BLO (2 * 64 * RS + 128 * RS)
#define SMEM_SZ (2 * 64 * RS + 2 * 128 * RS)   // 104448 B

__device__ __forceinline__ void gemm_fill_A(char* smem, const float* __restrict__ A,
                                            int row0, int M, int wid, int lane) {
#pragma unroll
    for (int it = 0; it < 8; it++) {
        int r = it * 8 + wid;
        int kc = lane * 4;
        int grow = row0 + r;
        float4 v = make_float4(0.f, 0.f, 0.f, 0.f);
        if (grow < M) v = *(const float4*)&A[(size_t)grow * 128 + kc];
        __nv_bfloat16 h0 = __float2bfloat16(v.x), h1 = __float2bfloat16(v.y);
        __nv_bfloat16 h2 = __float2bfloat16(v.z), h3 = __float2bfloat16(v.w);
        __nv_bfloat16 l0 = __float2bfloat16(v.x - __bfloat162float(h0));
        __nv_bfloat16 l1 = __float2bfloat16(v.y - __bfloat162float(h1));
        __nv_bfloat16 l2 = __float2bfloat16(v.z - __bfloat162float(h2));
        __nv_bfloat16 l3 = __float2bfloat16(v.w - __bfloat162float(h3));
        __nv_bfloat162 hA = {h0, h1}, hB = {h2, h3}, lA = {l0, l1}, lB = {l2, l3};
        uint2 hp = {*(uint32_t*)&hA, *(uint32_t*)&hB};
        uint2 lp = {*(uint32_t*)&lA, *(uint32_t*)&lB};
        *(uint2*)(smem + SM_AHI + r * RS + lane * 8) = hp;
        *(uint2*)(smem + SM_ALO + r * RS + lane * 8) = lp;
    }
}

__device__ __forceinline__ void gemm_fill_B(char* smem, int mat, int tid) {
    const float4* bh = (const float4*)(g_Whi + mat * 16384);
    const float4* bl = (const float4*)(g_Wlo + mat * 16384);
#pragma unroll
    for (int i = tid; i < 2048; i += 256) {
        int n = i >> 4, seg = i & 15;
        *(float4*)(smem + SM_BHI + n * RS + seg * 16) = bh[i];
        *(float4*)(smem + SM_BLO + n * RS + seg * 16) = bl[i];
    }
}

template <bool H16>
__device__ __forceinline__ void gemm_core_epi(char* smem, uint32_t sb,
                                              void* __restrict__ Cp, int M,
                                              const float* __restrict__ rowscale,
                                              int row0, int wid, int lane) {
    int arow = (wid >> 1) * 16 + (lane & 7) + ((lane >> 3) & 1) * 8;
    uint32_t akb = ((lane >> 4) & 1) * 16;
    uint32_t aA0 = sb + SM_AHI + arow * RS + akb;
    int brow = (lane & 7) + ((lane >> 4) & 1) * 8;
    uint32_t bkb = ((lane >> 3) & 1) * 16;
    uint32_t bB0 = sb + SM_BHI + ((wid & 1) * 64 + brow) * RS + bkb;

    float acc[8][4];
#pragma unroll
    for (int n = 0; n < 8; n++)
#pragma unroll
        for (int j = 0; j < 4; j++) acc[n][j] = 0.f;

#pragma unroll
    for (int ks = 0; ks < 8; ks++) {
        uint32_t ko = ks * 32;
        uint32_t ahi[4], alo[4];
        ldm4(ahi, aA0 + ko);
        ldm4(alo, aA0 + (SM_ALO - SM_AHI) + ko);
#pragma unroll
        for (int g = 0; g < 4; g++) {
            uint32_t bhi[4], blo[4];
            ldm4(bhi, bB0 + g * 16 * RS + ko);
            ldm4(blo, bB0 + g * 16 * RS + (SM_BLO - SM_BHI) + ko);
#pragma unroll
            for (int h = 0; h < 2; h++) {
                int n = g * 2 + h;
                mma_bf16(acc[n], ahi, &bhi[h * 2]);
                mma_bf16(acc[n], ahi, &blo[h * 2]);
                mma_bf16(acc[n], alo, &bhi[h * 2]);
            }
        }
    }

    int r0r = row0 + (wid >> 1) * 16 + (lane >> 2);
    int r1r = r0r + 8;
    int cbase = (wid & 1) * 64;
    float s0 = 1.f, s1 = 1.f;
    if (rowscale) {
        if (r0r < M) s0 = rowscale[r0r];
        if (r1r < M) s1 = rowscale[r1r];
    }
#pragma unroll
    for (int n = 0; n < 8; n++) {
        int col = cbase + n * 8 + (lane & 3) * 2;
        if (H16) {
            __half2* C2 = (__half2*)Cp;
            if (r0r < M)
                C2[(size_t)r0r * 64 + (col >> 1)] = __floats2half2_rn(acc[n][0] * s0, acc[n][1] * s0);
            if (r1r < M)
                C2[(size_t)r1r * 64 + (col >> 1)] = __floats2half2_rn(acc[n][2] * s1, acc[n][3] * s1);
        } else {
            float* C = (float*)Cp;
            if (r0r < M) {
                float2 o = {acc[n][0] * s0, acc[n][1] * s0};
                *(float2*)&C[(size_t)r0r * 128 + col] = o;
            }
            if (r1r < M) {
                float2 o = {acc[n][2] * s1, acc[n][3] * s1};
                *(float2*)&C[(size_t)r1r * 128 + col] = o;
            }
        }
    }
}

// conv-layer GEMM: writes fp16 h_scaled
__global__ void __launch_bounds__(256, 2)
k_gemm_h16(const float* __restrict__ A, int mat, __half* __restrict__ C, int M,
           const float* __restrict__ rowscale) {
    extern __shared__ char smem[];
    uint32_t sb = smem_u32(smem);
    int tid = threadIdx.x, wid = tid >> 5, lane = tid & 31;
    int row0 = blockIdx.x * 64;
    gemm_fill_B(smem, mat, tid);
    gemm_fill_A(smem, A, row0, M, wid, lane);
    __syncthreads();
    gemm_core_epi<true>(smem, sb, C, M, rowscale, row0, wid, lane);
}

// P (fp16) and Q (fp32) in one pass
__global__ void __launch_bounds__(256, 2)
k_gemm_pq(const float* __restrict__ A, __half* __restrict__ P, float* __restrict__ Q, int M) {
    extern __shared__ char smem[];
    uint32_t sb = smem_u32(smem);
    int tid = threadIdx.x, wid = tid >> 5, lane = tid & 31;
    int row0 = blockIdx.x * 64;
    gemm_fill_A(smem, A, row0, M, wid, lane);
    gemm_fill_B(smem, 3, tid);
    __syncthreads();
    gemm_core_epi<true>(smem, sb, P, M, nullptr, row0, wid, lane);
    __syncthreads();
    gemm_fill_B(smem, 4, tid);
    __syncthreads();
    gemm_core_epi<false>(smem, sb, Q, M, nullptr, row0, wid, lane);
}

// ---------------- encoder ----------------
__global__ void k_encoder(const float* __restrict__ nf,
                          const float* __restrict__ w,  const float* __restrict__ b,
                          const float* __restrict__ lg, const float* __restrict__ lb) {
    int gw = blockIdx.x * 8 + (threadIdx.x >> 5);
    int nw = gridDim.x * 8;
    int lane = threadIdx.x & 31;

    float wr[7][4], br[4], lgr[4], lbr[4];
#pragma unroll
    for (int j = 0; j < 4; j++) {
        int c = lane + 32 * j;
        br[j] = b[c]; lgr[j] = lg[c]; lbr[j] = lb[c];
#pragma unroll
        for (int k = 0; k < 7; k++) wr[k][j] = w[k * HH + c];
    }

    for (int n = gw; n < NN; n += nw) {
        float f[7];
#pragma unroll
        for (int k = 0; k < 7; k++) f[k] = nf[n * 7 + k];

        float v[4];
#pragma unroll
        for (int j = 0; j < 4; j++) {
            float a = br[j];
#pragma unroll
            for (int k = 0; k < 7; k++) a = fmaf(f[k], wr[k][j], a);
            v[j] = a;
        }
        float s = 0.f, ss = 0.f;
#pragma unroll
        for (int j = 0; j < 4; j++) { s += v[j]; ss += v[j] * v[j]; }
#pragma unroll
        for (int off = 16; off > 0; off >>= 1) {
            s  += __shfl_xor_sync(0xffffffffu, s,  off);
            ss += __shfl_xor_sync(0xffffffffu, ss, off);
        }
        float mu  = s * (1.f / HH);
        float var = ss * (1.f / HH) - mu * mu;
        float inv = rsqrtf(var + LN_EPS);
#pragma unroll
        for (int j = 0; j < 4; j++) {
            int c = lane + 32 * j;
            float y = (v[j] - mu) * inv * lgr[j] + lbr[j];
            g_x[(size_t)n * HH + c] = fmaxf(y, 0.f);
        }
    }
}

// ---------------- fused layer: fp16 gather + bias + LN + ReLU + residual ----------------
__device__ __forceinline__ void acc_h16(float* a, int row, int lane) {
    uint2 hv = *(const uint2*)&g_h16[(size_t)row * 128 + lane * 4];
    float2 fa = __half22float2(*(__half2*)&hv.x);
    float2 fb = __half22float2(*(__half2*)&hv.y);
    a[0] += fa.x; a[1] += fa.y; a[2] += fb.x; a[3] += fb.y;
}

__global__ void __launch_bounds__(256, 8)
k_gather_ln(const float* __restrict__ cb,
            const float* __restrict__ lg, const float* __restrict__ lb,
            float* __restrict__ xout) {
    int n = blockIdx.x * 8 + (threadIdx.x >> 5);
    if (n >= NN) return;
    int lane = threadIdx.x & 31;

    int beg = g_rowptr[n];
    int cnt = g_deg[n];

    float acc[4] = {0.f, 0.f, 0.f, 0.f};
    acc_h16(acc, n, lane);                         // self loop (pre-scaled)

    for (int base = 0; base < cnt; base += 32) {
        int k = cnt - base;
        if (k > 32) k = 32;
        int sidx = (lane < k) ? g_csrc[beg + base + lane] : 0;
        int j = 0;
        for (; j + 8 <= k; j += 8) {
            int s0 = __shfl_sync(0xffffffffu, sidx, j + 0);
            int s1 = __shfl_sync(0xffffffffu, sidx, j + 1);
            int s2 = __shfl_sync(0xffffffffu, sidx, j + 2);
            int s3 = __shfl_sync(0xffffffffu, sidx, j + 3);
            int s4 = __shfl_sync(0xffffffffu, sidx, j + 4);
            int s5 = __shfl_sync(0xffffffffu, sidx, j + 5);
            int s6 = __shfl_sync(0xffffffffu, sidx, j + 6);
            int s7 = __shfl_sync(0xffffffffu, sidx, j + 7);
            acc_h16(acc, s0, lane); acc_h16(acc, s1, lane);
            acc_h16(acc, s2, lane); acc_h16(acc, s3, lane);
            acc_h16(acc, s4, lane); acc_h16(acc, s5, lane);
            acc_h16(acc, s6, lane); acc_h16(acc, s7, lane);
        }
        for (; j < k; j++) {
            int sj = __shfl_sync(0xffffffffu, sidx, j);
            acc_h16(acc, sj, lane);
        }
    }

    float di = g_dinv[n];
    float4 b4 = *(const float4*)&cb[lane * 4];
    float v[4] = {acc[0] * di + b4.x, acc[1] * di + b4.y,
                  acc[2] * di + b4.z, acc[3] * di + b4.w};

    float s = 0.f, ss = 0.f;
#pragma unroll
    for (int j = 0; j < 4; j++) { s += v[j]; ss += v[j] * v[j]; }
#pragma unroll
    for (int off = 16; off > 0; off >>= 1) {
        s  += __shfl_xor_sync(0xffffffffu, s,  off);
        ss += __shfl_xor_sync(0xffffffffu, ss, off);
    }
    float mu   = s * (1.f / HH);
    float var  = ss * (1.f / HH) - mu * mu;
    float linv = rsqrtf(var + LN_EPS);

    float4 lg4 = *(const float4*)&lg[lane * 4];
    float4 lb4 = *(const float4*)&lb[lane * 4];
    float4 xo  = *(const float4*)&g_x[(size_t)n * 128 + lane * 4];

    float4 y;
    y.x = fmaxf((v[0] - mu) * linv * lg4.x + lb4.x, 0.f) + xo.x;
    y.y = fmaxf((v[1] - mu) * linv * lg4.y + lb4.y, 0.f) + xo.y;
    y.z = fmaxf((v[2] - mu) * linv * lg4.z + lb4.z, 0.f) + xo.z;
    y.w = fmaxf((v[3] - mu) * linv * lg4.w + lb4.w, 0.f) + xo.w;

    *(float4*)&g_x[(size_t)n * 128 + lane * 4] = y;
    if (xout) *(float4*)&xout[(size_t)n * 128 + lane * 4] = y;
}

// ---------------- edge MLP, CSR-grouped, smem-transpose reduction (no shfl chain) ----------------
// sp rows are 33 floats (4B-aligned only) -> reduction uses SCALAR LDS, bank-conflict-free.
__global__ void __launch_bounds__(256)
k_edge_mlp_csr(const float* __restrict__ b1, const float* __restrict__ w2,
               const float* __restrict__ b2, float* __restrict__ out) {
    __shared__ float sp[8][32][33];
    int wslot = threadIdx.x >> 5;
    int n = blockIdx.x * 8 + wslot;
    if (n >= NN) return;
    int lane = threadIdx.x & 31;

    int beg = g_rowptr[n];
    int cnt = g_deg[n];
    if (cnt == 0) return;

    float4 qb = *(const float4*)&g_Q[(size_t)n * 128 + lane * 4];
    float4 bb = *(const float4*)&b1[lane * 4];
    qb.x += bb.x; qb.y += bb.y; qb.z += bb.z; qb.w += bb.w;
    float4 w = *(const float4*)&w2[lane * 4];
    float bias2 = b2[0];

    for (int base = 0; base < cnt; base += 32) {
        int k = cnt - base;
        if (k > 32) k = 32;
        int sidx = 0, eidx = 0;
        if (lane < k) {
            sidx = g_csrc[beg + base + lane];
            eidx = g_eid [beg + base + lane];
        }
        // independent j iterations: 1 shfl + 1 LDG + fma + 1 STS, no reduce chain
        for (int j = 0; j < k; j++) {
            int sj = __shfl_sync(0xffffffffu, sidx, j);
            uint2 pv = *(const uint2*)&g_P16[(size_t)sj * 128 + lane * 4];
            float2 pa = __half22float2(*(__half2*)&pv.x);
            float2 pb = __half22float2(*(__half2*)&pv.y);
            float h0 = fmaxf(pa.x + qb.x, 0.f);
            float h1 = fmaxf(pa.y + qb.y, 0.f);
            float h2 = fmaxf(pb.x + qb.z, 0.f);
            float h3 = fmaxf(pb.y + qb.w, 0.f);
            sp[wslot][j][lane] = fmaf(h0, w.x, fmaf(h1, w.y, fmaf(h2, w.z, h3 * w.w)));
        }
        __syncwarp();
        if (lane < k) {
            const float* row = sp[wslot][lane];   // 4B-aligned; scalar loads only
            float t0 = 0.f, t1 = 0.f, t2 = 0.f, t3 = 0.f;
#pragma unroll
            for (int i = 0; i < 32; i += 4) {
                t0 += row[i + 0];
                t1 += row[i + 1];
                t2 += row[i + 2];
                t3 += row[i + 3];
            }
            out[eidx] = (t0 + t1) + (t2 + t3) + bias2;
        }
        __syncwarp();
    }
}

// ---------------- host ----------------
extern "C" void kernel_launch(void* const* d_in, const int* in_sizes, int n_in,
                              void* d_out, int out_size) {
    const float* nf       = (const float*)d_in[0];
    const int*   ei       = (const int*)  d_in[1];
    const float* enc_w    = (const float*)d_in[3];
    const float* enc_b    = (const float*)d_in[4];
    const float* enc_ln_g = (const float*)d_in[5];
    const float* enc_ln_b = (const float*)d_in[6];
    const float* conv_w   = (const float*)d_in[7];
    const float* conv_b   = (const float*)d_in[8];
    const float* ln_g     = (const float*)d_in[9];
    const float* ln_b     = (const float*)d_in[10];
    const float* mlp_w1   = (const float*)d_in[11];
    const float* mlp_b1   = (const float*)d_in[12];
    const float* mlp_w2   = (const float*)d_in[13];
    const float* mlp_b2   = (const float*)d_in[14];

    const int* src = ei;
    const int* dst = ei + EE;

    float* out        = (float*)d_out;
    float* out_logits = out + (size_t)NN * HH;

    float *px, *pQ, *pdinv;
    __half *ph16, *pP16;
    cudaGetSymbolAddress((void**)&px,   g_x);
    cudaGetSymbolAddress((void**)&ph16, g_h16);
    cudaGetSymbolAddress((void**)&pP16, g_P16);
    cudaGetSymbolAddress((void**)&pQ,   g_Q);
    cudaGetSymbolAddress((void**)&pdinv, g_dinv);

    cudaFuncSetAttribute(k_gemm_h16, cudaFuncAttributeMaxDynamicSharedMemorySize, SMEM_SZ);
    cudaFuncSetAttribute(k_gemm_pq,  cudaFuncAttributeMaxDynamicSharedMemorySize, SMEM_SZ);

    // side stream + events (created once; host-side only)
    static cudaStream_t s1 = nullptr;
    static cudaEvent_t ev_fork0 = nullptr, ev_enc = nullptr, ev_fork1 = nullptr, ev_fill = nullptr;
    if (!s1) {
        cudaStreamCreateWithFlags(&s1, cudaStreamNonBlocking);
        cudaEventCreateWithFlags(&ev_fork0, cudaEventDisableTiming);
        cudaEventCreateWithFlags(&ev_enc,   cudaEventDisableTiming);
        cudaEventCreateWithFlags(&ev_fork1, cudaEventDisableTiming);
        cudaEventCreateWithFlags(&ev_fill,  cudaEventDisableTiming);
    }

    // ---- fork: encoder + weight prep on s1 ----
    cudaEventRecord(ev_fork0, 0);
    cudaStreamWaitEvent(s1, ev_fork0, 0);
    k_encoder<<<1184, 256, 0, s1>>>(nf, enc_w, enc_b, enc_ln_g, enc_ln_b);
    k_prep_w <<<5, 256, 0, s1>>>(conv_w, mlp_w1);
    cudaEventRecord(ev_enc, s1);

    // ---- main: degree + scan chain ----
    k_deg_zero <<<(NN + 255) / 256, 256>>>();
    k_deg_count<<<(EE + 255) / 256, 256>>>(dst);
    k_scanA<<<NB, 256>>>();
    k_scanB<<<1, 512>>>();
    k_scanC<<<NB, 256>>>();

    // ---- fork: fill runs under gemm l0 ----
    cudaEventRecord(ev_fork1, 0);
    cudaStreamWaitEvent(s1, ev_fork1, 0);
    k_fill<<<(EE + 255) / 256, 256, 0, s1>>>(src, dst);
    cudaEventRecord(ev_fill, s1);

    // ---- main: layer pipeline ----
    cudaStreamWaitEvent(0, ev_enc, 0);
    for (int l = 0; l < 3; l++) {
        k_gemm_h16<<<GB64, 256, SMEM_SZ>>>(px, l, ph16, NN, pdinv);
        if (l == 0) cudaStreamWaitEvent(0, ev_fill, 0);
        k_gather_ln<<<(NN + 7) / 8, 256>>>(conv_b + l * HH, ln_g + l * HH, ln_b + l * HH,
                                           (l == 2) ? out : nullptr);
    }

    // edge scoring
    k_gemm_pq<<<GB64, 256, SMEM_SZ>>>(px, pP16, pQ, NN);
    k_edge_mlp_csr<<<(NN + 7) / 8, 256>>>(mlp_b1, mlp_w2, mlp_b2, out_logits);
}

// round 11
// speedup vs baseline: 2.7129x; 1.0607x over previous
#include <cuda_runtime.h>
#include <cuda_fp16.h>
#include <cstdint>

#define NN 100000
#define HH 128
#define EE 1600000
#define LN_EPS 1e-5f
#define NB 391           // (NN+255)/256
#define GB64 1563        // (NN+63)/64 gemm tiles

// ---------------- device scratch ----------------
__device__ float  g_x  [NN * HH];
__device__ __half g_h16[NN * HH];    // h_scaled = (x@W)*dinv, fp16 storage
__device__ __half g_P16[NN * HH];    // P = x@W1[:128], fp16 storage
__device__ float  g_Q  [NN * HH];    // Q = x@W1[128:], fp32 (read once per node)
__device__ int   g_deg   [NN];
__device__ float g_dinv  [NN];
__device__ int   g_rowptr[NN];
__device__ int   g_cursor[NN];
__device__ int   g_csrc  [EE];
__device__ int   g_eid   [EE];
__device__ int   g_bsum  [NB];
__device__ int   g_boff  [NB];
__device__ __half g_Whi[5 * 16384];   // B = W^T, [n][k] row-major, fp16 hi
__device__ __half g_Wlo[5 * 16384];   // fp16 lo (residual)

// ---------------- helpers ----------------
__device__ __forceinline__ uint32_t smem_u32(const void* p) {
    uint32_t a;
    asm("{ .reg .u64 t; cvta.to.shared.u64 t, %1; cvt.u32.u64 %0, t; }" : "=r"(a) : "l"(p));
    return a;
}
__device__ __forceinline__ void ldm4(uint32_t* r, uint32_t addr) {
    asm volatile("ldmatrix.sync.aligned.m8n8.x4.shared.b16 {%0,%1,%2,%3}, [%4];"
                 : "=r"(r[0]), "=r"(r[1]), "=r"(r[2]), "=r"(r[3]) : "r"(addr));
}
__device__ __forceinline__ void mma_f16(float* d, const uint32_t* a, const uint32_t* b) {
    asm volatile("mma.sync.aligned.m16n8k16.row.col.f32.f16.f16.f32 "
                 "{%0,%1,%2,%3}, {%4,%5,%6,%7}, {%8,%9}, {%0,%1,%2,%3};"
                 : "+f"(d[0]), "+f"(d[1]), "+f"(d[2]), "+f"(d[3])
                 : "r"(a[0]), "r"(a[1]), "r"(a[2]), "r"(a[3]), "r"(b[0]), "r"(b[1]));
}

// ---------------- degree ----------------
__global__ void k_deg_zero() {
    int i = blockIdx.x * blockDim.x + threadIdx.x;
    if (i < NN) g_deg[i] = 0;
}
__global__ void k_deg_count(const int* __restrict__ dst) {
    int i = blockIdx.x * blockDim.x + threadIdx.x;
    if (i < EE) atomicAdd(&g_deg[dst[i]], 1);
}

// ---------------- CSR build ----------------
__global__ void k_scanA() {
    __shared__ int ws[8];
    int i = blockIdx.x * 256 + threadIdx.x;
    int v = (i < NN) ? g_deg[i] : 0;
#pragma unroll
    for (int off = 16; off > 0; off >>= 1) v += __shfl_xor_sync(0xffffffffu, v, off);
    if ((threadIdx.x & 31) == 0) ws[threadIdx.x >> 5] = v;
    __syncthreads();
    if (threadIdx.x == 0) {
        int t = 0;
#pragma unroll
        for (int w = 0; w < 8; w++) t += ws[w];
        g_bsum[blockIdx.x] = t;
    }
}
__global__ void k_scanB() {
    __shared__ int s[512];
    int tid = threadIdx.x;
    int v = (tid < NB) ? g_bsum[tid] : 0;
    s[tid] = v;
    __syncthreads();
    for (int off = 1; off < 512; off <<= 1) {
        int t = (tid >= off) ? s[tid - off] : 0;
        __syncthreads();
        s[tid] += t;
        __syncthreads();
    }
    if (tid < NB) g_boff[tid] = s[tid] - v;
}
__global__ void k_scanC() {   // also computes dinv
    __shared__ int s[256];
    int tid = threadIdx.x;
    int i = blockIdx.x * 256 + tid;
    int v = (i < NN) ? g_deg[i] : 0;
    s[tid] = v;
    __syncthreads();
    for (int off = 1; off < 256; off <<= 1) {
        int t = (tid >= off) ? s[tid - off] : 0;
        __syncthreads();
        s[tid] += t;
        __syncthreads();
    }
    if (i < NN) {
        int r = g_boff[blockIdx.x] + s[tid] - v;
        g_rowptr[i] = r;
        g_cursor[i] = r;
        g_dinv[i] = rsqrtf((float)(v + 1));
    }
}
__global__ void k_fill(const int* __restrict__ src, const int* __restrict__ dst) {
    int e = blockIdx.x * blockDim.x + threadIdx.x;
    if (e >= EE) return;
    int d = dst[e];
    int p = atomicAdd(&g_cursor[d], 1);
    g_csrc[p] = src[e];
    g_eid[p] = e;
}

// ---------------- weight prep: transpose + fp16 hi/lo split, [n][k] layout ----------------
__global__ void k_prep_w(const float* __restrict__ conv_w, const float* __restrict__ mlp_w1) {
    int mat = blockIdx.x;   // 0..2 conv, 3..4 mlp halves
    const float* W = (mat < 3) ? conv_w + mat * 16384 : mlp_w1 + (mat - 3) * 16384;
    for (int idx = threadIdx.x; idx < 16384; idx += blockDim.x) {
        int n = idx >> 7, k = idx & 127;
        float w = W[k * 128 + n];                   // B[n][k] = W[k][n]
        __half hi = __float2half_rn(w);
        __half lo = __float2half_rn(w - __half2float(hi));
        g_Whi[mat * 16384 + idx] = hi;
        g_Wlo[mat * 16384 + idx] = lo;
    }
}

// ---------------- mma.sync GEMM: 64-row tiles, A fp16 single / B fp16 2-term ----------------
#define RS 272
#define SM_AHI 0
#define SM_BHI (64 * RS)
#define SM_BLO (64 * RS + 128 * RS)
#define SMEM_SZ ((64 + 256) * RS)   // 87040 B -> 2 CTA/SM

__device__ __forceinline__ void gemm_fill_A(char* smem, const float* __restrict__ A,
                                            int row0, int M, int wid, int lane) {
#pragma unroll
    for (int it = 0; it < 8; it++) {
        int r = it * 8 + wid;
        int kc = lane * 4;
        int grow = row0 + r;
        float4 v = make_float4(0.f, 0.f, 0.f, 0.f);
        if (grow < M) v = *(const float4*)&A[(size_t)grow * 128 + kc];
        __half2 h01 = __floats2half2_rn(v.x, v.y);
        __half2 h23 = __floats2half2_rn(v.z, v.w);
        uint2 hp = {*(uint32_t*)&h01, *(uint32_t*)&h23};
        *(uint2*)(smem + SM_AHI + r * RS + lane * 8) = hp;
    }
}

__device__ __forceinline__ void gemm_fill_B(char* smem, int mat, int tid) {
    const float4* bh = (const float4*)(g_Whi + mat * 16384);
    const float4* bl = (const float4*)(g_Wlo + mat * 16384);
#pragma unroll
    for (int i = tid; i < 2048; i += 256) {
        int n = i >> 4, seg = i & 15;
        *(float4*)(smem + SM_BHI + n * RS + seg * 16) = bh[i];
        *(float4*)(smem + SM_BLO + n * RS + seg * 16) = bl[i];
    }
}

template <bool H16>
__device__ __forceinline__ void gemm_core_epi(char* smem, uint32_t sb,
                                              void* __restrict__ Cp, int M,
                                              const float* __restrict__ rowscale,
                                              int row0, int wid, int lane) {
    // warp = 16 rows x 64 cols
    int arow = (wid >> 1) * 16 + (lane & 7) + ((lane >> 3) & 1) * 8;
    uint32_t akb = ((lane >> 4) & 1) * 16;
    uint32_t aA0 = sb + SM_AHI + arow * RS + akb;
    int brow = (lane & 7) + ((lane >> 4) & 1) * 8;
    uint32_t bkb = ((lane >> 3) & 1) * 16;
    uint32_t bB0 = sb + SM_BHI + ((wid & 1) * 64 + brow) * RS + bkb;

    float acc[8][4];
#pragma unroll
    for (int n = 0; n < 8; n++)
#pragma unroll
        for (int j = 0; j < 4; j++) acc[n][j] = 0.f;

#pragma unroll
    for (int ks = 0; ks < 8; ks++) {
        uint32_t ko = ks * 32;
        uint32_t ahi[4];
        ldm4(ahi, aA0 + ko);
#pragma unroll
        for (int g = 0; g < 4; g++) {
            uint32_t bhi[4], blo[4];
            ldm4(bhi, bB0 + g * 16 * RS + ko);
            ldm4(blo, bB0 + g * 16 * RS + (SM_BLO - SM_BHI) + ko);
#pragma unroll
            for (int h = 0; h < 2; h++) {
                int n = g * 2 + h;
                mma_f16(acc[n], ahi, &bhi[h * 2]);
                mma_f16(acc[n], ahi, &blo[h * 2]);
            }
        }
    }

    int r0r = row0 + (wid >> 1) * 16 + (lane >> 2);
    int r1r = r0r + 8;
    int cbase = (wid & 1) * 64;
    float s0 = 1.f, s1 = 1.f;
    if (rowscale) {
        if (r0r < M) s0 = rowscale[r0r];
        if (r1r < M) s1 = rowscale[r1r];
    }
#pragma unroll
    for (int n = 0; n < 8; n++) {
        int col = cbase + n * 8 + (lane & 3) * 2;
        if (H16) {
            __half2* C2 = (__half2*)Cp;
            if (r0r < M)
                C2[(size_t)r0r * 64 + (col >> 1)] = __floats2half2_rn(acc[n][0] * s0, acc[n][1] * s0);
            if (r1r < M)
                C2[(size_t)r1r * 64 + (col >> 1)] = __floats2half2_rn(acc[n][2] * s1, acc[n][3] * s1);
        } else {
            float* C = (float*)Cp;
            if (r0r < M) {
                float2 o = {acc[n][0] * s0, acc[n][1] * s0};
                *(float2*)&C[(size_t)r0r * 128 + col] = o;
            }
            if (r1r < M) {
                float2 o = {acc[n][2] * s1, acc[n][3] * s1};
                *(float2*)&C[(size_t)r1r * 128 + col] = o;
            }
        }
    }
}

// conv-layer GEMM: writes fp16 h_scaled
__global__ void __launch_bounds__(256, 2)
k_gemm_h16(const float* __restrict__ A, int mat, __half* __restrict__ C, int M,
           const float* __restrict__ rowscale) {
    extern __shared__ char smem[];
    uint32_t sb = smem_u32(smem);
    int tid = threadIdx.x, wid = tid >> 5, lane = tid & 31;
    int row0 = blockIdx.x * 64;
    gemm_fill_B(smem, mat, tid);
    gemm_fill_A(smem, A, row0, M, wid, lane);
    __syncthreads();
    gemm_core_epi<true>(smem, sb, C, M, rowscale, row0, wid, lane);
}

// P (fp16) and Q (fp32) in one pass
__global__ void __launch_bounds__(256, 2)
k_gemm_pq(const float* __restrict__ A, __half* __restrict__ P, float* __restrict__ Q, int M) {
    extern __shared__ char smem[];
    uint32_t sb = smem_u32(smem);
    int tid = threadIdx.x, wid = tid >> 5, lane = tid & 31;
    int row0 = blockIdx.x * 64;
    gemm_fill_A(smem, A, row0, M, wid, lane);
    gemm_fill_B(smem, 3, tid);
    __syncthreads();
    gemm_core_epi<true>(smem, sb, P, M, nullptr, row0, wid, lane);
    __syncthreads();
    gemm_fill_B(smem, 4, tid);
    __syncthreads();
    gemm_core_epi<false>(smem, sb, Q, M, nullptr, row0, wid, lane);
}

// ---------------- encoder ----------------
__global__ void k_encoder(const float* __restrict__ nf,
                          const float* __restrict__ w,  const float* __restrict__ b,
                          const float* __restrict__ lg, const float* __restrict__ lb) {
    int gw = blockIdx.x * 8 + (threadIdx.x >> 5);
    int nw = gridDim.x * 8;
    int lane = threadIdx.x & 31;

    float wr[7][4], br[4], lgr[4], lbr[4];
#pragma unroll
    for (int j = 0; j < 4; j++) {
        int c = lane + 32 * j;
        br[j] = b[c]; lgr[j] = lg[c]; lbr[j] = lb[c];
#pragma unroll
        for (int k = 0; k < 7; k++) wr[k][j] = w[k * HH + c];
    }

    for (int n = gw; n < NN; n += nw) {
        float f[7];
#pragma unroll
        for (int k = 0; k < 7; k++) f[k] = nf[n * 7 + k];

        float v[4];
#pragma unroll
        for (int j = 0; j < 4; j++) {
            float a = br[j];
#pragma unroll
            for (int k = 0; k < 7; k++) a = fmaf(f[k], wr[k][j], a);
            v[j] = a;
        }
        float s = 0.f, ss = 0.f;
#pragma unroll
        for (int j = 0; j < 4; j++) { s += v[j]; ss += v[j] * v[j]; }
#pragma unroll
        for (int off = 16; off > 0; off >>= 1) {
            s  += __shfl_xor_sync(0xffffffffu, s,  off);
            ss += __shfl_xor_sync(0xffffffffu, ss, off);
        }
        float mu  = s * (1.f / HH);
        float var = ss * (1.f / HH) - mu * mu;
        float inv = rsqrtf(var + LN_EPS);
#pragma unroll
        for (int j = 0; j < 4; j++) {
            int c = lane + 32 * j;
            float y = (v[j] - mu) * inv * lgr[j] + lbr[j];
            g_x[(size_t)n * HH + c] = fmaxf(y, 0.f);
        }
    }
}

// ---------------- fused layer: fp16 gather + bias + LN + ReLU + residual ----------------
__device__ __forceinline__ void acc_h16(float* a, int row, int lane) {
    uint2 hv = *(const uint2*)&g_h16[(size_t)row * 128 + lane * 4];
    float2 fa = __half22float2(*(__half2*)&hv.x);
    float2 fb = __half22float2(*(__half2*)&hv.y);
    a[0] += fa.x; a[1] += fa.y; a[2] += fb.x; a[3] += fb.y;
}

__global__ void __launch_bounds__(256, 8)
k_gather_ln(const float* __restrict__ cb,
            const float* __restrict__ lg, const float* __restrict__ lb,
            float* __restrict__ xout) {
    int n = blockIdx.x * 8 + (threadIdx.x >> 5);
    if (n >= NN) return;
    int lane = threadIdx.x & 31;

    int beg = g_rowptr[n];
    int cnt = g_deg[n];

    float acc[4] = {0.f, 0.f, 0.f, 0.f};
    acc_h16(acc, n, lane);                         // self loop (pre-scaled)

    for (int base = 0; base < cnt; base += 32) {
        int k = cnt - base;
        if (k > 32) k = 32;
        int sidx = (lane < k) ? g_csrc[beg + base + lane] : 0;
        int j = 0;
        for (; j + 8 <= k; j += 8) {
            int s0 = __shfl_sync(0xffffffffu, sidx, j + 0);
            int s1 = __shfl_sync(0xffffffffu, sidx, j + 1);
            int s2 = __shfl_sync(0xffffffffu, sidx, j + 2);
            int s3 = __shfl_sync(0xffffffffu, sidx, j + 3);
            int s4 = __shfl_sync(0xffffffffu, sidx, j + 4);
            int s5 = __shfl_sync(0xffffffffu, sidx, j + 5);
            int s6 = __shfl_sync(0xffffffffu, sidx, j + 6);
            int s7 = __shfl_sync(0xffffffffu, sidx, j + 7);
            acc_h16(acc, s0, lane); acc_h16(acc, s1, lane);
            acc_h16(acc, s2, lane); acc_h16(acc, s3, lane);
            acc_h16(acc, s4, lane); acc_h16(acc, s5, lane);
            acc_h16(acc, s6, lane); acc_h16(acc, s7, lane);
        }
        for (; j < k; j++) {
            int sj = __shfl_sync(0xffffffffu, sidx, j);
            acc_h16(acc, sj, lane);
        }
    }

    float di = g_dinv[n];
    float4 b4 = *(const float4*)&cb[lane * 4];
    float v[4] = {acc[0] * di + b4.x, acc[1] * di + b4.y,
                  acc[2] * di + b4.z, acc[3] * di + b4.w};

    float s = 0.f, ss = 0.f;
#pragma unroll
    for (int j = 0; j < 4; j++) { s += v[j]; ss += v[j] * v[j]; }
#pragma unroll
    for (int off = 16; off > 0; off >>= 1) {
        s  += __shfl_xor_sync(0xffffffffu, s,  off);
        ss += __shfl_xor_sync(0xffffffffu, ss, off);
    }
    float mu   = s * (1.f / HH);
    float var  = ss * (1.f / HH) - mu * mu;
    float linv = rsqrtf(var + LN_EPS);

    float4 lg4 = *(const float4*)&lg[lane * 4];
    float4 lb4 = *(const float4*)&lb[lane * 4];
    float4 xo  = *(const float4*)&g_x[(size_t)n * 128 + lane * 4];

    float4 y;
    y.x = fmaxf((v[0] - mu) * linv * lg4.x + lb4.x, 0.f) + xo.x;
    y.y = fmaxf((v[1] - mu) * linv * lg4.y + lb4.y, 0.f) + xo.y;
    y.z = fmaxf((v[2] - mu) * linv * lg4.z + lb4.z, 0.f) + xo.z;
    y.w = fmaxf((v[3] - mu) * linv * lg4.w + lb4.w, 0.f) + xo.w;

    *(float4*)&g_x[(size_t)n * 128 + lane * 4] = y;
    if (xout) *(float4*)&xout[(size_t)n * 128 + lane * 4] = y;
}

// ---------------- edge MLP, CSR-grouped, smem-transpose reduction ----------------
__global__ void __launch_bounds__(256)
k_edge_mlp_csr(const float* __restrict__ b1, const float* __restrict__ w2,
               const float* __restrict__ b2, float* __restrict__ out) {
    __shared__ float sp[8][32][33];
    int wslot = threadIdx.x >> 5;
    int n = blockIdx.x * 8 + wslot;
    if (n >= NN) return;
    int lane = threadIdx.x & 31;

    int beg = g_rowptr[n];
    int cnt = g_deg[n];
    if (cnt == 0) return;

    float4 qb = *(const float4*)&g_Q[(size_t)n * 128 + lane * 4];
    float4 bb = *(const float4*)&b1[lane * 4];
    qb.x += bb.x; qb.y += bb.y; qb.z += bb.z; qb.w += bb.w;
    float4 w = *(const float4*)&w2[lane * 4];
    float bias2 = b2[0];

    for (int base = 0; base < cnt; base += 32) {
        int k = cnt - base;
        if (k > 32) k = 32;
        int sidx = 0, eidx = 0;
        if (lane < k) {
            sidx = g_csrc[beg + base + lane];
            eidx = g_eid [beg + base + lane];
        }
        for (int j = 0; j < k; j++) {
            int sj = __shfl_sync(0xffffffffu, sidx, j);
            uint2 pv = *(const uint2*)&g_P16[(size_t)sj * 128 + lane * 4];
            float2 pa = __half22float2(*(__half2*)&pv.x);
            float2 pb = __half22float2(*(__half2*)&pv.y);
            float h0 = fmaxf(pa.x + qb.x, 0.f);
            float h1 = fmaxf(pa.y + qb.y, 0.f);
            float h2 = fmaxf(pb.x + qb.z, 0.f);
            float h3 = fmaxf(pb.y + qb.w, 0.f);
            sp[wslot][j][lane] = fmaf(h0, w.x, fmaf(h1, w.y, fmaf(h2, w.z, h3 * w.w)));
        }
        __syncwarp();
        if (lane < k) {
            const float* row = sp[wslot][lane];   // 4B-aligned; scalar loads
            float t0 = 0.f, t1 = 0.f, t2 = 0.f, t3 = 0.f;
#pragma unroll
            for (int i = 0; i < 32; i += 4) {
                t0 += row[i + 0];
                t1 += row[i + 1];
                t2 += row[i + 2];
                t3 += row[i + 3];
            }
            out[eidx] = (t0 + t1) + (t2 + t3) + bias2;
        }
        __syncwarp();
    }
}

// ---------------- host ----------------
extern "C" void kernel_launch(void* const* d_in, const int* in_sizes, int n_in,
                              void* d_out, int out_size) {
    const float* nf       = (const float*)d_in[0];
    const int*   ei       = (const int*)  d_in[1];
    const float* enc_w    = (const float*)d_in[3];
    const float* enc_b    = (const float*)d_in[4];
    const float* enc_ln_g = (const float*)d_in[5];
    const float* enc_ln_b = (const float*)d_in[6];
    const float* conv_w   = (const float*)d_in[7];
    const float* conv_b   = (const float*)d_in[8];
    const float* ln_g     = (const float*)d_in[9];
    const float* ln_b     = (const float*)d_in[10];
    const float* mlp_w1   = (const float*)d_in[11];
    const float* mlp_b1   = (const float*)d_in[12];
    const float* mlp_w2   = (const float*)d_in[13];
    const float* mlp_b2   = (const float*)d_in[14];

    const int* src = ei;
    const int* dst = ei + EE;

    float* out        = (float*)d_out;
    float* out_logits = out + (size_t)NN * HH;

    float *px, *pQ, *pdinv;
    __half *ph16, *pP16;
    cudaGetSymbolAddress((void**)&px,   g_x);
    cudaGetSymbolAddress((void**)&ph16, g_h16);
    cudaGetSymbolAddress((void**)&pP16, g_P16);
    cudaGetSymbolAddress((void**)&pQ,   g_Q);
    cudaGetSymbolAddress((void**)&pdinv, g_dinv);

    cudaFuncSetAttribute(k_gemm_h16, cudaFuncAttributeMaxDynamicSharedMemorySize, SMEM_SZ);
    cudaFuncSetAttribute(k_gemm_pq,  cudaFuncAttributeMaxDynamicSharedMemorySize, SMEM_SZ);

    // side stream + events (created once; host-side only)
    static cudaStream_t s1 = nullptr;
    static cudaEvent_t ev_fork0 = nullptr, ev_enc = nullptr, ev_fork1 = nullptr, ev_fill = nullptr;
    if (!s1) {
        cudaStreamCreateWithFlags(&s1, cudaStreamNonBlocking);
        cudaEventCreateWithFlags(&ev_fork0, cudaEventDisableTiming);
        cudaEventCreateWithFlags(&ev_enc,   cudaEventDisableTiming);
        cudaEventCreateWithFlags(&ev_fork1, cudaEventDisableTiming);
        cudaEventCreateWithFlags(&ev_fill,  cudaEventDisableTiming);
    }

    // ---- fork: encoder + weight prep on s1 ----
    cudaEventRecord(ev_fork0, 0);
    cudaStreamWaitEvent(s1, ev_fork0, 0);
    k_encoder<<<1184, 256, 0, s1>>>(nf, enc_w, enc_b, enc_ln_g, enc_ln_b);
    k_prep_w <<<5, 256, 0, s1>>>(conv_w, mlp_w1);
    cudaEventRecord(ev_enc, s1);

    // ---- main: degree + scan chain ----
    k_deg_zero <<<(NN + 255) / 256, 256>>>();
    k_deg_count<<<(EE + 255) / 256, 256>>>(dst);
    k_scanA<<<NB, 256>>>();
    k_scanB<<<1, 512>>>();
    k_scanC<<<NB, 256>>>();

    // ---- fork: fill runs under gemm l0 ----
    cudaEventRecord(ev_fork1, 0);
    cudaStreamWaitEvent(s1, ev_fork1, 0);
    k_fill<<<(EE + 255) / 256, 256, 0, s1>>>(src, dst);
    cudaEventRecord(ev_fill, s1);

    // ---- main: layer pipeline ----
    cudaStreamWaitEvent(0, ev_enc, 0);
    for (int l = 0; l < 3; l++) {
        k_gemm_h16<<<GB64, 256, SMEM_SZ>>>(px, l, ph16, NN, pdinv);
        if (l == 0) cudaStreamWaitEvent(0, ev_fill, 0);
        k_gather_ln<<<(NN + 7) / 8, 256>>>(conv_b + l * HH, ln_g + l * HH, ln_b + l * HH,
                                           (l == 2) ? out : nullptr);
    }

    // edge scoring
    k_gemm_pq<<<GB64, 256, SMEM_SZ>>>(px, pP16, pQ, NN);
    k_edge_mlp_csr<<<(NN + 7) / 8, 256>>>(mlp_b1, mlp_w2, mlp_b2, out_logits);
}

// round 13
// speedup vs baseline: 2.9908x; 1.1024x over previous
#include <cuda_runtime.h>
#include <cuda_fp16.h>
#include <cstdint>

#define NN 100000
#define HH 128
#define EE 1600000
#define LN_EPS 1e-5f
#define NB 391           // (NN+255)/256
#define GB64 1563        // (NN+63)/64 gemm tiles

// ---------------- device scratch ----------------
__device__ float  g_x  [NN * HH];    // fp32 master (residual path)
__device__ __half g_x16[NN * HH];    // fp16 mirror, GEMM A input
__device__ __half g_h16[NN * HH];    // h_scaled = (x@W)*dinv, fp16 storage
__device__ __half g_P16[NN * HH];    // P = x@W1[:128], fp16 storage
__device__ float  g_Q  [NN * HH];    // Q = x@W1[128:], fp32 (read once per node)
__device__ int   g_deg   [NN];
__device__ float g_dinv  [NN];
__device__ int   g_rowptr[NN];
__device__ int   g_cursor[NN];
__device__ int   g_csrc  [EE];
__device__ int   g_eid   [EE];
__device__ int   g_bsum  [NB];
__device__ int   g_boff  [NB];
__device__ __half g_W16[5 * 16384];  // B = W^T, [n][k] row-major, fp16

// ---------------- helpers ----------------
__device__ __forceinline__ uint32_t smem_u32(const void* p) {
    uint32_t a;
    asm("{ .reg .u64 t; cvta.to.shared.u64 t, %1; cvt.u32.u64 %0, t; }" : "=r"(a) : "l"(p));
    return a;
}
__device__ __forceinline__ void ldm4(uint32_t* r, uint32_t addr) {
    asm volatile("ldmatrix.sync.aligned.m8n8.x4.shared.b16 {%0,%1,%2,%3}, [%4];"
                 : "=r"(r[0]), "=r"(r[1]), "=r"(r[2]), "=r"(r[3]) : "r"(addr));
}
__device__ __forceinline__ void mma_f16(float* d, const uint32_t* a, const uint32_t* b) {
    asm volatile("mma.sync.aligned.m16n8k16.row.col.f32.f16.f16.f32 "
                 "{%0,%1,%2,%3}, {%4,%5,%6,%7}, {%8,%9}, {%0,%1,%2,%3};"
                 : "+f"(d[0]), "+f"(d[1]), "+f"(d[2]), "+f"(d[3])
                 : "r"(a[0]), "r"(a[1]), "r"(a[2]), "r"(a[3]), "r"(b[0]), "r"(b[1]));
}

// ---------------- degree ----------------
__global__ void k_deg_zero() {
    int i = blockIdx.x * blockDim.x + threadIdx.x;
    if (i < NN) g_deg[i] = 0;
}
__global__ void k_deg_count(const int* __restrict__ dst) {
    int i = blockIdx.x * blockDim.x + threadIdx.x;
    if (i < EE) atomicAdd(&g_deg[dst[i]], 1);
}

// ---------------- CSR build ----------------
__global__ void k_scanA() {
    __shared__ int ws[8];
    int i = blockIdx.x * 256 + threadIdx.x;
    int v = (i < NN) ? g_deg[i] : 0;
#pragma unroll
    for (int off = 16; off > 0; off >>= 1) v += __shfl_xor_sync(0xffffffffu, v, off);
    if ((threadIdx.x & 31) == 0) ws[threadIdx.x >> 5] = v;
    __syncthreads();
    if (threadIdx.x == 0) {
        int t = 0;
#pragma unroll
        for (int w = 0; w < 8; w++) t += ws[w];
        g_bsum[blockIdx.x] = t;
    }
}
__global__ void k_scanB() {
    __shared__ int s[512];
    int tid = threadIdx.x;
    int v = (tid < NB) ? g_bsum[tid] : 0;
    s[tid] = v;
    __syncthreads();
    for (int off = 1; off < 512; off <<= 1) {
        int t = (tid >= off) ? s[tid - off] : 0;
        __syncthreads();
        s[tid] += t;
        __syncthreads();
    }
    if (tid < NB) g_boff[tid] = s[tid] - v;
}
__global__ void k_scanC() {   // also computes dinv
    __shared__ int s[256];
    int tid = threadIdx.x;
    int i = blockIdx.x * 256 + tid;
    int v = (i < NN) ? g_deg[i] : 0;
    s[tid] = v;
    __syncthreads();
    for (int off = 1; off < 256; off <<= 1) {
        int t = (tid >= off) ? s[tid - off] : 0;
        __syncthreads();
        s[tid] += t;
        __syncthreads();
    }
    if (i < NN) {
        int r = g_boff[blockIdx.x] + s[tid] - v;
        g_rowptr[i] = r;
        g_cursor[i] = r;
        g_dinv[i] = rsqrtf((float)(v + 1));
    }
}
__global__ void k_fill(const int* __restrict__ src, const int* __restrict__ dst) {
    int e = blockIdx.x * blockDim.x + threadIdx.x;
    if (e >= EE) return;
    int d = dst[e];
    int p = atomicAdd(&g_cursor[d], 1);
    g_csrc[p] = src[e];
    g_eid[p] = e;
}

// ---------------- weight prep: transpose + fp16, [n][k] layout ----------------
__global__ void k_prep_w(const float* __restrict__ conv_w, const float* __restrict__ mlp_w1) {
    int mat = blockIdx.x;   // 0..2 conv, 3..4 mlp halves
    const float* W = (mat < 3) ? conv_w + mat * 16384 : mlp_w1 + (mat - 3) * 16384;
    for (int idx = threadIdx.x; idx < 16384; idx += blockDim.x) {
        int n = idx >> 7, k = idx & 127;
        g_W16[mat * 16384 + idx] = __float2half_rn(W[k * 128 + n]);   // B[n][k] = W[k][n]
    }
}

// ---------------- mma.sync GEMM: 64-row tiles, fp16 A x fp16 B, fp32 acc ----------------
#define RS 272
#define SM_A 0
#define SM_B (64 * RS)
#define SMEM_SZ (192 * RS)   // 52224 B -> 3 CTA/SM

__device__ __forceinline__ void gemm_fill_A(char* smem, const __half* __restrict__ A16,
                                            int row0, int M, int wid, int lane) {
#pragma unroll
    for (int it = 0; it < 8; it++) {
        int r = it * 8 + wid;
        int grow = row0 + r;
        uint2 v = make_uint2(0u, 0u);
        if (grow < M) v = *(const uint2*)&A16[(size_t)grow * 128 + lane * 4];
        *(uint2*)(smem + SM_A + r * RS + lane * 8) = v;
    }
}

__device__ __forceinline__ void gemm_fill_B(char* smem, int mat, int tid) {
    const float4* b = (const float4*)(g_W16 + mat * 16384);
    // 16384 halves = 32768 B = 2048 float4; each [n] row = 128 halves = 16 segs of 16B
#pragma unroll
    for (int i = tid; i < 2048; i += 256) {
        int n = i >> 4, seg = i & 15;
        *(float4*)(smem + SM_B + n * RS + seg * 16) = b[i];
    }
}

template <bool H16>
__device__ __forceinline__ void gemm_core_epi(char* smem, uint32_t sb,
                                              void* __restrict__ Cp, int M,
                                              const float* __restrict__ rowscale,
                                              int row0, int wid, int lane) {
    // warp = 16 rows x 64 cols
    int arow = (wid >> 1) * 16 + (lane & 7) + ((lane >> 3) & 1) * 8;
    uint32_t akb = ((lane >> 4) & 1) * 16;
    uint32_t aA0 = sb + SM_A + arow * RS + akb;
    int brow = (lane & 7) + ((lane >> 4) & 1) * 8;
    uint32_t bkb = ((lane >> 3) & 1) * 16;
    uint32_t bB0 = sb + SM_B + ((wid & 1) * 64 + brow) * RS + bkb;

    float acc[8][4];
#pragma unroll
    for (int n = 0; n < 8; n++)
#pragma unroll
        for (int j = 0; j < 4; j++) acc[n][j] = 0.f;

#pragma unroll
    for (int ks = 0; ks < 8; ks++) {
        uint32_t ko = ks * 32;
        uint32_t a[4];
        ldm4(a, aA0 + ko);
#pragma unroll
        for (int g = 0; g < 4; g++) {
            uint32_t b[4];
            ldm4(b, bB0 + g * 16 * RS + ko);
            mma_f16(acc[g * 2 + 0], a, &b[0]);
            mma_f16(acc[g * 2 + 1], a, &b[2]);
        }
    }

    int r0r = row0 + (wid >> 1) * 16 + (lane >> 2);
    int r1r = r0r + 8;
    int cbase = (wid & 1) * 64;
    float s0 = 1.f, s1 = 1.f;
    if (rowscale) {
        if (r0r < M) s0 = rowscale[r0r];
        if (r1r < M) s1 = rowscale[r1r];
    }
#pragma unroll
    for (int n = 0; n < 8; n++) {
        int col = cbase + n * 8 + (lane & 3) * 2;
        if (H16) {
            __half2* C2 = (__half2*)Cp;
            if (r0r < M)
                C2[(size_t)r0r * 64 + (col >> 1)] = __floats2half2_rn(acc[n][0] * s0, acc[n][1] * s0);
            if (r1r < M)
                C2[(size_t)r1r * 64 + (col >> 1)] = __floats2half2_rn(acc[n][2] * s1, acc[n][3] * s1);
        } else {
            float* C = (float*)Cp;
            if (r0r < M) {
                float2 o = {acc[n][0] * s0, acc[n][1] * s0};
                *(float2*)&C[(size_t)r0r * 128 + col] = o;
            }
            if (r1r < M) {
                float2 o = {acc[n][2] * s1, acc[n][3] * s1};
                *(float2*)&C[(size_t)r1r * 128 + col] = o;
            }
        }
    }
}

// conv-layer GEMM: reads fp16 x-mirror, writes fp16 h_scaled
__global__ void __launch_bounds__(256, 3)
k_gemm_h16(const __half* __restrict__ A16, int mat, __half* __restrict__ C, int M,
           const float* __restrict__ rowscale) {
    extern __shared__ char smem[];
    uint32_t sb = smem_u32(smem);
    int tid = threadIdx.x, wid = tid >> 5, lane = tid & 31;
    int row0 = blockIdx.x * 64;
    gemm_fill_B(smem, mat, tid);
    gemm_fill_A(smem, A16, row0, M, wid, lane);
    __syncthreads();
    gemm_core_epi<true>(smem, sb, C, M, rowscale, row0, wid, lane);
}

// P (fp16) and Q (fp32) in one pass
__global__ void __launch_bounds__(256, 3)
k_gemm_pq(const __half* __restrict__ A16, __half* __restrict__ P, float* __restrict__ Q, int M) {
    extern __shared__ char smem[];
    uint32_t sb = smem_u32(smem);
    int tid = threadIdx.x, wid = tid >> 5, lane = tid & 31;
    int row0 = blockIdx.x * 64;
    gemm_fill_A(smem, A16, row0, M, wid, lane);
    gemm_fill_B(smem, 3, tid);
    __syncthreads();
    gemm_core_epi<true>(smem, sb, P, M, nullptr, row0, wid, lane);
    __syncthreads();
    gemm_fill_B(smem, 4, tid);
    __syncthreads();
    gemm_core_epi<false>(smem, sb, Q, M, nullptr, row0, wid, lane);
}

// ---------------- encoder: writes fp32 x + fp16 mirror ----------------
__global__ void k_encoder(const float* __restrict__ nf,
                          const float* __restrict__ w,  const float* __restrict__ b,
                          const float* __restrict__ lg, const float* __restrict__ lb) {
    int gw = blockIdx.x * 8 + (threadIdx.x >> 5);
    int nw = gridDim.x * 8;
    int lane = threadIdx.x & 31;

    float wr[7][4], br[4], lgr[4], lbr[4];
#pragma unroll
    for (int j = 0; j < 4; j++) {
        int c = lane + 32 * j;
        br[j] = b[c]; lgr[j] = lg[c]; lbr[j] = lb[c];
#pragma unroll
        for (int k = 0; k < 7; k++) wr[k][j] = w[k * HH + c];
    }

    for (int n = gw; n < NN; n += nw) {
        float f[7];
#pragma unroll
        for (int k = 0; k < 7; k++) f[k] = nf[n * 7 + k];

        float v[4];
#pragma unroll
        for (int j = 0; j < 4; j++) {
            float a = br[j];
#pragma unroll
            for (int k = 0; k < 7; k++) a = fmaf(f[k], wr[k][j], a);
            v[j] = a;
        }
        float s = 0.f, ss = 0.f;
#pragma unroll
        for (int j = 0; j < 4; j++) { s += v[j]; ss += v[j] * v[j]; }
#pragma unroll
        for (int off = 16; off > 0; off >>= 1) {
            s  += __shfl_xor_sync(0xffffffffu, s,  off);
            ss += __shfl_xor_sync(0xffffffffu, ss, off);
        }
        float mu  = s * (1.f / HH);
        float var = ss * (1.f / HH) - mu * mu;
        float inv = rsqrtf(var + LN_EPS);
#pragma unroll
        for (int j = 0; j < 4; j++) {
            int c = lane + 32 * j;
            float y = fmaxf((v[j] - mu) * inv * lgr[j] + lbr[j], 0.f);
            g_x  [(size_t)n * HH + c] = y;
            g_x16[(size_t)n * HH + c] = __float2half_rn(y);
        }
    }
}

// ---------------- fused layer: fp16 gather + bias + LN + ReLU + residual ----------------
__device__ __forceinline__ void acc_h16(float* a, int row, int lane) {
    uint2 hv = *(const uint2*)&g_h16[(size_t)row * 128 + lane * 4];
    float2 fa = __half22float2(*(__half2*)&hv.x);
    float2 fb = __half22float2(*(__half2*)&hv.y);
    a[0] += fa.x; a[1] += fa.y; a[2] += fb.x; a[3] += fb.y;
}

__global__ void __launch_bounds__(256, 8)
k_gather_ln(const float* __restrict__ cb,
            const float* __restrict__ lg, const float* __restrict__ lb,
            float* __restrict__ xout) {
    int n = blockIdx.x * 8 + (threadIdx.x >> 5);
    if (n >= NN) return;
    int lane = threadIdx.x & 31;

    int beg = g_rowptr[n];
    int cnt = g_deg[n];

    float acc[4] = {0.f, 0.f, 0.f, 0.f};
    acc_h16(acc, n, lane);                         // self loop (pre-scaled)

    for (int base = 0; base < cnt; base += 32) {
        int k = cnt - base;
        if (k > 32) k = 32;
        int sidx = (lane < k) ? g_csrc[beg + base + lane] : 0;
        int j = 0;
        for (; j + 8 <= k; j += 8) {
            int s0 = __shfl_sync(0xffffffffu, sidx, j + 0);
            int s1 = __shfl_sync(0xffffffffu, sidx, j + 1);
            int s2 = __shfl_sync(0xffffffffu, sidx, j + 2);
            int s3 = __shfl_sync(0xffffffffu, sidx, j + 3);
            int s4 = __shfl_sync(0xffffffffu, sidx, j + 4);
            int s5 = __shfl_sync(0xffffffffu, sidx, j + 5);
            int s6 = __shfl_sync(0xffffffffu, sidx, j + 6);
            int s7 = __shfl_sync(0xffffffffu, sidx, j + 7);
            acc_h16(acc, s0, lane); acc_h16(acc, s1, lane);
            acc_h16(acc, s2, lane); acc_h16(acc, s3, lane);
            acc_h16(acc, s4, lane); acc_h16(acc, s5, lane);
            acc_h16(acc, s6, lane); acc_h16(acc, s7, lane);
        }
        for (; j < k; j++) {
            int sj = __shfl_sync(0xffffffffu, sidx, j);
            acc_h16(acc, sj, lane);
        }
    }

    float di = g_dinv[n];
    float4 b4 = *(const float4*)&cb[lane * 4];
    float v[4] = {acc[0] * di + b4.x, acc[1] * di + b4.y,
                  acc[2] * di + b4.z, acc[3] * di + b4.w};

    float s = 0.f, ss = 0.f;
#pragma unroll
    for (int j = 0; j < 4; j++) { s += v[j]; ss += v[j] * v[j]; }
#pragma unroll
    for (int off = 16; off > 0; off >>= 1) {
        s  += __shfl_xor_sync(0xffffffffu, s,  off);
        ss += __shfl_xor_sync(0xffffffffu, ss, off);
    }
    float mu   = s * (1.f / HH);
    float var  = ss * (1.f / HH) - mu * mu;
    float linv = rsqrtf(var + LN_EPS);

    float4 lg4 = *(const float4*)&lg[lane * 4];
    float4 lb4 = *(const float4*)&lb[lane * 4];
    float4 xo  = *(const float4*)&g_x[(size_t)n * 128 + lane * 4];

    float4 y;
    y.x = fmaxf((v[0] - mu) * linv * lg4.x + lb4.x, 0.f) + xo.x;
    y.y = fmaxf((v[1] - mu) * linv * lg4.y + lb4.y, 0.f) + xo.y;
    y.z = fmaxf((v[2] - mu) * linv * lg4.z + lb4.z, 0.f) + xo.z;
    y.w = fmaxf((v[3] - mu) * linv * lg4.w + lb4.w, 0.f) + xo.w;

    *(float4*)&g_x[(size_t)n * 128 + lane * 4] = y;
    __half2 m0 = __floats2half2_rn(y.x, y.y);
    __half2 m1 = __floats2half2_rn(y.z, y.w);
    uint2 mv = {*(uint32_t*)&m0, *(uint32_t*)&m1};
    *(uint2*)&g_x16[(size_t)n * 128 + lane * 4] = mv;
    if (xout) *(float4*)&xout[(size_t)n * 128 + lane * 4] = y;
}

// ---------------- edge MLP, CSR-grouped, smem-transpose reduction ----------------
__global__ void __launch_bounds__(256)
k_edge_mlp_csr(const float* __restrict__ b1, const float* __restrict__ w2,
               const float* __restrict__ b2, float* __restrict__ out) {
    __shared__ float sp[8][32][33];
    int wslot = threadIdx.x >> 5;
    int n = blockIdx.x * 8 + wslot;
    if (n >= NN) return;
    int lane = threadIdx.x & 31;

    int beg = g_rowptr[n];
    int cnt = g_deg[n];
    if (cnt == 0) return;

    float4 qb = *(const float4*)&g_Q[(size_t)n * 128 + lane * 4];
    float4 bb = *(const float4*)&b1[lane * 4];
    qb.x += bb.x; qb.y += bb.y; qb.z += bb.z; qb.w += bb.w;
    float4 w = *(const float4*)&w2[lane * 4];
    float bias2 = b2[0];

    for (int base = 0; base < cnt; base += 32) {
        int k = cnt - base;
        if (k > 32) k = 32;
        int sidx = 0, eidx = 0;
        if (lane < k) {
            sidx = g_csrc[beg + base + lane];
            eidx = g_eid [beg + base + lane];
        }
        for (int j = 0; j < k; j++) {
            int sj = __shfl_sync(0xffffffffu, sidx, j);
            uint2 pv = *(const uint2*)&g_P16[(size_t)sj * 128 + lane * 4];
            float2 pa = __half22float2(*(__half2*)&pv.x);
            float2 pb = __half22float2(*(__half2*)&pv.y);
            float h0 = fmaxf(pa.x + qb.x, 0.f);
            float h1 = fmaxf(pa.y + qb.y, 0.f);
            float h2 = fmaxf(pb.x + qb.z, 0.f);
            float h3 = fmaxf(pb.y + qb.w, 0.f);
            sp[wslot][j][lane] = fmaf(h0, w.x, fmaf(h1, w.y, fmaf(h2, w.z, h3 * w.w)));
        }
        __syncwarp();
        if (lane < k) {
            const float* row = sp[wslot][lane];   // 4B-aligned; scalar loads
            float t0 = 0.f, t1 = 0.f, t2 = 0.f, t3 = 0.f;
#pragma unroll
            for (int i = 0; i < 32; i += 4) {
                t0 += row[i + 0];
                t1 += row[i + 1];
                t2 += row[i + 2];
                t3 += row[i + 3];
            }
            out[eidx] = (t0 + t1) + (t2 + t3) + bias2;
        }
        __syncwarp();
    }
}

// ---------------- host ----------------
extern "C" void kernel_launch(void* const* d_in, const int* in_sizes, int n_in,
                              void* d_out, int out_size) {
    const float* nf       = (const float*)d_in[0];
    const int*   ei       = (const int*)  d_in[1];
    const float* enc_w    = (const float*)d_in[3];
    const float* enc_b    = (const float*)d_in[4];
    const float* enc_ln_g = (const float*)d_in[5];
    const float* enc_ln_b = (const float*)d_in[6];
    const float* conv_w   = (const float*)d_in[7];
    const float* conv_b   = (const float*)d_in[8];
    const float* ln_g     = (const float*)d_in[9];
    const float* ln_b     = (const float*)d_in[10];
    const float* mlp_w1   = (const float*)d_in[11];
    const float* mlp_b1   = (const float*)d_in[12];
    const float* mlp_w2   = (const float*)d_in[13];
    const float* mlp_b2   = (const float*)d_in[14];

    const int* src = ei;
    const int* dst = ei + EE;

    float* out        = (float*)d_out;
    float* out_logits = out + (size_t)NN * HH;

    float *pQ, *pdinv;
    __half *px16, *ph16, *pP16;
    cudaGetSymbolAddress((void**)&px16, g_x16);
    cudaGetSymbolAddress((void**)&ph16, g_h16);
    cudaGetSymbolAddress((void**)&pP16, g_P16);
    cudaGetSymbolAddress((void**)&pQ,   g_Q);
    cudaGetSymbolAddress((void**)&pdinv, g_dinv);

    cudaFuncSetAttribute(k_gemm_h16, cudaFuncAttributeMaxDynamicSharedMemorySize, SMEM_SZ);
    cudaFuncSetAttribute(k_gemm_pq,  cudaFuncAttributeMaxDynamicSharedMemorySize, SMEM_SZ);

    // side stream + events (created once; host-side only)
    static cudaStream_t s1 = nullptr;
    static cudaEvent_t ev_fork0 = nullptr, ev_enc = nullptr, ev_fork1 = nullptr, ev_fill = nullptr;
    if (!s1) {
        cudaStreamCreateWithFlags(&s1, cudaStreamNonBlocking);
        cudaEventCreateWithFlags(&ev_fork0, cudaEventDisableTiming);
        cudaEventCreateWithFlags(&ev_enc,   cudaEventDisableTiming);
        cudaEventCreateWithFlags(&ev_fork1, cudaEventDisableTiming);
        cudaEventCreateWithFlags(&ev_fill,  cudaEventDisableTiming);
    }

    // ---- fork: encoder + weight prep on s1 ----
    cudaEventRecord(ev_fork0, 0);
    cudaStreamWaitEvent(s1, ev_fork0, 0);
    k_encoder<<<1184, 256, 0, s1>>>(nf, enc_w, enc_b, enc_ln_g, enc_ln_b);
    k_prep_w <<<5, 256, 0, s1>>>(conv_w, mlp_w1);
    cudaEventRecord(ev_enc, s1);

    // ---- main: degree + scan chain ----
    k_deg_zero <<<(NN + 255) / 256, 256>>>();
    k_deg_count<<<(EE + 255) / 256, 256>>>(dst);
    k_scanA<<<NB, 256>>>();
    k_scanB<<<1, 512>>>();
    k_scanC<<<NB, 256>>>();

    // ---- fork: fill runs under gemm l0 ----
    cudaEventRecord(ev_fork1, 0);
    cudaStreamWaitEvent(s1, ev_fork1, 0);
    k_fill<<<(EE + 255) / 256, 256, 0, s1>>>(src, dst);
    cudaEventRecord(ev_fill, s1);

    // ---- main: layer pipeline ----
    cudaStreamWaitEvent(0, ev_enc, 0);
    for (int l = 0; l < 3; l++) {
        k_gemm_h16<<<GB64, 256, SMEM_SZ>>>(px16, l, ph16, NN, pdinv);
        if (l == 0) cudaStreamWaitEvent(0, ev_fill, 0);
        k_gather_ln<<<(NN + 7) / 8, 256>>>(conv_b + l * HH, ln_g + l * HH, ln_b + l * HH,
                                           (l == 2) ? out : nullptr);
    }

    // edge scoring
    k_gemm_pq<<<GB64, 256, SMEM_SZ>>>(px16, pP16, pQ, NN);
    k_edge_mlp_csr<<<(NN + 7) / 8, 256>>>(mlp_b1, mlp_w2, mlp_b2, out_logits);
}